// round 9
// baseline (speedup 1.0000x reference)
#include <cuda_runtime.h>
#include <cuda_bf16.h>
#include <cstdint>
#include <math.h>

#define Cdim   192
#define NHEAD  8
#define HDIM   24
#define HWPIX  12544          // 112*112
#define LTOK   784            // 7*112
#define GK     192            // gemm K
#define NPIX   12544
#define M_QKV  576
#define M_PROJ 192
#define SCALE_F 0.20412414523193154f  // 24^-0.5

typedef unsigned short ushort_t;

// ---------------- scratch (device globals; no allocation) ----------------
__device__ float g_qkv_h[M_QKV * HWPIX];
__device__ float g_qkv_v[M_QKV * HWPIX];
__device__ float g_att_h[Cdim * HWPIX];
__device__ float g_att_v[Cdim * HWPIX];
__device__ ushort_t g_xhi[GK * NPIX];
__device__ ushort_t g_xlo[GK * NPIX];
__device__ ushort_t g_phi[GK * NPIX];
__device__ ushort_t g_plo[GK * NPIX];
__device__ ushort_t g_whh[M_QKV * GK];
__device__ ushort_t g_whl[M_QKV * GK];
__device__ ushort_t g_wvh[M_QKV * GK];
__device__ ushort_t g_wvl[M_QKV * GK];
__device__ ushort_t g_pwh[M_PROJ * GK];
__device__ ushort_t g_pwl[M_PROJ * GK];

// ---------------- bf16 helpers ----------------
__device__ __forceinline__ uint32_t bfp(float lo_el, float hi_el) {
    uint32_t r;
    asm("cvt.rn.bf16x2.f32 %0, %1, %2;" : "=r"(r) : "f"(hi_el), "f"(lo_el));
    return r;
}
__device__ __forceinline__ float bflo(uint32_t p) { return __uint_as_float(p << 16); }
__device__ __forceinline__ float bfhi(uint32_t p) { return __uint_as_float(p & 0xFFFF0000u); }

__device__ __forceinline__ uint32_t s2u(const void* p) {
    uint32_t a;
    asm("{ .reg .u64 t; cvta.to.shared.u64 t, %1; cvt.u32.u64 %0, t; }" : "=r"(a) : "l"(p));
    return a;
}

__device__ __forceinline__ void mma_bf16(float* c,
    uint32_t a0, uint32_t a1, uint32_t a2, uint32_t a3,
    uint32_t b0, uint32_t b1)
{
    asm volatile("mma.sync.aligned.m16n8k16.row.col.f32.bf16.bf16.f32 "
        "{%0,%1,%2,%3}, {%4,%5,%6,%7}, {%8,%9}, {%0,%1,%2,%3};"
        : "+f"(c[0]), "+f"(c[1]), "+f"(c[2]), "+f"(c[3])
        : "r"(a0), "r"(a1), "r"(a2), "r"(a3), "r"(b0), "r"(b1));
}

__device__ __forceinline__ void ldsm4t(uint32_t& r0, uint32_t& r1,
                                       uint32_t& r2, uint32_t& r3, uint32_t a)
{
    asm volatile("ldmatrix.sync.aligned.m8n8.x4.trans.shared.b16 {%0,%1,%2,%3}, [%4];"
        : "=r"(r0), "=r"(r1), "=r"(r2), "=r"(r3) : "r"(a));
}
__device__ __forceinline__ void ldsm4(uint32_t& r0, uint32_t& r1,
                                      uint32_t& r2, uint32_t& r3, uint32_t a)
{
    asm volatile("ldmatrix.sync.aligned.m8n8.x4.shared.b16 {%0,%1,%2,%3}, [%4];"
        : "=r"(r0), "=r"(r1), "=r"(r2), "=r"(r3) : "r"(a));
}

#define CPA16(dst, src) asm volatile("cp.async.ca.shared.global [%0], [%1], 16;" :: "r"(dst), "l"(src) : "memory")
#define CPC()  asm volatile("cp.async.commit_group;" ::: "memory")
#define CPW1() asm volatile("cp.async.wait_group 1;" ::: "memory")
#define CPW0() asm volatile("cp.async.wait_group 0;" ::: "memory")

// ---------------- split fp32 -> bf16 hi/lo planes (vec4) ----------------
__global__ __launch_bounds__(256) void split_kernel(
    const float4* __restrict__ in, uint2* __restrict__ hi,
    uint2* __restrict__ lo, int n4)
{
    int i = blockIdx.x * blockDim.x + threadIdx.x;
    if (i >= n4) return;
    float4 v = in[i];
    uint32_t h0 = bfp(v.x, v.y);
    uint32_t h1 = bfp(v.z, v.w);
    uint32_t l0 = bfp(v.x - bflo(h0), v.y - bfhi(h0));
    uint32_t l1 = bfp(v.z - bflo(h1), v.w - bfhi(h1));
    hi[i] = make_uint2(h0, h1);
    lo[i] = make_uint2(l0, l1);
}

__global__ __launch_bounds__(256) void split_weights(
    const float4* __restrict__ w1, uint2* __restrict__ h1p, uint2* __restrict__ l1p, int n1,
    const float4* __restrict__ w2, uint2* __restrict__ h2p, uint2* __restrict__ l2p, int n2,
    const float4* __restrict__ w3, uint2* __restrict__ h3p, uint2* __restrict__ l3p, int n3)
{
    int i = blockIdx.x * blockDim.x + threadIdx.x;
    const float4* src; uint2 *hd, *ld; int j = i;
    if (j < n1) { src = w1; hd = h1p; ld = l1p; }
    else if ((j -= n1) < n2) { src = w2; hd = h2p; ld = l2p; }
    else if ((j -= n2) < n3) { src = w3; hd = h3p; ld = l3p; }
    else return;
    float4 v = src[j];
    uint32_t h0 = bfp(v.x, v.y);
    uint32_t h1 = bfp(v.z, v.w);
    uint32_t l0 = bfp(v.x - bflo(h0), v.y - bfhi(h0));
    uint32_t l1 = bfp(v.z - bflo(h1), v.w - bfhi(h1));
    hd[j] = make_uint2(h0, h1);
    ld[j] = make_uint2(l0, l1);
}

// ---------------- hi/lo bf16 mma GEMM, A staged + ldmatrix, cp.async DB ------------
#define G_SBH 0
#define G_SBL 8704
#define G_SAH 17408
#define G_SAL 22528
#define G_BSTR 136
#define G_BBUF 4352
#define G_ASTR 40
#define G_ABUF 2560
#define G_TOTAL_BYTES 55296

__global__ __launch_bounds__(256) void gemm_mma(
    const ushort_t* __restrict__ Ahi, const ushort_t* __restrict__ Alo,
    const ushort_t* __restrict__ Bhi, const ushort_t* __restrict__ Blo,
    const float* __restrict__ bias, float* __restrict__ C)
{
    extern __shared__ ushort_t gsm[];
    const int tid = threadIdx.x;
    const int bn = blockIdx.x * 128, bm = blockIdx.y * 64;
    const int wid = tid >> 5, lane = tid & 31;
    const int wm = wid & 3, wn = wid >> 2;
    const int g = lane >> 2, q = lane & 3;
    const int wc = wn * 64;
    const int row0 = bm + wm * 16 + g;
    const int row1 = row0 + 8;

    float acc[8][4];
    #pragma unroll
    for (int i = 0; i < 8; i++)
        #pragma unroll
        for (int j = 0; j < 4; j++) acc[i][j] = 0.f;

    const int rB = tid >> 3;
    const int cB = (tid & 7) * 8;
    const int rA = tid >> 2;
    const int cA = (tid & 3) * 8;

    uint32_t smb = s2u(gsm);
    uint32_t dstBh[2], dstBl[2], dstAh[2], dstAl[2];
    #pragma unroll
    for (int b = 0; b < 2; b++) {
        dstBh[b] = smb + (uint32_t)((G_SBH + b * G_BBUF + rB * G_BSTR + cB) * 2);
        dstBl[b] = smb + (uint32_t)((G_SBL + b * G_BBUF + rB * G_BSTR + cB) * 2);
        dstAh[b] = smb + (uint32_t)((G_SAH + b * G_ABUF + rA * G_ASTR + cA) * 2);
        dstAl[b] = smb + (uint32_t)((G_SAL + b * G_ABUF + rA * G_ASTR + cA) * 2);
    }

    const int lm = lane >> 3, lr = lane & 7;
    const int lkrow = (lm & 1) * 8 + lr;
    const int lncol = wc + (lm >> 1) * 8;
    uint32_t sbh_base[2], sbl_base[2];
    const int arow = wm * 16 + (lm & 1) * 8 + lr;
    const int acol = (lane >> 4) * 8;
    uint32_t sah_base[2], sal_base[2];
    #pragma unroll
    for (int b = 0; b < 2; b++) {
        sbh_base[b] = smb + (uint32_t)((G_SBH + b * G_BBUF + lkrow * G_BSTR + lncol) * 2);
        sbl_base[b] = smb + (uint32_t)((G_SBL + b * G_BBUF + lkrow * G_BSTR + lncol) * 2);
        sah_base[b] = smb + (uint32_t)((G_SAH + b * G_ABUF + arow * G_ASTR + acol) * 2);
        sal_base[b] = smb + (uint32_t)((G_SAL + b * G_ABUF + arow * G_ASTR + acol) * 2);
    }

    {
        const ushort_t* bh = &Bhi[rB * NPIX + bn + cB];
        const ushort_t* bl = &Blo[rB * NPIX + bn + cB];
        CPA16(dstBh[0], bh); CPA16(dstBh[0] + 128, bh + 64);
        CPA16(dstBl[0], bl); CPA16(dstBl[0] + 128, bl + 64);
        CPA16(dstAh[0], &Ahi[(bm + rA) * GK + cA]);
        CPA16(dstAl[0], &Alo[(bm + rA) * GK + cA]);
        CPC();
    }

    #pragma unroll
    for (int ki = 0; ki < 6; ki++) {
        if (ki < 5) {
            const int kn = (ki + 1) * 32;
            const int bf = (ki + 1) & 1;
            const ushort_t* bh = &Bhi[(kn + rB) * NPIX + bn + cB];
            const ushort_t* bl = &Blo[(kn + rB) * NPIX + bn + cB];
            CPA16(dstBh[bf], bh); CPA16(dstBh[bf] + 128, bh + 64);
            CPA16(dstBl[bf], bl); CPA16(dstBl[bf] + 128, bl + 64);
            CPA16(dstAh[bf], &Ahi[(bm + rA) * GK + kn + cA]);
            CPA16(dstAl[bf], &Alo[(bm + rA) * GK + kn + cA]);
            CPC();
            CPW1();
        } else {
            CPW0();
        }
        __syncthreads();

        const int buf = ki & 1;
        #pragma unroll
        for (int hh = 0; hh < 2; hh++) {
            uint32_t ah[4], al[4];
            ldsm4(ah[0], ah[1], ah[2], ah[3], sah_base[buf] + hh * 32);
            ldsm4(al[0], al[1], al[2], al[3], sal_base[buf] + hh * 32);

            const uint32_t hoff = (uint32_t)(hh * 16 * G_BSTR) * 2;
            #pragma unroll
            for (int j = 0; j < 4; j++) {
                uint32_t off = hoff + (uint32_t)(j * 16) * 2;
                uint32_t bh0, bh1, bh2, bh3, bl0, bl1, bl2, bl3;
                ldsm4t(bh0, bh1, bh2, bh3, sbh_base[buf] + off);
                ldsm4t(bl0, bl1, bl2, bl3, sbl_base[buf] + off);
                float* c0 = acc[2 * j];
                float* c1 = acc[2 * j + 1];
                mma_bf16(c0, ah[0], ah[1], ah[2], ah[3], bh0, bh1);
                mma_bf16(c0, al[0], al[1], al[2], al[3], bh0, bh1);
                mma_bf16(c0, ah[0], ah[1], ah[2], ah[3], bl0, bl1);
                mma_bf16(c1, ah[0], ah[1], ah[2], ah[3], bh2, bh3);
                mma_bf16(c1, al[0], al[1], al[2], al[3], bh2, bh3);
                mma_bf16(c1, ah[0], ah[1], ah[2], ah[3], bl2, bl3);
            }
        }
        __syncthreads();
    }

    const float b0 = bias[row0], b1 = bias[row1];
    #pragma unroll
    for (int nf = 0; nf < 8; nf++) {
        int col = bn + wc + nf * 8 + 2 * q;
        *(float2*)&C[row0 * NPIX + col] = make_float2(acc[nf][0] + b0, acc[nf][1] + b0);
        *(float2*)&C[row1 * NPIX + col] = make_float2(acc[nf][2] + b1, acc[nf][3] + b1);
    }
}

// ============================================================================
// mma.sync bf16 flash attention — full K/V resident, ldmatrix, PAIRED m-tiles
// ============================================================================
#define KSTR 40
#define VSTRF 792
#define NW    14

#define A_SKH 0
#define A_SKL (A_SKH + LTOK * KSTR * 2)
#define A_SVH (A_SKL + LTOK * KSTR * 2)
#define A_SVL (A_SVH + HDIM * VSTRF * 2)
#define A_SB  (A_SVL + HDIM * VSTRF * 2)
#define A_TOTAL (A_SB + 256)

__global__ __launch_bounds__(448, 1) void attn_mma(
    const float* __restrict__ tab_h, const float* __restrict__ tab_v)
{
    extern __shared__ char asm_[];
    ushort_t* sKhi = (ushort_t*)(asm_ + A_SKH);
    ushort_t* sKlo = (ushort_t*)(asm_ + A_SKL);
    ushort_t* sVhi = (ushort_t*)(asm_ + A_SVH);
    ushort_t* sVlo = (ushort_t*)(asm_ + A_SVL);
    float* sb = (float*)(asm_ + A_SB);

    const int tid = threadIdx.x;
    const int w = blockIdx.x, h = blockIdx.y, br = blockIdx.z;
    const float* __restrict__ qkv = br ? g_qkv_v : g_qkv_h;
    float* __restrict__ outp = br ? g_att_v : g_att_h;
    const float* __restrict__ tab = br ? tab_v : tab_h;

    if (tid < 49) {
        int r1 = tid / 7, r2 = tid % 7, off = r1 - r2 + 6;
        sb[tid] = br ? tab[(6 * 13 + off) * NHEAD + h]
                     : tab[(off * 13 + 6) * NHEAD + h];
    }
    for (int i = tid; i < LTOK * 8; i += 448) {
        int k = i >> 3, d = 24 + (i & 7);
        sKhi[k * KSTR + d] = 0; sKlo[k * KSTR + d] = 0;
    }
    if (tid < HDIM * 8) {
        int d = tid >> 3, k = LTOK + (tid & 7);
        sVhi[d * VSTRF + k] = 0; sVlo[d * VSTRF + k] = 0;
    }
    for (int idx = tid; idx < LTOK * HDIM; idx += 448) {
        int d = idx / LTOK, k = idx - d * LTOK;
        int pix = br ? ((k / 7) * 112 + w * 7 + (k % 7)) : (w * LTOK + k);
        float kv = qkv[(192 + h * HDIM + d) * HWPIX + pix];
        float vv = qkv[(384 + h * HDIM + d) * HWPIX + pix];
        __nv_bfloat16 kh = __float2bfloat16(kv);
        __nv_bfloat16 vh = __float2bfloat16(vv);
        sKhi[k * KSTR + d] = __bfloat16_as_ushort(kh);
        sKlo[k * KSTR + d] = __bfloat16_as_ushort(__float2bfloat16(kv - __bfloat162float(kh)));
        sVhi[d * VSTRF + k] = __bfloat16_as_ushort(vh);
        sVlo[d * VSTRF + k] = __bfloat16_as_ushort(__float2bfloat16(vv - __bfloat162float(vh)));
    }
    __syncthreads();

    const int warp = tid >> 5, lane = tid & 31;
    const int g = lane >> 2, q = lane & 3;
    const int d0 = 2 * q;
    const int lr = lane & 7;

    const uint32_t kln = (uint32_t)((lr * KSTR + (lane >> 3) * 8) * 2);
    const uint32_t skh_b = s2u(sKhi) + kln;
    const uint32_t skl_b = s2u(sKlo) + kln;
    const int vko = ((lane >> 3) & 1) * 8;
    const int vdh = ((lane >> 4) & 1) * 8 + lr;
    const uint32_t sv1 = s2u(sVhi) + (uint32_t)((vdh * VSTRF + vko) * 2);
    const uint32_t sv2 = (lane < 16)
        ? s2u(sVhi) + (uint32_t)(((16 + lr) * VSTRF + vko) * 2)
        : s2u(sVlo) + (uint32_t)((lr * VSTRF + vko) * 2);
    const uint32_t sv3 = s2u(sVlo) + (uint32_t)(((8 + ((lane >> 4) & 1) * 8 + lr) * VSTRF + vko) * 2);

    // paired m-tile loop: 25 pairs cover tiles 0..48 (last pair duplicates 48)
    for (int p = warp; p < 25; p += NW) {
        const int mtA = 2 * p;
        const bool hasY = (mtA + 1) < 49;
        int mts[2]; mts[0] = mtA; mts[1] = hasY ? mtA + 1 : mtA;

        int pix0[2], pix1[2], bro0[2], bro1[2];
        uint32_t qh[2][6], ql[2][6];
        float o[2][3][4];
        float rs0[2], rs1[2];

        #pragma unroll
        for (int t = 0; t < 2; t++) {
            const int r0 = mts[t] * 16 + g, r1 = r0 + 8;
            pix0[t] = br ? ((r0 / 7) * 112 + w * 7 + (r0 % 7)) : (w * LTOK + r0);
            pix1[t] = br ? ((r1 / 7) * 112 + w * 7 + (r1 % 7)) : (w * LTOK + r1);
            bro0[t] = (br ? (r0 % 7) : (r0 / 112)) * 7;
            bro1[t] = (br ? (r1 % 7) : (r1 / 112)) * 7;
            #pragma unroll
            for (int pp = 0; pp < 3; pp++) {
                int d = d0 + 8 * pp;
                float a0v = qkv[(h * HDIM + d)     * HWPIX + pix0[t]] * SCALE_F;
                float a1v = qkv[(h * HDIM + d + 1) * HWPIX + pix0[t]] * SCALE_F;
                float b0v = qkv[(h * HDIM + d)     * HWPIX + pix1[t]] * SCALE_F;
                float b1v = qkv[(h * HDIM + d + 1) * HWPIX + pix1[t]] * SCALE_F;
                uint32_t hA = bfp(a0v, a1v), hB = bfp(b0v, b1v);
                qh[t][2 * pp] = hA; qh[t][2 * pp + 1] = hB;
                ql[t][2 * pp]     = bfp(a0v - bflo(hA), a1v - bfhi(hA));
                ql[t][2 * pp + 1] = bfp(b0v - bflo(hB), b1v - bfhi(hB));
            }
            rs0[t] = 0.f; rs1[t] = 0.f;
            #pragma unroll
            for (int nd = 0; nd < 3; nd++)
                #pragma unroll
                for (int i = 0; i < 4; i++) o[t][nd][i] = 0.f;
        }

        for (int kt = 0; kt < 14; kt++) {
            const int kbase = kt * 56;
            float bh0[2], bh1[2];
            if (!br) {
                #pragma unroll
                for (int t = 0; t < 2; t++) {
                    bh0[t] = sb[bro0[t] + (kt >> 1)];
                    bh1[t] = sb[bro1[t] + (kt >> 1)];
                }
            }

            #pragma unroll
            for (int ks = 0; ks < 4; ks++) {
                const int nt0 = 2 * ks, nt1 = nt0 + 1;
                const bool has1 = (nt1 < 7);
                float sA[2][4] = {{0.f,0.f,0.f,0.f},{0.f,0.f,0.f,0.f}};
                float sB[2][4] = {{0.f,0.f,0.f,0.f},{0.f,0.f,0.f,0.f}};

                {
                    uint32_t ko = (uint32_t)((kbase + nt0 * 8) * KSTR * 2);
                    uint32_t h0, h1, h2, h3, l0, l1, l2, l3;
                    ldsm4(h0, h1, h2, h3, skh_b + ko);
                    ldsm4(l0, l1, l2, l3, skl_b + ko);
                    #pragma unroll
                    for (int t = 0; t < 2; t++) {
                        mma_bf16(sA[t], qh[t][0], qh[t][1], qh[t][2], qh[t][3], h0, h1);
                        mma_bf16(sA[t], ql[t][0], ql[t][1], ql[t][2], ql[t][3], h0, h1);
                        mma_bf16(sA[t], qh[t][0], qh[t][1], qh[t][2], qh[t][3], l0, l1);
                        mma_bf16(sA[t], qh[t][4], qh[t][5], 0u, 0u, h2, h3);
                        mma_bf16(sA[t], ql[t][4], ql[t][5], 0u, 0u, h2, h3);
                        mma_bf16(sA[t], qh[t][4], qh[t][5], 0u, 0u, l2, l3);
                    }
                }
                if (has1) {
                    uint32_t ko = (uint32_t)((kbase + nt1 * 8) * KSTR * 2);
                    uint32_t h0, h1, h2, h3, l0, l1, l2, l3;
                    ldsm4(h0, h1, h2, h3, skh_b + ko);
                    ldsm4(l0, l1, l2, l3, skl_b + ko);
                    #pragma unroll
                    for (int t = 0; t < 2; t++) {
                        mma_bf16(sB[t], qh[t][0], qh[t][1], qh[t][2], qh[t][3], h0, h1);
                        mma_bf16(sB[t], ql[t][0], ql[t][1], ql[t][2], ql[t][3], h0, h1);
                        mma_bf16(sB[t], qh[t][0], qh[t][1], qh[t][2], qh[t][3], l0, l1);
                        mma_bf16(sB[t], qh[t][4], qh[t][5], 0u, 0u, h2, h3);
                        mma_bf16(sB[t], ql[t][4], ql[t][5], 0u, 0u, h2, h3);
                        mma_bf16(sB[t], qh[t][4], qh[t][5], 0u, 0u, l2, l3);
                    }
                }

                uint32_t pa[2][4], pl[2][4];
                #pragma unroll
                for (int t = 0; t < 2; t++) {
                    float eA0, eA1, eA2, eA3, eB0 = 0.f, eB1 = 0.f, eB2 = 0.f, eB3 = 0.f;
                    if (!br) {
                        eA0 = __expf(sA[t][0] + bh0[t]); eA1 = __expf(sA[t][1] + bh0[t]);
                        eA2 = __expf(sA[t][2] + bh1[t]); eA3 = __expf(sA[t][3] + bh1[t]);
                        if (has1) {
                            eB0 = __expf(sB[t][0] + bh0[t]); eB1 = __expf(sB[t][1] + bh0[t]);
                            eB2 = __expf(sB[t][2] + bh1[t]); eB3 = __expf(sB[t][3] + bh1[t]);
                        }
                    } else {
                        int i0 = (nt0 + d0) % 7;
                        int i1 = i0 + 1; if (i1 == 7) i1 = 0;
                        int j1 = i1 + 1; if (j1 == 7) j1 = 0;
                        eA0 = __expf(sA[t][0] + sb[bro0[t] + i0]); eA1 = __expf(sA[t][1] + sb[bro0[t] + i1]);
                        eA2 = __expf(sA[t][2] + sb[bro1[t] + i0]); eA3 = __expf(sA[t][3] + sb[bro1[t] + i1]);
                        if (has1) {
                            eB0 = __expf(sB[t][0] + sb[bro0[t] + i1]); eB1 = __expf(sB[t][1] + sb[bro0[t] + j1]);
                            eB2 = __expf(sB[t][2] + sb[bro1[t] + i1]); eB3 = __expf(sB[t][3] + sb[bro1[t] + j1]);
                        }
                    }
                    rs0[t] += eA0 + eA1 + eB0 + eB1;
                    rs1[t] += eA2 + eA3 + eB2 + eB3;

                    pa[t][0] = bfp(eA0, eA1); pa[t][1] = bfp(eA2, eA3);
                    pa[t][2] = has1 ? bfp(eB0, eB1) : 0u;
                    pa[t][3] = has1 ? bfp(eB2, eB3) : 0u;
                    pl[t][0] = bfp(eA0 - bflo(pa[t][0]), eA1 - bfhi(pa[t][0]));
                    pl[t][1] = bfp(eA2 - bflo(pa[t][1]), eA3 - bfhi(pa[t][1]));
                    pl[t][2] = has1 ? bfp(eB0 - bflo(pa[t][2]), eB1 - bfhi(pa[t][2])) : 0u;
                    pl[t][3] = has1 ? bfp(eB2 - bflo(pa[t][3]), eB3 - bfhi(pa[t][3])) : 0u;
                }

                {
                    uint32_t vo = (uint32_t)((kbase + ks * 16) * 2);
                    uint32_t va0, va1, va2, va3, vb0, vb1, vb2, vb3, vc0, vc1, vc2, vc3;
                    ldsm4(va0, va1, va2, va3, sv1 + vo);   // nd0 hi | nd1 hi
                    ldsm4(vb0, vb1, vb2, vb3, sv2 + vo);   // nd2 hi | nd0 lo
                    ldsm4(vc0, vc1, vc2, vc3, sv3 + vo);   // nd1 lo | nd2 lo
                    #pragma unroll
                    for (int t = 0; t < 2; t++) {
                        mma_bf16(o[t][0], pa[t][0], pa[t][1], pa[t][2], pa[t][3], va0, va1);
                        mma_bf16(o[t][0], pl[t][0], pl[t][1], pl[t][2], pl[t][3], va0, va1);
                        mma_bf16(o[t][0], pa[t][0], pa[t][1], pa[t][2], pa[t][3], vb2, vb3);
                        mma_bf16(o[t][1], pa[t][0], pa[t][1], pa[t][2], pa[t][3], va2, va3);
                        mma_bf16(o[t][1], pl[t][0], pl[t][1], pl[t][2], pl[t][3], va2, va3);
                        mma_bf16(o[t][1], pa[t][0], pa[t][1], pa[t][2], pa[t][3], vc0, vc1);
                        mma_bf16(o[t][2], pa[t][0], pa[t][1], pa[t][2], pa[t][3], vb0, vb1);
                        mma_bf16(o[t][2], pl[t][0], pl[t][1], pl[t][2], pl[t][3], vb0, vb1);
                        mma_bf16(o[t][2], pa[t][0], pa[t][1], pa[t][2], pa[t][3], vc2, vc3);
                    }
                }
            }
        }

        #pragma unroll
        for (int t = 0; t < 2; t++) {
            if (t == 1 && !hasY) break;
            float a0 = rs0[t], a1 = rs1[t];
            a0 += __shfl_xor_sync(0xFFFFFFFFu, a0, 1);
            a0 += __shfl_xor_sync(0xFFFFFFFFu, a0, 2);
            a1 += __shfl_xor_sync(0xFFFFFFFFu, a1, 1);
            a1 += __shfl_xor_sync(0xFFFFFFFFu, a1, 2);
            float inv0 = 1.f / a0, inv1 = 1.f / a1;
            #pragma unroll
            for (int nd = 0; nd < 3; nd++) {
                int d = nd * 8 + d0;
                outp[(h * HDIM + d)     * HWPIX + pix0[t]] = o[t][nd][0] * inv0;
                outp[(h * HDIM + d + 1) * HWPIX + pix0[t]] = o[t][nd][1] * inv0;
                outp[(h * HDIM + d)     * HWPIX + pix1[t]] = o[t][nd][2] * inv1;
                outp[(h * HDIM + d + 1) * HWPIX + pix1[t]] = o[t][nd][3] * inv1;
            }
        }
    }
}

// ---------------- fused dual LePE -> 0.5*(h+v) -> bf16 hi/lo planes ----------------
__global__ __launch_bounds__(256) void lepe_fused(
    const float* __restrict__ attH, const float* __restrict__ attV,
    const float* __restrict__ wH, const float* __restrict__ bH,
    const float* __restrict__ wV, const float* __restrict__ bV,
    ushort_t* __restrict__ phi, ushort_t* __restrict__ plo)
{
    int t = blockIdx.x * blockDim.x + threadIdx.x;
    if (t >= Cdim * (HWPIX / 4)) return;
    int c = t / (HWPIX / 4);
    int r = t % (HWPIX / 4);
    int y = r / 28, x4 = (r % 28) * 4;
    const float* baseH = attH + c * HWPIX;
    const float* baseV = attV + c * HWPIX;

    float wvh[9], wvv[9];
    #pragma unroll
    for (int i = 0; i < 9; i++) { wvh[i] = wH[c * 9 + i]; wvv[i] = wV[c * 9 + i]; }
    float ah0 = bH[c], ah1 = ah0, ah2 = ah0, ah3 = ah0;
    float av0 = bV[c], av1 = av0, av2 = av0, av3 = av0;

    #pragma unroll
    for (int ky = 0; ky < 3; ky++) {
        int yy = y + ky - 1;
        if (yy < 0 || yy >= 112) continue;
        const float* rpH = baseH + yy * 112 + x4;
        const float* rpV = baseV + yy * 112 + x4;
        float4 mH = *(const float4*)rpH;
        float4 mV = *(const float4*)rpV;
        float lfH = (x4 > 0)   ? rpH[-1] : 0.f;
        float rtH = (x4 < 108) ? rpH[4]  : 0.f;
        float lfV = (x4 > 0)   ? rpV[-1] : 0.f;
        float rtV = (x4 < 108) ? rpV[4]  : 0.f;
        float h0 = wvh[ky*3], h1 = wvh[ky*3+1], h2 = wvh[ky*3+2];
        float v0 = wvv[ky*3], v1 = wvv[ky*3+1], v2 = wvv[ky*3+2];
        ah0 += h0 * lfH  + h1 * mH.x + h2 * mH.y;
        ah1 += h0 * mH.x + h1 * mH.y + h2 * mH.z;
        ah2 += h0 * mH.y + h1 * mH.z + h2 * mH.w;
        ah3 += h0 * mH.z + h1 * mH.w + h2 * rtH;
        av0 += v0 * lfV  + v1 * mV.x + v2 * mV.y;
        av1 += v0 * mV.x + v1 * mV.y + v2 * mV.z;
        av2 += v0 * mV.y + v1 * mV.z + v2 * mV.w;
        av3 += v0 * mV.z + v1 * mV.w + v2 * rtV;
    }

    float4 inH = *(const float4*)(baseH + y * 112 + x4);
    float4 inV = *(const float4*)(baseV + y * 112 + x4);
    const float RS2 = 0.70710678118654752f;
    float oh0 = inH.x + 0.5f * ah0 * (1.f + erff(ah0 * RS2));
    float oh1 = inH.y + 0.5f * ah1 * (1.f + erff(ah1 * RS2));
    float oh2 = inH.z + 0.5f * ah2 * (1.f + erff(ah2 * RS2));
    float oh3 = inH.w + 0.5f * ah3 * (1.f + erff(ah3 * RS2));
    float ov0 = inV.x + 0.5f * av0 * (1.f + erff(av0 * RS2));
    float ov1 = inV.y + 0.5f * av1 * (1.f + erff(av1 * RS2));
    float ov2 = inV.z + 0.5f * av2 * (1.f + erff(av2 * RS2));
    float ov3 = inV.w + 0.5f * av3 * (1.f + erff(av3 * RS2));

    float p0 = 0.5f * (oh0 + ov0);
    float p1 = 0.5f * (oh1 + ov1);
    float p2 = 0.5f * (oh2 + ov2);
    float p3 = 0.5f * (oh3 + ov3);

    uint32_t h0w = bfp(p0, p1), h1w = bfp(p2, p3);
    uint32_t l0w = bfp(p0 - bflo(h0w), p1 - bfhi(h0w));
    uint32_t l1w = bfp(p2 - bflo(h1w), p3 - bfhi(h1w));
    int idx = c * HWPIX + y * 112 + x4;
    *(uint2*)&phi[idx] = make_uint2(h0w, h1w);
    *(uint2*)&plo[idx] = make_uint2(l0w, l1w);
}

// ---------------- launch ----------------
extern "C" void kernel_launch(void* const* d_in, const int* in_sizes, int n_in,
                              void* d_out, int out_size)
{
    const float* x        = (const float*)d_in[0];
    const float* qkv_h_w  = (const float*)d_in[1];
    const float* qkv_h_b  = (const float*)d_in[2];
    const float* qkv_v_w  = (const float*)d_in[3];
    const float* qkv_v_b  = (const float*)d_in[4];
    const float* proj_w   = (const float*)d_in[5];
    const float* proj_b   = (const float*)d_in[6];
    const float* lepe_h_w = (const float*)d_in[7];
    const float* lepe_h_b = (const float*)d_in[8];
    const float* lepe_v_w = (const float*)d_in[9];
    const float* lepe_v_b = (const float*)d_in[10];
    const float* tab_h    = (const float*)d_in[11];
    const float* tab_v    = (const float*)d_in[12];
    float* out = (float*)d_out;

    float *qh, *qv, *ah, *av;
    ushort_t *xhi, *xlo, *phi, *plo, *whh, *whl, *wvh, *wvl, *pwh, *pwl;
    cudaGetSymbolAddress((void**)&qh, g_qkv_h);
    cudaGetSymbolAddress((void**)&qv, g_qkv_v);
    cudaGetSymbolAddress((void**)&ah, g_att_h);
    cudaGetSymbolAddress((void**)&av, g_att_v);
    cudaGetSymbolAddress((void**)&xhi, g_xhi);
    cudaGetSymbolAddress((void**)&xlo, g_xlo);
    cudaGetSymbolAddress((void**)&phi, g_phi);
    cudaGetSymbolAddress((void**)&plo, g_plo);
    cudaGetSymbolAddress((void**)&whh, g_whh);
    cudaGetSymbolAddress((void**)&whl, g_whl);
    cudaGetSymbolAddress((void**)&wvh, g_wvh);
    cudaGetSymbolAddress((void**)&wvl, g_wvl);
    cudaGetSymbolAddress((void**)&pwh, g_pwh);
    cudaGetSymbolAddress((void**)&pwl, g_pwl);

    int nx4 = GK * NPIX / 4;
    split_kernel<<<(nx4 + 255) / 256, 256>>>((const float4*)x, (uint2*)xhi, (uint2*)xlo, nx4);
    int nw4 = M_QKV * GK / 4;
    int np4 = M_PROJ * GK / 4;
    int ntotw = nw4 * 2 + np4;
    split_weights<<<(ntotw + 255) / 256, 256>>>(
        (const float4*)qkv_h_w, (uint2*)whh, (uint2*)whl, nw4,
        (const float4*)qkv_v_w, (uint2*)wvh, (uint2*)wvl, nw4,
        (const float4*)proj_w,  (uint2*)pwh, (uint2*)pwl, np4);

    cudaFuncSetAttribute(gemm_mma,
                         cudaFuncAttributeMaxDynamicSharedMemorySize, G_TOTAL_BYTES);
    dim3 gq(NPIX / 128, M_QKV / 64);
    gemm_mma<<<gq, 256, G_TOTAL_BYTES>>>(whh, whl, xhi, xlo, qkv_h_b, qh);
    gemm_mma<<<gq, 256, G_TOTAL_BYTES>>>(wvh, wvl, xhi, xlo, qkv_v_b, qv);

    cudaFuncSetAttribute(attn_mma,
                         cudaFuncAttributeMaxDynamicSharedMemorySize, A_TOTAL);
    dim3 ga(16, NHEAD, 2);
    attn_mma<<<ga, 448, A_TOTAL>>>(tab_h, tab_v);

    int nthr = Cdim * (HWPIX / 4);
    lepe_fused<<<(nthr + 255) / 256, 256>>>(ah, av, lepe_h_w, lepe_h_b,
                                            lepe_v_w, lepe_v_b, phi, plo);

    dim3 gp(NPIX / 128, M_PROJ / 64);
    gemm_mma<<<gp, 256, G_TOTAL_BYTES>>>(pwh, pwl, phi, plo, proj_b, out);
}

// round 10
// speedup vs baseline: 1.1225x; 1.1225x over previous
#include <cuda_runtime.h>
#include <cuda_bf16.h>
#include <cstdint>
#include <math.h>

#define Cdim   192
#define NHEAD  8
#define HDIM   24
#define HWPIX  12544          // 112*112
#define LTOK   784            // 7*112
#define GK     192            // gemm K
#define NPIX   12544
#define M_QKV  576
#define M_PROJ 192
#define SCALE_F 0.20412414523193154f  // 24^-0.5
#define LOG2E   1.44269504088896340736f

typedef unsigned short ushort_t;

// ---------------- scratch (device globals; no allocation) ----------------
__device__ float g_qkv_h[M_QKV * HWPIX];
__device__ float g_qkv_v[M_QKV * HWPIX];
__device__ float g_att_h[Cdim * HWPIX];
__device__ float g_att_v[Cdim * HWPIX];
__device__ ushort_t g_xhi[GK * NPIX];
__device__ ushort_t g_xlo[GK * NPIX];
__device__ ushort_t g_phi[GK * NPIX];
__device__ ushort_t g_plo[GK * NPIX];
__device__ ushort_t g_whh[M_QKV * GK];
__device__ ushort_t g_whl[M_QKV * GK];
__device__ ushort_t g_wvh[M_QKV * GK];
__device__ ushort_t g_wvl[M_QKV * GK];
__device__ ushort_t g_pwh[M_PROJ * GK];
__device__ ushort_t g_pwl[M_PROJ * GK];

// ---------------- bf16 helpers ----------------
__device__ __forceinline__ uint32_t bfp(float lo_el, float hi_el) {
    uint32_t r;
    asm("cvt.rn.bf16x2.f32 %0, %1, %2;" : "=r"(r) : "f"(hi_el), "f"(lo_el));
    return r;
}
__device__ __forceinline__ float bflo(uint32_t p) { return __uint_as_float(p << 16); }
__device__ __forceinline__ float bfhi(uint32_t p) { return __uint_as_float(p & 0xFFFF0000u); }

__device__ __forceinline__ uint32_t s2u(const void* p) {
    uint32_t a;
    asm("{ .reg .u64 t; cvta.to.shared.u64 t, %1; cvt.u32.u64 %0, t; }" : "=r"(a) : "l"(p));
    return a;
}
__device__ __forceinline__ float ex2f(float x) {
    float r;
    asm("ex2.approx.f32 %0, %1;" : "=f"(r) : "f"(x));
    return r;
}

__device__ __forceinline__ void mma_bf16(float* c,
    uint32_t a0, uint32_t a1, uint32_t a2, uint32_t a3,
    uint32_t b0, uint32_t b1)
{
    asm volatile("mma.sync.aligned.m16n8k16.row.col.f32.bf16.bf16.f32 "
        "{%0,%1,%2,%3}, {%4,%5,%6,%7}, {%8,%9}, {%0,%1,%2,%3};"
        : "+f"(c[0]), "+f"(c[1]), "+f"(c[2]), "+f"(c[3])
        : "r"(a0), "r"(a1), "r"(a2), "r"(a3), "r"(b0), "r"(b1));
}
__device__ __forceinline__ void mma_bf16_k8(float* c,
    uint32_t a0, uint32_t a1, uint32_t b0)
{
    asm volatile("mma.sync.aligned.m16n8k8.row.col.f32.bf16.bf16.f32 "
        "{%0,%1,%2,%3}, {%4,%5}, {%6}, {%0,%1,%2,%3};"
        : "+f"(c[0]), "+f"(c[1]), "+f"(c[2]), "+f"(c[3])
        : "r"(a0), "r"(a1), "r"(b0));
}

__device__ __forceinline__ void ldsm4t(uint32_t& r0, uint32_t& r1,
                                       uint32_t& r2, uint32_t& r3, uint32_t a)
{
    asm volatile("ldmatrix.sync.aligned.m8n8.x4.trans.shared.b16 {%0,%1,%2,%3}, [%4];"
        : "=r"(r0), "=r"(r1), "=r"(r2), "=r"(r3) : "r"(a));
}
__device__ __forceinline__ void ldsm4(uint32_t& r0, uint32_t& r1,
                                      uint32_t& r2, uint32_t& r3, uint32_t a)
{
    asm volatile("ldmatrix.sync.aligned.m8n8.x4.shared.b16 {%0,%1,%2,%3}, [%4];"
        : "=r"(r0), "=r"(r1), "=r"(r2), "=r"(r3) : "r"(a));
}

#define CPA16(dst, src) asm volatile("cp.async.ca.shared.global [%0], [%1], 16;" :: "r"(dst), "l"(src) : "memory")
#define CPC()  asm volatile("cp.async.commit_group;" ::: "memory")
#define CPW1() asm volatile("cp.async.wait_group 1;" ::: "memory")
#define CPW0() asm volatile("cp.async.wait_group 0;" ::: "memory")

// ---------------- split fp32 -> bf16 hi/lo planes (vec4) ----------------
__global__ __launch_bounds__(256) void split_kernel(
    const float4* __restrict__ in, uint2* __restrict__ hi,
    uint2* __restrict__ lo, int n4)
{
    int i = blockIdx.x * blockDim.x + threadIdx.x;
    if (i >= n4) return;
    float4 v = in[i];
    uint32_t h0 = bfp(v.x, v.y);
    uint32_t h1 = bfp(v.z, v.w);
    uint32_t l0 = bfp(v.x - bflo(h0), v.y - bfhi(h0));
    uint32_t l1 = bfp(v.z - bflo(h1), v.w - bfhi(h1));
    hi[i] = make_uint2(h0, h1);
    lo[i] = make_uint2(l0, l1);
}

__global__ __launch_bounds__(256) void split_weights(
    const float4* __restrict__ w1, uint2* __restrict__ h1p, uint2* __restrict__ l1p, int n1,
    const float4* __restrict__ w2, uint2* __restrict__ h2p, uint2* __restrict__ l2p, int n2,
    const float4* __restrict__ w3, uint2* __restrict__ h3p, uint2* __restrict__ l3p, int n3)
{
    int i = blockIdx.x * blockDim.x + threadIdx.x;
    const float4* src; uint2 *hd, *ld; int j = i;
    if (j < n1) { src = w1; hd = h1p; ld = l1p; }
    else if ((j -= n1) < n2) { src = w2; hd = h2p; ld = l2p; }
    else if ((j -= n2) < n3) { src = w3; hd = h3p; ld = l3p; }
    else return;
    float4 v = src[j];
    uint32_t h0 = bfp(v.x, v.y);
    uint32_t h1 = bfp(v.z, v.w);
    uint32_t l0 = bfp(v.x - bflo(h0), v.y - bfhi(h0));
    uint32_t l1 = bfp(v.z - bflo(h1), v.w - bfhi(h1));
    hd[j] = make_uint2(h0, h1);
    ld[j] = make_uint2(l0, l1);
}

// ---------------- hi/lo bf16 mma GEMM, A staged + ldmatrix, cp.async DB ------------
#define G_SBH 0
#define G_SBL 8704
#define G_SAH 17408
#define G_SAL 22528
#define G_BSTR 136
#define G_BBUF 4352
#define G_ASTR 40
#define G_ABUF 2560
#define G_TOTAL_BYTES 55296

__global__ __launch_bounds__(256) void gemm_mma(
    const ushort_t* __restrict__ Ahi, const ushort_t* __restrict__ Alo,
    const ushort_t* __restrict__ Bhi, const ushort_t* __restrict__ Blo,
    const float* __restrict__ bias, float* __restrict__ C)
{
    extern __shared__ ushort_t gsm[];
    const int tid = threadIdx.x;
    const int bn = blockIdx.x * 128, bm = blockIdx.y * 64;
    const int wid = tid >> 5, lane = tid & 31;
    const int wm = wid & 3, wn = wid >> 2;
    const int g = lane >> 2, q = lane & 3;
    const int wc = wn * 64;
    const int row0 = bm + wm * 16 + g;
    const int row1 = row0 + 8;

    float acc[8][4];
    #pragma unroll
    for (int i = 0; i < 8; i++)
        #pragma unroll
        for (int j = 0; j < 4; j++) acc[i][j] = 0.f;

    const int rB = tid >> 3;
    const int cB = (tid & 7) * 8;
    const int rA = tid >> 2;
    const int cA = (tid & 3) * 8;

    uint32_t smb = s2u(gsm);
    uint32_t dstBh[2], dstBl[2], dstAh[2], dstAl[2];
    #pragma unroll
    for (int b = 0; b < 2; b++) {
        dstBh[b] = smb + (uint32_t)((G_SBH + b * G_BBUF + rB * G_BSTR + cB) * 2);
        dstBl[b] = smb + (uint32_t)((G_SBL + b * G_BBUF + rB * G_BSTR + cB) * 2);
        dstAh[b] = smb + (uint32_t)((G_SAH + b * G_ABUF + rA * G_ASTR + cA) * 2);
        dstAl[b] = smb + (uint32_t)((G_SAL + b * G_ABUF + rA * G_ASTR + cA) * 2);
    }

    const int lm = lane >> 3, lr = lane & 7;
    const int lkrow = (lm & 1) * 8 + lr;
    const int lncol = wc + (lm >> 1) * 8;
    uint32_t sbh_base[2], sbl_base[2];
    const int arow = wm * 16 + (lm & 1) * 8 + lr;
    const int acol = (lane >> 4) * 8;
    uint32_t sah_base[2], sal_base[2];
    #pragma unroll
    for (int b = 0; b < 2; b++) {
        sbh_base[b] = smb + (uint32_t)((G_SBH + b * G_BBUF + lkrow * G_BSTR + lncol) * 2);
        sbl_base[b] = smb + (uint32_t)((G_SBL + b * G_BBUF + lkrow * G_BSTR + lncol) * 2);
        sah_base[b] = smb + (uint32_t)((G_SAH + b * G_ABUF + arow * G_ASTR + acol) * 2);
        sal_base[b] = smb + (uint32_t)((G_SAL + b * G_ABUF + arow * G_ASTR + acol) * 2);
    }

    {
        const ushort_t* bh = &Bhi[rB * NPIX + bn + cB];
        const ushort_t* bl = &Blo[rB * NPIX + bn + cB];
        CPA16(dstBh[0], bh); CPA16(dstBh[0] + 128, bh + 64);
        CPA16(dstBl[0], bl); CPA16(dstBl[0] + 128, bl + 64);
        CPA16(dstAh[0], &Ahi[(bm + rA) * GK + cA]);
        CPA16(dstAl[0], &Alo[(bm + rA) * GK + cA]);
        CPC();
    }

    #pragma unroll
    for (int ki = 0; ki < 6; ki++) {
        if (ki < 5) {
            const int kn = (ki + 1) * 32;
            const int bf = (ki + 1) & 1;
            const ushort_t* bh = &Bhi[(kn + rB) * NPIX + bn + cB];
            const ushort_t* bl = &Blo[(kn + rB) * NPIX + bn + cB];
            CPA16(dstBh[bf], bh); CPA16(dstBh[bf] + 128, bh + 64);
            CPA16(dstBl[bf], bl); CPA16(dstBl[bf] + 128, bl + 64);
            CPA16(dstAh[bf], &Ahi[(bm + rA) * GK + kn + cA]);
            CPA16(dstAl[bf], &Alo[(bm + rA) * GK + kn + cA]);
            CPC();
            CPW1();
        } else {
            CPW0();
        }
        __syncthreads();

        const int buf = ki & 1;
        #pragma unroll
        for (int hh = 0; hh < 2; hh++) {
            uint32_t ah[4], al[4];
            ldsm4(ah[0], ah[1], ah[2], ah[3], sah_base[buf] + hh * 32);
            ldsm4(al[0], al[1], al[2], al[3], sal_base[buf] + hh * 32);

            const uint32_t hoff = (uint32_t)(hh * 16 * G_BSTR) * 2;
            #pragma unroll
            for (int j = 0; j < 4; j++) {
                uint32_t off = hoff + (uint32_t)(j * 16) * 2;
                uint32_t bh0, bh1, bh2, bh3, bl0, bl1, bl2, bl3;
                ldsm4t(bh0, bh1, bh2, bh3, sbh_base[buf] + off);
                ldsm4t(bl0, bl1, bl2, bl3, sbl_base[buf] + off);
                float* c0 = acc[2 * j];
                float* c1 = acc[2 * j + 1];
                mma_bf16(c0, ah[0], ah[1], ah[2], ah[3], bh0, bh1);
                mma_bf16(c0, al[0], al[1], al[2], al[3], bh0, bh1);
                mma_bf16(c0, ah[0], ah[1], ah[2], ah[3], bl0, bl1);
                mma_bf16(c1, ah[0], ah[1], ah[2], ah[3], bh2, bh3);
                mma_bf16(c1, al[0], al[1], al[2], al[3], bh2, bh3);
                mma_bf16(c1, ah[0], ah[1], ah[2], ah[3], bl2, bl3);
            }
        }
        __syncthreads();
    }

    const float b0 = bias[row0], b1 = bias[row1];
    #pragma unroll
    for (int nf = 0; nf < 8; nf++) {
        int col = bn + wc + nf * 8 + 2 * q;
        *(float2*)&C[row0 * NPIX + col] = make_float2(acc[nf][0] + b0, acc[nf][1] + b0);
        *(float2*)&C[row1 * NPIX + col] = make_float2(acc[nf][2] + b1, acc[nf][3] + b1);
    }
}

// ============================================================================
// mma.sync bf16 flash attention — full K/V resident, ldmatrix, 16 warps,
// k8-mma for the padded dim chunk, ex2 with folded log2e.
// ============================================================================
#define KSTR 40
#define VSTRF 792
#define NW    16
#define NTHR  512

#define A_SKH 0
#define A_SKL (A_SKH + LTOK * KSTR * 2)
#define A_SVH (A_SKL + LTOK * KSTR * 2)
#define A_SVL (A_SVH + HDIM * VSTRF * 2)
#define A_SB  (A_SVL + HDIM * VSTRF * 2)
#define A_TOTAL (A_SB + 256)

__global__ __launch_bounds__(NTHR, 1) void attn_mma(
    const float* __restrict__ tab_h, const float* __restrict__ tab_v)
{
    extern __shared__ char asm_[];
    ushort_t* sKhi = (ushort_t*)(asm_ + A_SKH);
    ushort_t* sKlo = (ushort_t*)(asm_ + A_SKL);
    ushort_t* sVhi = (ushort_t*)(asm_ + A_SVH);
    ushort_t* sVlo = (ushort_t*)(asm_ + A_SVL);
    float* sb = (float*)(asm_ + A_SB);

    const int tid = threadIdx.x;
    const int w = blockIdx.x, h = blockIdx.y, br = blockIdx.z;
    const float* __restrict__ qkv = br ? g_qkv_v : g_qkv_h;
    float* __restrict__ outp = br ? g_att_v : g_att_h;
    const float* __restrict__ tab = br ? tab_v : tab_h;

    if (tid < 49) {
        int r1 = tid / 7, r2 = tid % 7, off = r1 - r2 + 6;
        float bv = br ? tab[(6 * 13 + off) * NHEAD + h]
                      : tab[(off * 13 + 6) * NHEAD + h];
        sb[tid] = bv * LOG2E;          // folded log2e
    }
    for (int i = tid; i < LTOK * 8; i += NTHR) {
        int k = i >> 3, d = 24 + (i & 7);
        sKhi[k * KSTR + d] = 0; sKlo[k * KSTR + d] = 0;
    }
    if (tid < HDIM * 8) {
        int d = tid >> 3, k = LTOK + (tid & 7);
        sVhi[d * VSTRF + k] = 0; sVlo[d * VSTRF + k] = 0;
    }
    for (int idx = tid; idx < LTOK * HDIM; idx += NTHR) {
        int d = idx / LTOK, k = idx - d * LTOK;
        int pix = br ? ((k / 7) * 112 + w * 7 + (k % 7)) : (w * LTOK + k);
        float kv = qkv[(192 + h * HDIM + d) * HWPIX + pix];
        float vv = qkv[(384 + h * HDIM + d) * HWPIX + pix];
        __nv_bfloat16 kh = __float2bfloat16(kv);
        __nv_bfloat16 vh = __float2bfloat16(vv);
        sKhi[k * KSTR + d] = __bfloat16_as_ushort(kh);
        sKlo[k * KSTR + d] = __bfloat16_as_ushort(__float2bfloat16(kv - __bfloat162float(kh)));
        sVhi[d * VSTRF + k] = __bfloat16_as_ushort(vh);
        sVlo[d * VSTRF + k] = __bfloat16_as_ushort(__float2bfloat16(vv - __bfloat162float(vh)));
    }
    __syncthreads();

    const int warp = tid >> 5, lane = tid & 31;
    const int g = lane >> 2, q = lane & 3;
    const int d0 = 2 * q;
    const int lr = lane & 7;

    const uint32_t kln = (uint32_t)((lr * KSTR + (lane >> 3) * 8) * 2);
    const uint32_t skh_b = s2u(sKhi) + kln;
    const uint32_t skl_b = s2u(sKlo) + kln;
    const int vko = ((lane >> 3) & 1) * 8;
    const int vdh = ((lane >> 4) & 1) * 8 + lr;
    const uint32_t sv1 = s2u(sVhi) + (uint32_t)((vdh * VSTRF + vko) * 2);
    const uint32_t sv2 = (lane < 16)
        ? s2u(sVhi) + (uint32_t)(((16 + lr) * VSTRF + vko) * 2)
        : s2u(sVlo) + (uint32_t)((lr * VSTRF + vko) * 2);
    const uint32_t sv3 = s2u(sVlo) + (uint32_t)(((8 + ((lane >> 4) & 1) * 8 + lr) * VSTRF + vko) * 2);

    const float qscale = SCALE_F * LOG2E;  // folded log2e

    for (int mt = warp; mt < 49; mt += NW) {
        const int r0 = mt * 16 + g, r1 = r0 + 8;
        const int pix0 = br ? ((r0 / 7) * 112 + w * 7 + (r0 % 7)) : (w * LTOK + r0);
        const int pix1 = br ? ((r1 / 7) * 112 + w * 7 + (r1 % 7)) : (w * LTOK + r1);
        const int bro0 = (br ? (r0 % 7) : (r0 / 112)) * 7;
        const int bro1 = (br ? (r1 % 7) : (r1 / 112)) * 7;

        uint32_t qh[6], ql[6];
        #pragma unroll
        for (int p = 0; p < 3; p++) {
            int d = d0 + 8 * p;
            float a0v = qkv[(h * HDIM + d)     * HWPIX + pix0] * qscale;
            float a1v = qkv[(h * HDIM + d + 1) * HWPIX + pix0] * qscale;
            float b0v = qkv[(h * HDIM + d)     * HWPIX + pix1] * qscale;
            float b1v = qkv[(h * HDIM + d + 1) * HWPIX + pix1] * qscale;
            uint32_t hA = bfp(a0v, a1v), hB = bfp(b0v, b1v);
            qh[2 * p] = hA; qh[2 * p + 1] = hB;
            ql[2 * p]     = bfp(a0v - bflo(hA), a1v - bfhi(hA));
            ql[2 * p + 1] = bfp(b0v - bflo(hB), b1v - bfhi(hB));
        }

        float o[3][4];
        #pragma unroll
        for (int nd = 0; nd < 3; nd++)
            #pragma unroll
            for (int i = 0; i < 4; i++) o[nd][i] = 0.f;
        float rs0 = 0.f, rs1 = 0.f;

        for (int kt = 0; kt < 14; kt++) {
            float bh0 = 0.f, bh1 = 0.f;
            if (!br) { bh0 = sb[bro0 + (kt >> 1)]; bh1 = sb[bro1 + (kt >> 1)]; }
            const int kbase = kt * 56;

            #pragma unroll
            for (int ks = 0; ks < 4; ks++) {
                const int nt0 = 2 * ks, nt1 = nt0 + 1;
                const bool has1 = (nt1 < 7);
                float sA[4] = {0.f, 0.f, 0.f, 0.f};
                float sB[4] = {0.f, 0.f, 0.f, 0.f};

                {
                    uint32_t ko = (uint32_t)((kbase + nt0 * 8) * KSTR * 2);
                    uint32_t h0, h1, h2, h3, l0, l1, l2, l3;
                    ldsm4(h0, h1, h2, h3, skh_b + ko);
                    ldsm4(l0, l1, l2, l3, skl_b + ko);
                    mma_bf16(sA, qh[0], qh[1], qh[2], qh[3], h0, h1);
                    mma_bf16(sA, ql[0], ql[1], ql[2], ql[3], h0, h1);
                    mma_bf16(sA, qh[0], qh[1], qh[2], qh[3], l0, l1);
                    mma_bf16_k8(sA, qh[4], qh[5], h2);
                    mma_bf16_k8(sA, ql[4], ql[5], h2);
                    mma_bf16_k8(sA, qh[4], qh[5], l2);
                }
                if (has1) {
                    uint32_t ko = (uint32_t)((kbase + nt1 * 8) * KSTR * 2);
                    uint32_t h0, h1, h2, h3, l0, l1, l2, l3;
                    ldsm4(h0, h1, h2, h3, skh_b + ko);
                    ldsm4(l0, l1, l2, l3, skl_b + ko);
                    mma_bf16(sB, qh[0], qh[1], qh[2], qh[3], h0, h1);
                    mma_bf16(sB, ql[0], ql[1], ql[2], ql[3], h0, h1);
                    mma_bf16(sB, qh[0], qh[1], qh[2], qh[3], l0, l1);
                    mma_bf16_k8(sB, qh[4], qh[5], h2);
                    mma_bf16_k8(sB, ql[4], ql[5], h2);
                    mma_bf16_k8(sB, qh[4], qh[5], l2);
                }

                float eA0, eA1, eA2, eA3, eB0 = 0.f, eB1 = 0.f, eB2 = 0.f, eB3 = 0.f;
                if (!br) {
                    eA0 = ex2f(sA[0] + bh0); eA1 = ex2f(sA[1] + bh0);
                    eA2 = ex2f(sA[2] + bh1); eA3 = ex2f(sA[3] + bh1);
                    if (has1) {
                        eB0 = ex2f(sB[0] + bh0); eB1 = ex2f(sB[1] + bh0);
                        eB2 = ex2f(sB[2] + bh1); eB3 = ex2f(sB[3] + bh1);
                    }
                } else {
                    int i0 = (nt0 + d0) % 7;
                    int i1 = i0 + 1; if (i1 == 7) i1 = 0;
                    int j1 = i1 + 1; if (j1 == 7) j1 = 0;
                    eA0 = ex2f(sA[0] + sb[bro0 + i0]); eA1 = ex2f(sA[1] + sb[bro0 + i1]);
                    eA2 = ex2f(sA[2] + sb[bro1 + i0]); eA3 = ex2f(sA[3] + sb[bro1 + i1]);
                    if (has1) {
                        eB0 = ex2f(sB[0] + sb[bro0 + i1]); eB1 = ex2f(sB[1] + sb[bro0 + j1]);
                        eB2 = ex2f(sB[2] + sb[bro1 + i1]); eB3 = ex2f(sB[3] + sb[bro1 + j1]);
                    }
                }
                rs0 += eA0 + eA1 + eB0 + eB1;
                rs1 += eA2 + eA3 + eB2 + eB3;

                uint32_t pa0 = bfp(eA0, eA1), pa1 = bfp(eA2, eA3);
                uint32_t pa2 = has1 ? bfp(eB0, eB1) : 0u;
                uint32_t pa3 = has1 ? bfp(eB2, eB3) : 0u;
                uint32_t pl0 = bfp(eA0 - bflo(pa0), eA1 - bfhi(pa0));
                uint32_t pl1 = bfp(eA2 - bflo(pa1), eA3 - bfhi(pa1));
                uint32_t pl2 = has1 ? bfp(eB0 - bflo(pa2), eB1 - bfhi(pa2)) : 0u;
                uint32_t pl3 = has1 ? bfp(eB2 - bflo(pa3), eB3 - bfhi(pa3)) : 0u;

                {
                    uint32_t vo = (uint32_t)((kbase + ks * 16) * 2);
                    uint32_t va0, va1, va2, va3, vb0, vb1, vb2, vb3, vc0, vc1, vc2, vc3;
                    ldsm4(va0, va1, va2, va3, sv1 + vo);   // nd0 hi | nd1 hi
                    ldsm4(vb0, vb1, vb2, vb3, sv2 + vo);   // nd2 hi | nd0 lo
                    ldsm4(vc0, vc1, vc2, vc3, sv3 + vo);   // nd1 lo | nd2 lo
                    mma_bf16(o[0], pa0, pa1, pa2, pa3, va0, va1);
                    mma_bf16(o[0], pl0, pl1, pl2, pl3, va0, va1);
                    mma_bf16(o[0], pa0, pa1, pa2, pa3, vb2, vb3);
                    mma_bf16(o[1], pa0, pa1, pa2, pa3, va2, va3);
                    mma_bf16(o[1], pl0, pl1, pl2, pl3, va2, va3);
                    mma_bf16(o[1], pa0, pa1, pa2, pa3, vc0, vc1);
                    mma_bf16(o[2], pa0, pa1, pa2, pa3, vb0, vb1);
                    mma_bf16(o[2], pl0, pl1, pl2, pl3, vb0, vb1);
                    mma_bf16(o[2], pa0, pa1, pa2, pa3, vc2, vc3);
                }
            }
        }

        float a0 = rs0, a1 = rs1;
        a0 += __shfl_xor_sync(0xFFFFFFFFu, a0, 1);
        a0 += __shfl_xor_sync(0xFFFFFFFFu, a0, 2);
        a1 += __shfl_xor_sync(0xFFFFFFFFu, a1, 1);
        a1 += __shfl_xor_sync(0xFFFFFFFFu, a1, 2);
        float inv0 = 1.f / a0, inv1 = 1.f / a1;
        #pragma unroll
        for (int nd = 0; nd < 3; nd++) {
            int d = nd * 8 + d0;
            outp[(h * HDIM + d)     * HWPIX + pix0] = o[nd][0] * inv0;
            outp[(h * HDIM + d + 1) * HWPIX + pix0] = o[nd][1] * inv0;
            outp[(h * HDIM + d)     * HWPIX + pix1] = o[nd][2] * inv1;
            outp[(h * HDIM + d + 1) * HWPIX + pix1] = o[nd][3] * inv1;
        }
    }
}

// ---------------- fused dual LePE -> 0.5*(h+v) -> bf16 hi/lo planes ----------------
__global__ __launch_bounds__(256) void lepe_fused(
    const float* __restrict__ attH, const float* __restrict__ attV,
    const float* __restrict__ wH, const float* __restrict__ bH,
    const float* __restrict__ wV, const float* __restrict__ bV,
    ushort_t* __restrict__ phi, ushort_t* __restrict__ plo)
{
    int t = blockIdx.x * blockDim.x + threadIdx.x;
    if (t >= Cdim * (HWPIX / 4)) return;
    int c = t / (HWPIX / 4);
    int r = t % (HWPIX / 4);
    int y = r / 28, x4 = (r % 28) * 4;
    const float* baseH = attH + c * HWPIX;
    const float* baseV = attV + c * HWPIX;

    float wvh[9], wvv[9];
    #pragma unroll
    for (int i = 0; i < 9; i++) { wvh[i] = wH[c * 9 + i]; wvv[i] = wV[c * 9 + i]; }
    float ah0 = bH[c], ah1 = ah0, ah2 = ah0, ah3 = ah0;
    float av0 = bV[c], av1 = av0, av2 = av0, av3 = av0;

    #pragma unroll
    for (int ky = 0; ky < 3; ky++) {
        int yy = y + ky - 1;
        if (yy < 0 || yy >= 112) continue;
        const float* rpH = baseH + yy * 112 + x4;
        const float* rpV = baseV + yy * 112 + x4;
        float4 mH = *(const float4*)rpH;
        float4 mV = *(const float4*)rpV;
        float lfH = (x4 > 0)   ? rpH[-1] : 0.f;
        float rtH = (x4 < 108) ? rpH[4]  : 0.f;
        float lfV = (x4 > 0)   ? rpV[-1] : 0.f;
        float rtV = (x4 < 108) ? rpV[4]  : 0.f;
        float h0 = wvh[ky*3], h1 = wvh[ky*3+1], h2 = wvh[ky*3+2];
        float v0 = wvv[ky*3], v1 = wvv[ky*3+1], v2 = wvv[ky*3+2];
        ah0 += h0 * lfH  + h1 * mH.x + h2 * mH.y;
        ah1 += h0 * mH.x + h1 * mH.y + h2 * mH.z;
        ah2 += h0 * mH.y + h1 * mH.z + h2 * mH.w;
        ah3 += h0 * mH.z + h1 * mH.w + h2 * rtH;
        av0 += v0 * lfV  + v1 * mV.x + v2 * mV.y;
        av1 += v0 * mV.x + v1 * mV.y + v2 * mV.z;
        av2 += v0 * mV.y + v1 * mV.z + v2 * mV.w;
        av3 += v0 * mV.z + v1 * mV.w + v2 * rtV;
    }

    float4 inH = *(const float4*)(baseH + y * 112 + x4);
    float4 inV = *(const float4*)(baseV + y * 112 + x4);
    const float RS2 = 0.70710678118654752f;
    float oh0 = inH.x + 0.5f * ah0 * (1.f + erff(ah0 * RS2));
    float oh1 = inH.y + 0.5f * ah1 * (1.f + erff(ah1 * RS2));
    float oh2 = inH.z + 0.5f * ah2 * (1.f + erff(ah2 * RS2));
    float oh3 = inH.w + 0.5f * ah3 * (1.f + erff(ah3 * RS2));
    float ov0 = inV.x + 0.5f * av0 * (1.f + erff(av0 * RS2));
    float ov1 = inV.y + 0.5f * av1 * (1.f + erff(av1 * RS2));
    float ov2 = inV.z + 0.5f * av2 * (1.f + erff(av2 * RS2));
    float ov3 = inV.w + 0.5f * av3 * (1.f + erff(av3 * RS2));

    float p0 = 0.5f * (oh0 + ov0);
    float p1 = 0.5f * (oh1 + ov1);
    float p2 = 0.5f * (oh2 + ov2);
    float p3 = 0.5f * (oh3 + ov3);

    uint32_t h0w = bfp(p0, p1), h1w = bfp(p2, p3);
    uint32_t l0w = bfp(p0 - bflo(h0w), p1 - bfhi(h0w));
    uint32_t l1w = bfp(p2 - bflo(h1w), p3 - bfhi(h1w));
    int idx = c * HWPIX + y * 112 + x4;
    *(uint2*)&phi[idx] = make_uint2(h0w, h1w);
    *(uint2*)&plo[idx] = make_uint2(l0w, l1w);
}

// ---------------- launch ----------------
extern "C" void kernel_launch(void* const* d_in, const int* in_sizes, int n_in,
                              void* d_out, int out_size)
{
    const float* x        = (const float*)d_in[0];
    const float* qkv_h_w  = (const float*)d_in[1];
    const float* qkv_h_b  = (const float*)d_in[2];
    const float* qkv_v_w  = (const float*)d_in[3];
    const float* qkv_v_b  = (const float*)d_in[4];
    const float* proj_w   = (const float*)d_in[5];
    const float* proj_b   = (const float*)d_in[6];
    const float* lepe_h_w = (const float*)d_in[7];
    const float* lepe_h_b = (const float*)d_in[8];
    const float* lepe_v_w = (const float*)d_in[9];
    const float* lepe_v_b = (const float*)d_in[10];
    const float* tab_h    = (const float*)d_in[11];
    const float* tab_v    = (const float*)d_in[12];
    float* out = (float*)d_out;

    float *qh, *qv, *ah, *av;
    ushort_t *xhi, *xlo, *phi, *plo, *whh, *whl, *wvh, *wvl, *pwh, *pwl;
    cudaGetSymbolAddress((void**)&qh, g_qkv_h);
    cudaGetSymbolAddress((void**)&qv, g_qkv_v);
    cudaGetSymbolAddress((void**)&ah, g_att_h);
    cudaGetSymbolAddress((void**)&av, g_att_v);
    cudaGetSymbolAddress((void**)&xhi, g_xhi);
    cudaGetSymbolAddress((void**)&xlo, g_xlo);
    cudaGetSymbolAddress((void**)&phi, g_phi);
    cudaGetSymbolAddress((void**)&plo, g_plo);
    cudaGetSymbolAddress((void**)&whh, g_whh);
    cudaGetSymbolAddress((void**)&whl, g_whl);
    cudaGetSymbolAddress((void**)&wvh, g_wvh);
    cudaGetSymbolAddress((void**)&wvl, g_wvl);
    cudaGetSymbolAddress((void**)&pwh, g_pwh);
    cudaGetSymbolAddress((void**)&pwl, g_pwl);

    int nx4 = GK * NPIX / 4;
    split_kernel<<<(nx4 + 255) / 256, 256>>>((const float4*)x, (uint2*)xhi, (uint2*)xlo, nx4);
    int nw4 = M_QKV * GK / 4;
    int np4 = M_PROJ * GK / 4;
    int ntotw = nw4 * 2 + np4;
    split_weights<<<(ntotw + 255) / 256, 256>>>(
        (const float4*)qkv_h_w, (uint2*)whh, (uint2*)whl, nw4,
        (const float4*)qkv_v_w, (uint2*)wvh, (uint2*)wvl, nw4,
        (const float4*)proj_w,  (uint2*)pwh, (uint2*)pwl, np4);

    cudaFuncSetAttribute(gemm_mma,
                         cudaFuncAttributeMaxDynamicSharedMemorySize, G_TOTAL_BYTES);
    dim3 gq(NPIX / 128, M_QKV / 64);
    gemm_mma<<<gq, 256, G_TOTAL_BYTES>>>(whh, whl, xhi, xlo, qkv_h_b, qh);
    gemm_mma<<<gq, 256, G_TOTAL_BYTES>>>(wvh, wvl, xhi, xlo, qkv_v_b, qv);

    cudaFuncSetAttribute(attn_mma,
                         cudaFuncAttributeMaxDynamicSharedMemorySize, A_TOTAL);
    dim3 ga(16, NHEAD, 2);
    attn_mma<<<ga, NTHR, A_TOTAL>>>(tab_h, tab_v);

    int nthr = Cdim * (HWPIX / 4);
    lepe_fused<<<(nthr + 255) / 256, 256>>>(ah, av, lepe_h_w, lepe_h_b,
                                            lepe_v_w, lepe_v_b, phi, plo);

    dim3 gp(NPIX / 128, M_PROJ / 64);
    gemm_mma<<<gp, 256, G_TOTAL_BYTES>>>(pwh, pwl, phi, plo, proj_b, out);
}

// round 11
// speedup vs baseline: 1.2861x; 1.1457x over previous
#include <cuda_runtime.h>
#include <cuda_bf16.h>
#include <cuda_fp16.h>
#include <cstdint>
#include <math.h>

#define Cdim   192
#define NHEAD  8
#define HDIM   24
#define HWPIX  12544          // 112*112
#define LTOK   784            // 7*112
#define GK     192            // gemm K
#define NPIX   12544
#define M_QKV  576
#define M_PROJ 192
#define SCALE_F 0.20412414523193154f  // 24^-0.5
#define LOG2E   1.44269504088896340736f

typedef unsigned short ushort_t;

// ---------------- scratch (device globals; no allocation) ----------------
__device__ float g_qkv_h[M_QKV * HWPIX];
__device__ float g_qkv_v[M_QKV * HWPIX];
__device__ float g_att_h[Cdim * HWPIX];
__device__ float g_att_v[Cdim * HWPIX];
__device__ ushort_t g_xhi[GK * NPIX];
__device__ ushort_t g_xlo[GK * NPIX];
__device__ ushort_t g_phi[GK * NPIX];
__device__ ushort_t g_plo[GK * NPIX];
__device__ ushort_t g_whh[M_QKV * GK];
__device__ ushort_t g_whl[M_QKV * GK];
__device__ ushort_t g_wvh[M_QKV * GK];
__device__ ushort_t g_wvl[M_QKV * GK];
__device__ ushort_t g_pwh[M_PROJ * GK];
__device__ ushort_t g_pwl[M_PROJ * GK];

// ---------------- bf16 helpers (GEMM path) ----------------
__device__ __forceinline__ uint32_t bfp(float lo_el, float hi_el) {
    uint32_t r;
    asm("cvt.rn.bf16x2.f32 %0, %1, %2;" : "=r"(r) : "f"(hi_el), "f"(lo_el));
    return r;
}
__device__ __forceinline__ float bflo(uint32_t p) { return __uint_as_float(p << 16); }
__device__ __forceinline__ float bfhi(uint32_t p) { return __uint_as_float(p & 0xFFFF0000u); }

__device__ __forceinline__ uint32_t s2u(const void* p) {
    uint32_t a;
    asm("{ .reg .u64 t; cvta.to.shared.u64 t, %1; cvt.u32.u64 %0, t; }" : "=r"(a) : "l"(p));
    return a;
}
__device__ __forceinline__ float ex2f(float x) {
    float r;
    asm("ex2.approx.f32 %0, %1;" : "=f"(r) : "f"(x));
    return r;
}
// pack two f32 -> f16x2 (first arg in low half)
__device__ __forceinline__ uint32_t hfp(float lo_el, float hi_el) {
    uint32_t r;
    asm("cvt.rn.f16x2.f32 %0, %1, %2;" : "=r"(r) : "f"(hi_el), "f"(lo_el));
    return r;
}

__device__ __forceinline__ void mma_bf16(float* c,
    uint32_t a0, uint32_t a1, uint32_t a2, uint32_t a3,
    uint32_t b0, uint32_t b1)
{
    asm volatile("mma.sync.aligned.m16n8k16.row.col.f32.bf16.bf16.f32 "
        "{%0,%1,%2,%3}, {%4,%5,%6,%7}, {%8,%9}, {%0,%1,%2,%3};"
        : "+f"(c[0]), "+f"(c[1]), "+f"(c[2]), "+f"(c[3])
        : "r"(a0), "r"(a1), "r"(a2), "r"(a3), "r"(b0), "r"(b1));
}
__device__ __forceinline__ void mma_f16(float* c,
    uint32_t a0, uint32_t a1, uint32_t a2, uint32_t a3,
    uint32_t b0, uint32_t b1)
{
    asm volatile("mma.sync.aligned.m16n8k16.row.col.f32.f16.f16.f32 "
        "{%0,%1,%2,%3}, {%4,%5,%6,%7}, {%8,%9}, {%0,%1,%2,%3};"
        : "+f"(c[0]), "+f"(c[1]), "+f"(c[2]), "+f"(c[3])
        : "r"(a0), "r"(a1), "r"(a2), "r"(a3), "r"(b0), "r"(b1));
}
__device__ __forceinline__ void mma_f16_k8(float* c,
    uint32_t a0, uint32_t a1, uint32_t b0)
{
    asm volatile("mma.sync.aligned.m16n8k8.row.col.f32.f16.f16.f32 "
        "{%0,%1,%2,%3}, {%4,%5}, {%6}, {%0,%1,%2,%3};"
        : "+f"(c[0]), "+f"(c[1]), "+f"(c[2]), "+f"(c[3])
        : "r"(a0), "r"(a1), "r"(b0));
}

__device__ __forceinline__ void ldsm4t(uint32_t& r0, uint32_t& r1,
                                       uint32_t& r2, uint32_t& r3, uint32_t a)
{
    asm volatile("ldmatrix.sync.aligned.m8n8.x4.trans.shared.b16 {%0,%1,%2,%3}, [%4];"
        : "=r"(r0), "=r"(r1), "=r"(r2), "=r"(r3) : "r"(a));
}
__device__ __forceinline__ void ldsm4(uint32_t& r0, uint32_t& r1,
                                      uint32_t& r2, uint32_t& r3, uint32_t a)
{
    asm volatile("ldmatrix.sync.aligned.m8n8.x4.shared.b16 {%0,%1,%2,%3}, [%4];"
        : "=r"(r0), "=r"(r1), "=r"(r2), "=r"(r3) : "r"(a));
}
__device__ __forceinline__ void ldsm2(uint32_t& r0, uint32_t& r1, uint32_t a)
{
    asm volatile("ldmatrix.sync.aligned.m8n8.x2.shared.b16 {%0,%1}, [%2];"
        : "=r"(r0), "=r"(r1) : "r"(a));
}

#define CPA16(dst, src) asm volatile("cp.async.ca.shared.global [%0], [%1], 16;" :: "r"(dst), "l"(src) : "memory")
#define CPC()  asm volatile("cp.async.commit_group;" ::: "memory")
#define CPW1() asm volatile("cp.async.wait_group 1;" ::: "memory")
#define CPW0() asm volatile("cp.async.wait_group 0;" ::: "memory")

// ---------------- combined split: x + 3 weights, one launch ----------------
__global__ __launch_bounds__(256) void split_all(
    const float4* __restrict__ sx, uint2* __restrict__ xh, uint2* __restrict__ xl, int n0,
    const float4* __restrict__ w1, uint2* __restrict__ h1p, uint2* __restrict__ l1p, int n1,
    const float4* __restrict__ w2, uint2* __restrict__ h2p, uint2* __restrict__ l2p, int n2,
    const float4* __restrict__ w3, uint2* __restrict__ h3p, uint2* __restrict__ l3p, int n3)
{
    int i = blockIdx.x * blockDim.x + threadIdx.x;
    const float4* src; uint2 *hd, *ld; int j = i;
    if (j < n0) { src = sx; hd = xh; ld = xl; }
    else if ((j -= n0) < n1) { src = w1; hd = h1p; ld = l1p; }
    else if ((j -= n1) < n2) { src = w2; hd = h2p; ld = l2p; }
    else if ((j -= n2) < n3) { src = w3; hd = h3p; ld = l3p; }
    else return;
    float4 v = src[j];
    uint32_t h0 = bfp(v.x, v.y);
    uint32_t h1 = bfp(v.z, v.w);
    uint32_t l0 = bfp(v.x - bflo(h0), v.y - bfhi(h0));
    uint32_t l1 = bfp(v.z - bflo(h1), v.w - bfhi(h1));
    hd[j] = make_uint2(h0, h1);
    ld[j] = make_uint2(l0, l1);
}

// ---------------- hi/lo bf16 mma GEMM, z-select A/bias/C ----------------
#define G_SBH 0
#define G_SBL 8704
#define G_SAH 17408
#define G_SAL 22528
#define G_BSTR 136
#define G_BBUF 4352
#define G_ASTR 40
#define G_ABUF 2560
#define G_TOTAL_BYTES 55296

__global__ __launch_bounds__(256) void gemm_mma(
    const ushort_t* __restrict__ Ah0, const ushort_t* __restrict__ Al0,
    const ushort_t* __restrict__ Ah1, const ushort_t* __restrict__ Al1,
    const ushort_t* __restrict__ Bhi, const ushort_t* __restrict__ Blo,
    const float* __restrict__ bias0, const float* __restrict__ bias1,
    float* __restrict__ C0, float* __restrict__ C1)
{
    extern __shared__ ushort_t gsm[];
    const ushort_t* __restrict__ Ahi = blockIdx.z ? Ah1 : Ah0;
    const ushort_t* __restrict__ Alo = blockIdx.z ? Al1 : Al0;
    const float* __restrict__ bias = blockIdx.z ? bias1 : bias0;
    float* __restrict__ C = blockIdx.z ? C1 : C0;

    const int tid = threadIdx.x;
    const int bn = blockIdx.x * 128, bm = blockIdx.y * 64;
    const int wid = tid >> 5, lane = tid & 31;
    const int wm = wid & 3, wn = wid >> 2;
    const int g = lane >> 2, q = lane & 3;
    const int wc = wn * 64;
    const int row0 = bm + wm * 16 + g;
    const int row1 = row0 + 8;

    float acc[8][4];
    #pragma unroll
    for (int i = 0; i < 8; i++)
        #pragma unroll
        for (int j = 0; j < 4; j++) acc[i][j] = 0.f;

    const int rB = tid >> 3;
    const int cB = (tid & 7) * 8;
    const int rA = tid >> 2;
    const int cA = (tid & 3) * 8;

    uint32_t smb = s2u(gsm);
    uint32_t dstBh[2], dstBl[2], dstAh[2], dstAl[2];
    #pragma unroll
    for (int b = 0; b < 2; b++) {
        dstBh[b] = smb + (uint32_t)((G_SBH + b * G_BBUF + rB * G_BSTR + cB) * 2);
        dstBl[b] = smb + (uint32_t)((G_SBL + b * G_BBUF + rB * G_BSTR + cB) * 2);
        dstAh[b] = smb + (uint32_t)((G_SAH + b * G_ABUF + rA * G_ASTR + cA) * 2);
        dstAl[b] = smb + (uint32_t)((G_SAL + b * G_ABUF + rA * G_ASTR + cA) * 2);
    }

    const int lm = lane >> 3, lr = lane & 7;
    const int lkrow = (lm & 1) * 8 + lr;
    const int lncol = wc + (lm >> 1) * 8;
    uint32_t sbh_base[2], sbl_base[2];
    const int arow = wm * 16 + (lm & 1) * 8 + lr;
    const int acol = (lane >> 4) * 8;
    uint32_t sah_base[2], sal_base[2];
    #pragma unroll
    for (int b = 0; b < 2; b++) {
        sbh_base[b] = smb + (uint32_t)((G_SBH + b * G_BBUF + lkrow * G_BSTR + lncol) * 2);
        sbl_base[b] = smb + (uint32_t)((G_SBL + b * G_BBUF + lkrow * G_BSTR + lncol) * 2);
        sah_base[b] = smb + (uint32_t)((G_SAH + b * G_ABUF + arow * G_ASTR + acol) * 2);
        sal_base[b] = smb + (uint32_t)((G_SAL + b * G_ABUF + arow * G_ASTR + acol) * 2);
    }

    {
        const ushort_t* bh = &Bhi[rB * NPIX + bn + cB];
        const ushort_t* bl = &Blo[rB * NPIX + bn + cB];
        CPA16(dstBh[0], bh); CPA16(dstBh[0] + 128, bh + 64);
        CPA16(dstBl[0], bl); CPA16(dstBl[0] + 128, bl + 64);
        CPA16(dstAh[0], &Ahi[(bm + rA) * GK + cA]);
        CPA16(dstAl[0], &Alo[(bm + rA) * GK + cA]);
        CPC();
    }

    #pragma unroll
    for (int ki = 0; ki < 6; ki++) {
        if (ki < 5) {
            const int kn = (ki + 1) * 32;
            const int bf = (ki + 1) & 1;
            const ushort_t* bh = &Bhi[(kn + rB) * NPIX + bn + cB];
            const ushort_t* bl = &Blo[(kn + rB) * NPIX + bn + cB];
            CPA16(dstBh[bf], bh); CPA16(dstBh[bf] + 128, bh + 64);
            CPA16(dstBl[bf], bl); CPA16(dstBl[bf] + 128, bl + 64);
            CPA16(dstAh[bf], &Ahi[(bm + rA) * GK + kn + cA]);
            CPA16(dstAl[bf], &Alo[(bm + rA) * GK + kn + cA]);
            CPC();
            CPW1();
        } else {
            CPW0();
        }
        __syncthreads();

        const int buf = ki & 1;
        #pragma unroll
        for (int hh = 0; hh < 2; hh++) {
            uint32_t ah[4], al[4];
            ldsm4(ah[0], ah[1], ah[2], ah[3], sah_base[buf] + hh * 32);
            ldsm4(al[0], al[1], al[2], al[3], sal_base[buf] + hh * 32);

            const uint32_t hoff = (uint32_t)(hh * 16 * G_BSTR) * 2;
            #pragma unroll
            for (int j = 0; j < 4; j++) {
                uint32_t off = hoff + (uint32_t)(j * 16) * 2;
                uint32_t bh0, bh1, bh2, bh3, bl0, bl1, bl2, bl3;
                ldsm4t(bh0, bh1, bh2, bh3, sbh_base[buf] + off);
                ldsm4t(bl0, bl1, bl2, bl3, sbl_base[buf] + off);
                float* c0 = acc[2 * j];
                float* c1 = acc[2 * j + 1];
                mma_bf16(c0, ah[0], ah[1], ah[2], ah[3], bh0, bh1);
                mma_bf16(c0, al[0], al[1], al[2], al[3], bh0, bh1);
                mma_bf16(c0, ah[0], ah[1], ah[2], ah[3], bl0, bl1);
                mma_bf16(c1, ah[0], ah[1], ah[2], ah[3], bh2, bh3);
                mma_bf16(c1, al[0], al[1], al[2], al[3], bh2, bh3);
                mma_bf16(c1, ah[0], ah[1], ah[2], ah[3], bl2, bl3);
            }
        }
        __syncthreads();
    }

    const float b0 = bias[row0], b1 = bias[row1];
    #pragma unroll
    for (int nf = 0; nf < 8; nf++) {
        int col = bn + wc + nf * 8 + 2 * q;
        *(float2*)&C[row0 * NPIX + col] = make_float2(acc[nf][0] + b0, acc[nf][1] + b0);
        *(float2*)&C[row1 * NPIX + col] = make_float2(acc[nf][2] + b1, acc[nf][3] + b1);
    }
}

// ============================================================================
// fp16 flash attention — full K/V resident, S 3-term fp16, PV 2-term (no Vlo)
// ============================================================================
#define KSTR 40
#define VSTRF 792
#define NW    16
#define NTHR  512

#define A_SKH 0
#define A_SKL (A_SKH + LTOK * KSTR * 2)          // 62720
#define A_SVH (A_SKL + LTOK * KSTR * 2)          // 125440
#define A_SB  (A_SVH + HDIM * VSTRF * 2)         // 163456
#define A_TOTAL (A_SB + 256)

__global__ __launch_bounds__(NTHR, 1) void attn_mma(
    const float* __restrict__ tab_h, const float* __restrict__ tab_v)
{
    extern __shared__ char asm_[];
    ushort_t* sKhi = (ushort_t*)(asm_ + A_SKH);
    ushort_t* sKlo = (ushort_t*)(asm_ + A_SKL);
    ushort_t* sVhi = (ushort_t*)(asm_ + A_SVH);
    float* sb = (float*)(asm_ + A_SB);

    const int tid = threadIdx.x;
    const int w = blockIdx.x, h = blockIdx.y, br = blockIdx.z;
    const float* __restrict__ qkv = br ? g_qkv_v : g_qkv_h;
    float* __restrict__ outp = br ? g_att_v : g_att_h;
    const float* __restrict__ tab = br ? tab_v : tab_h;

    if (tid < 49) {
        int r1 = tid / 7, r2 = tid % 7, off = r1 - r2 + 6;
        float bv = br ? tab[(6 * 13 + off) * NHEAD + h]
                      : tab[(off * 13 + 6) * NHEAD + h];
        sb[tid] = bv * LOG2E;
    }
    for (int i = tid; i < LTOK * 8; i += NTHR) {
        int k = i >> 3, d = 24 + (i & 7);
        sKhi[k * KSTR + d] = 0; sKlo[k * KSTR + d] = 0;
    }
    if (tid < HDIM * 8) {
        int d = tid >> 3, k = LTOK + (tid & 7);
        sVhi[d * VSTRF + k] = 0;
    }
    for (int idx = tid; idx < LTOK * HDIM; idx += NTHR) {
        int d = idx / LTOK, k = idx - d * LTOK;
        int pix = br ? ((k / 7) * 112 + w * 7 + (k % 7)) : (w * LTOK + k);
        float kv = qkv[(192 + h * HDIM + d) * HWPIX + pix];
        float vv = qkv[(384 + h * HDIM + d) * HWPIX + pix];
        __half kh = __float2half_rn(kv);
        sKhi[k * KSTR + d] = __half_as_ushort(kh);
        sKlo[k * KSTR + d] = __half_as_ushort(__float2half_rn(kv - __half2float(kh)));
        sVhi[d * VSTRF + k] = __half_as_ushort(__float2half_rn(vv));
    }
    __syncthreads();

    const int warp = tid >> 5, lane = tid & 31;
    const int g = lane >> 2, q = lane & 3;
    const int d0 = 2 * q;
    const int lr = lane & 7;

    const uint32_t kln = (uint32_t)((lr * KSTR + (lane >> 3) * 8) * 2);
    const uint32_t skh_b = s2u(sKhi) + kln;
    const uint32_t skl_b = s2u(sKlo) + kln;
    // V hi: x4 = {nd0 k0-7, nd0 k8-15, nd1 k0-7, nd1 k8-15}, x2 = {nd2 k0-7, nd2 k8-15}
    const int vko = ((lane >> 3) & 1) * 8;
    const int vdh = ((lane >> 4) & 1) * 8 + lr;
    const uint32_t sv4 = s2u(sVhi) + (uint32_t)((vdh * VSTRF + vko) * 2);
    const uint32_t sv2a = s2u(sVhi) + (uint32_t)(((16 + lr) * VSTRF + vko) * 2);

    const float qscale = SCALE_F * LOG2E;

    for (int mt = warp; mt < 49; mt += NW) {
        const int r0 = mt * 16 + g, r1 = r0 + 8;
        const int pix0 = br ? ((r0 / 7) * 112 + w * 7 + (r0 % 7)) : (w * LTOK + r0);
        const int pix1 = br ? ((r1 / 7) * 112 + w * 7 + (r1 % 7)) : (w * LTOK + r1);
        const int bro0 = (br ? (r0 % 7) : (r0 / 112)) * 7;
        const int bro1 = (br ? (r1 % 7) : (r1 / 112)) * 7;

        uint32_t qh[6], ql[6];
        #pragma unroll
        for (int p = 0; p < 3; p++) {
            int d = d0 + 8 * p;
            float a0v = qkv[(h * HDIM + d)     * HWPIX + pix0] * qscale;
            float a1v = qkv[(h * HDIM + d + 1) * HWPIX + pix0] * qscale;
            float b0v = qkv[(h * HDIM + d)     * HWPIX + pix1] * qscale;
            float b1v = qkv[(h * HDIM + d + 1) * HWPIX + pix1] * qscale;
            __half ha0 = __float2half_rn(a0v), ha1 = __float2half_rn(a1v);
            __half hb0 = __float2half_rn(b0v), hb1 = __float2half_rn(b1v);
            qh[2 * p]     = (uint32_t)__half_as_ushort(ha0) | ((uint32_t)__half_as_ushort(ha1) << 16);
            qh[2 * p + 1] = (uint32_t)__half_as_ushort(hb0) | ((uint32_t)__half_as_ushort(hb1) << 16);
            ql[2 * p]     = hfp(a0v - __half2float(ha0), a1v - __half2float(ha1));
            ql[2 * p + 1] = hfp(b0v - __half2float(hb0), b1v - __half2float(hb1));
        }

        float o[3][4];
        #pragma unroll
        for (int nd = 0; nd < 3; nd++)
            #pragma unroll
            for (int i = 0; i < 4; i++) o[nd][i] = 0.f;
        float rs0 = 0.f, rs1 = 0.f;

        for (int kt = 0; kt < 14; kt++) {
            float bh0 = 0.f, bh1 = 0.f;
            if (!br) { bh0 = sb[bro0 + (kt >> 1)]; bh1 = sb[bro1 + (kt >> 1)]; }
            const int kbase = kt * 56;

            #pragma unroll
            for (int ks = 0; ks < 4; ks++) {
                const int nt0 = 2 * ks, nt1 = nt0 + 1;
                const bool has1 = (nt1 < 7);
                float sA[4] = {0.f, 0.f, 0.f, 0.f};
                float sB[4] = {0.f, 0.f, 0.f, 0.f};

                {
                    uint32_t ko = (uint32_t)((kbase + nt0 * 8) * KSTR * 2);
                    uint32_t h0, h1, h2, h3, l0, l1, l2, l3;
                    ldsm4(h0, h1, h2, h3, skh_b + ko);
                    ldsm4(l0, l1, l2, l3, skl_b + ko);
                    mma_f16(sA, qh[0], qh[1], qh[2], qh[3], h0, h1);
                    mma_f16(sA, ql[0], ql[1], ql[2], ql[3], h0, h1);
                    mma_f16(sA, qh[0], qh[1], qh[2], qh[3], l0, l1);
                    mma_f16_k8(sA, qh[4], qh[5], h2);
                    mma_f16_k8(sA, ql[4], ql[5], h2);
                    mma_f16_k8(sA, qh[4], qh[5], l2);
                }
                if (has1) {
                    uint32_t ko = (uint32_t)((kbase + nt1 * 8) * KSTR * 2);
                    uint32_t h0, h1, h2, h3, l0, l1, l2, l3;
                    ldsm4(h0, h1, h2, h3, skh_b + ko);
                    ldsm4(l0, l1, l2, l3, skl_b + ko);
                    mma_f16(sB, qh[0], qh[1], qh[2], qh[3], h0, h1);
                    mma_f16(sB, ql[0], ql[1], ql[2], ql[3], h0, h1);
                    mma_f16(sB, qh[0], qh[1], qh[2], qh[3], l0, l1);
                    mma_f16_k8(sB, qh[4], qh[5], h2);
                    mma_f16_k8(sB, ql[4], ql[5], h2);
                    mma_f16_k8(sB, qh[4], qh[5], l2);
                }

                float eA0, eA1, eA2, eA3, eB0 = 0.f, eB1 = 0.f, eB2 = 0.f, eB3 = 0.f;
                if (!br) {
                    eA0 = ex2f(sA[0] + bh0); eA1 = ex2f(sA[1] + bh0);
                    eA2 = ex2f(sA[2] + bh1); eA3 = ex2f(sA[3] + bh1);
                    if (has1) {
                        eB0 = ex2f(sB[0] + bh0); eB1 = ex2f(sB[1] + bh0);
                        eB2 = ex2f(sB[2] + bh1); eB3 = ex2f(sB[3] + bh1);
                    }
                } else {
                    int i0 = (nt0 + d0) % 7;
                    int i1 = i0 + 1; if (i1 == 7) i1 = 0;
                    int j1 = i1 + 1; if (j1 == 7) j1 = 0;
                    eA0 = ex2f(sA[0] + sb[bro0 + i0]); eA1 = ex2f(sA[1] + sb[bro0 + i1]);
                    eA2 = ex2f(sA[2] + sb[bro1 + i0]); eA3 = ex2f(sA[3] + sb[bro1 + i1]);
                    if (has1) {
                        eB0 = ex2f(sB[0] + sb[bro0 + i1]); eB1 = ex2f(sB[1] + sb[bro0 + j1]);
                        eB2 = ex2f(sB[2] + sb[bro1 + i1]); eB3 = ex2f(sB[3] + sb[bro1 + j1]);
                    }
                }
                rs0 += eA0 + eA1 + eB0 + eB1;
                rs1 += eA2 + eA3 + eB2 + eB3;

                // P fragments fp16 hi + lo
                uint32_t pa0 = hfp(eA0, eA1), pa1 = hfp(eA2, eA3);
                uint32_t pa2 = has1 ? hfp(eB0, eB1) : 0u;
                uint32_t pa3 = has1 ? hfp(eB2, eB3) : 0u;
                uint32_t pl0 = hfp(eA0 - __half2float(__ushort_as_half((ushort_t)pa0)),
                                   eA1 - __half2float(__ushort_as_half((ushort_t)(pa0 >> 16))));
                uint32_t pl1 = hfp(eA2 - __half2float(__ushort_as_half((ushort_t)pa1)),
                                   eA3 - __half2float(__ushort_as_half((ushort_t)(pa1 >> 16))));
                uint32_t pl2 = has1 ? hfp(eB0 - __half2float(__ushort_as_half((ushort_t)pa2)),
                                          eB1 - __half2float(__ushort_as_half((ushort_t)(pa2 >> 16)))) : 0u;
                uint32_t pl3 = has1 ? hfp(eB2 - __half2float(__ushort_as_half((ushort_t)pa3)),
                                          eB3 - __half2float(__ushort_as_half((ushort_t)(pa3 >> 16)))) : 0u;

                {
                    uint32_t vo = (uint32_t)((kbase + ks * 16) * 2);
                    uint32_t va0, va1, va2, va3, vx0, vx1;
                    ldsm4(va0, va1, va2, va3, sv4 + vo);   // nd0 (va0,va1) | nd1 (va2,va3)
                    ldsm2(vx0, vx1, sv2a + vo);            // nd2
                    mma_f16(o[0], pa0, pa1, pa2, pa3, va0, va1);
                    mma_f16(o[0], pl0, pl1, pl2, pl3, va0, va1);
                    mma_f16(o[1], pa0, pa1, pa2, pa3, va2, va3);
                    mma_f16(o[1], pl0, pl1, pl2, pl3, va2, va3);
                    mma_f16(o[2], pa0, pa1, pa2, pa3, vx0, vx1);
                    mma_f16(o[2], pl0, pl1, pl2, pl3, vx0, vx1);
                }
            }
        }

        float a0 = rs0, a1 = rs1;
        a0 += __shfl_xor_sync(0xFFFFFFFFu, a0, 1);
        a0 += __shfl_xor_sync(0xFFFFFFFFu, a0, 2);
        a1 += __shfl_xor_sync(0xFFFFFFFFu, a1, 1);
        a1 += __shfl_xor_sync(0xFFFFFFFFu, a1, 2);
        float inv0 = 1.f / a0, inv1 = 1.f / a1;
        #pragma unroll
        for (int nd = 0; nd < 3; nd++) {
            int d = nd * 8 + d0;
            outp[(h * HDIM + d)     * HWPIX + pix0] = o[nd][0] * inv0;
            outp[(h * HDIM + d + 1) * HWPIX + pix0] = o[nd][1] * inv0;
            outp[(h * HDIM + d)     * HWPIX + pix1] = o[nd][2] * inv1;
            outp[(h * HDIM + d + 1) * HWPIX + pix1] = o[nd][3] * inv1;
        }
    }
}

// ---------------- fused dual LePE -> 0.5*(h+v) -> bf16 hi/lo planes ----------------
__global__ __launch_bounds__(256) void lepe_fused(
    const float* __restrict__ attH, const float* __restrict__ attV,
    const float* __restrict__ wH, const float* __restrict__ bH,
    const float* __restrict__ wV, const float* __restrict__ bV,
    ushort_t* __restrict__ phi, ushort_t* __restrict__ plo)
{
    int t = blockIdx.x * blockDim.x + threadIdx.x;
    if (t >= Cdim * (HWPIX / 4)) return;
    int c = t / (HWPIX / 4);
    int r = t % (HWPIX / 4);
    int y = r / 28, x4 = (r % 28) * 4;
    const float* baseH = attH + c * HWPIX;
    const float* baseV = attV + c * HWPIX;

    float wvh[9], wvv[9];
    #pragma unroll
    for (int i = 0; i < 9; i++) { wvh[i] = wH[c * 9 + i]; wvv[i] = wV[c * 9 + i]; }
    float ah0 = bH[c], ah1 = ah0, ah2 = ah0, ah3 = ah0;
    float av0 = bV[c], av1 = av0, av2 = av0, av3 = av0;

    #pragma unroll
    for (int ky = 0; ky < 3; ky++) {
        int yy = y + ky - 1;
        if (yy < 0 || yy >= 112) continue;
        const float* rpH = baseH + yy * 112 + x4;
        const float* rpV = baseV + yy * 112 + x4;
        float4 mH = *(const float4*)rpH;
        float4 mV = *(const float4*)rpV;
        float lfH = (x4 > 0)   ? rpH[-1] : 0.f;
        float rtH = (x4 < 108) ? rpH[4]  : 0.f;
        float lfV = (x4 > 0)   ? rpV[-1] : 0.f;
        float rtV = (x4 < 108) ? rpV[4]  : 0.f;
        float h0 = wvh[ky*3], h1 = wvh[ky*3+1], h2 = wvh[ky*3+2];
        float v0 = wvv[ky*3], v1 = wvv[ky*3+1], v2 = wvv[ky*3+2];
        ah0 += h0 * lfH  + h1 * mH.x + h2 * mH.y;
        ah1 += h0 * mH.x + h1 * mH.y + h2 * mH.z;
        ah2 += h0 * mH.y + h1 * mH.z + h2 * mH.w;
        ah3 += h0 * mH.z + h1 * mH.w + h2 * rtH;
        av0 += v0 * lfV  + v1 * mV.x + v2 * mV.y;
        av1 += v0 * mV.x + v1 * mV.y + v2 * mV.z;
        av2 += v0 * mV.y + v1 * mV.z + v2 * mV.w;
        av3 += v0 * mV.z + v1 * mV.w + v2 * rtV;
    }

    float4 inH = *(const float4*)(baseH + y * 112 + x4);
    float4 inV = *(const float4*)(baseV + y * 112 + x4);
    const float RS2 = 0.70710678118654752f;
    float oh0 = inH.x + 0.5f * ah0 * (1.f + erff(ah0 * RS2));
    float oh1 = inH.y + 0.5f * ah1 * (1.f + erff(ah1 * RS2));
    float oh2 = inH.z + 0.5f * ah2 * (1.f + erff(ah2 * RS2));
    float oh3 = inH.w + 0.5f * ah3 * (1.f + erff(ah3 * RS2));
    float ov0 = inV.x + 0.5f * av0 * (1.f + erff(av0 * RS2));
    float ov1 = inV.y + 0.5f * av1 * (1.f + erff(av1 * RS2));
    float ov2 = inV.z + 0.5f * av2 * (1.f + erff(av2 * RS2));
    float ov3 = inV.w + 0.5f * av3 * (1.f + erff(av3 * RS2));

    float p0 = 0.5f * (oh0 + ov0);
    float p1 = 0.5f * (oh1 + ov1);
    float p2 = 0.5f * (oh2 + ov2);
    float p3 = 0.5f * (oh3 + ov3);

    uint32_t h0w = bfp(p0, p1), h1w = bfp(p2, p3);
    uint32_t l0w = bfp(p0 - bflo(h0w), p1 - bfhi(h0w));
    uint32_t l1w = bfp(p2 - bflo(h1w), p3 - bfhi(h1w));
    int idx = c * HWPIX + y * 112 + x4;
    *(uint2*)&phi[idx] = make_uint2(h0w, h1w);
    *(uint2*)&plo[idx] = make_uint2(l0w, l1w);
}

// ---------------- launch ----------------
extern "C" void kernel_launch(void* const* d_in, const int* in_sizes, int n_in,
                              void* d_out, int out_size)
{
    const float* x        = (const float*)d_in[0];
    const float* qkv_h_w  = (const float*)d_in[1];
    const float* qkv_h_b  = (const float*)d_in[2];
    const float* qkv_v_w  = (const float*)d_in[3];
    const float* qkv_v_b  = (const float*)d_in[4];
    const float* proj_w   = (const float*)d_in[5];
    const float* proj_b   = (const float*)d_in[6];
    const float* lepe_h_w = (const float*)d_in[7];
    const float* lepe_h_b = (const float*)d_in[8];
    const float* lepe_v_w = (const float*)d_in[9];
    const float* lepe_v_b = (const float*)d_in[10];
    const float* tab_h    = (const float*)d_in[11];
    const float* tab_v    = (const float*)d_in[12];
    float* out = (float*)d_out;

    float *qh, *qv, *ah, *av;
    ushort_t *xhi, *xlo, *phi, *plo, *whh, *whl, *wvh, *wvl, *pwh, *pwl;
    cudaGetSymbolAddress((void**)&qh, g_qkv_h);
    cudaGetSymbolAddress((void**)&qv, g_qkv_v);
    cudaGetSymbolAddress((void**)&ah, g_att_h);
    cudaGetSymbolAddress((void**)&av, g_att_v);
    cudaGetSymbolAddress((void**)&xhi, g_xhi);
    cudaGetSymbolAddress((void**)&xlo, g_xlo);
    cudaGetSymbolAddress((void**)&phi, g_phi);
    cudaGetSymbolAddress((void**)&plo, g_plo);
    cudaGetSymbolAddress((void**)&whh, g_whh);
    cudaGetSymbolAddress((void**)&whl, g_whl);
    cudaGetSymbolAddress((void**)&wvh, g_wvh);
    cudaGetSymbolAddress((void**)&wvl, g_wvl);
    cudaGetSymbolAddress((void**)&pwh, g_pwh);
    cudaGetSymbolAddress((void**)&pwl, g_pwl);

    // one combined split launch (x + 3 weight tensors)
    int nx4 = GK * NPIX / 4;
    int nw4 = M_QKV * GK / 4;
    int np4 = M_PROJ * GK / 4;
    int ntot = nx4 + nw4 * 2 + np4;
    split_all<<<(ntot + 255) / 256, 256>>>(
        (const float4*)x,       (uint2*)xhi, (uint2*)xlo, nx4,
        (const float4*)qkv_h_w, (uint2*)whh, (uint2*)whl, nw4,
        (const float4*)qkv_v_w, (uint2*)wvh, (uint2*)wvl, nw4,
        (const float4*)proj_w,  (uint2*)pwh, (uint2*)pwl, np4);

    // both QKV GEMMs in one launch (grid.z selects branch)
    cudaFuncSetAttribute(gemm_mma,
                         cudaFuncAttributeMaxDynamicSharedMemorySize, G_TOTAL_BYTES);
    dim3 gq(NPIX / 128, M_QKV / 64, 2);
    gemm_mma<<<gq, 256, G_TOTAL_BYTES>>>(whh, whl, wvh, wvl, xhi, xlo,
                                         qkv_h_b, qkv_v_b, qh, qv);

    cudaFuncSetAttribute(attn_mma,
                         cudaFuncAttributeMaxDynamicSharedMemorySize, A_TOTAL);
    dim3 ga(16, NHEAD, 2);
    attn_mma<<<ga, NTHR, A_TOTAL>>>(tab_h, tab_v);

    int nthr = Cdim * (HWPIX / 4);
    lepe_fused<<<(nthr + 255) / 256, 256>>>(ah, av, lepe_h_w, lepe_h_b,
                                            lepe_v_w, lepe_v_b, phi, plo);

    dim3 gp(NPIX / 128, M_PROJ / 64, 1);
    gemm_mma<<<gp, 256, G_TOTAL_BYTES>>>(pwh, pwl, pwh, pwl, phi, plo,
                                         proj_b, proj_b, out, out);
}

// round 12
// speedup vs baseline: 1.4461x; 1.1244x over previous
#include <cuda_runtime.h>
#include <cuda_bf16.h>
#include <cuda_fp16.h>
#include <cstdint>
#include <math.h>

#define Cdim   192
#define NHEAD  8
#define HDIM   24
#define HWPIX  12544          // 112*112
#define LTOK   784            // 7*112
#define GK     192            // gemm K
#define NPIX   12544
#define M_QKV  576
#define M_PROJ 192
#define SCALE_F 0.20412414523193154f  // 24^-0.5
#define LOG2E   1.44269504088896340736f

typedef unsigned short ushort_t;

// ---------------- scratch (device globals; no allocation) ----------------
__device__ float g_qkv_h[M_QKV * HWPIX];
__device__ float g_qkv_v[M_QKV * HWPIX];
__device__ float g_att_h[Cdim * HWPIX];
__device__ float g_att_v[Cdim * HWPIX];
__device__ ushort_t g_xhi[GK * NPIX];
__device__ ushort_t g_xlo[GK * NPIX];
__device__ ushort_t g_phi[GK * NPIX];
__device__ ushort_t g_plo[GK * NPIX];
__device__ ushort_t g_whh[M_QKV * GK];
__device__ ushort_t g_whl[M_QKV * GK];
__device__ ushort_t g_wvh[M_QKV * GK];
__device__ ushort_t g_wvl[M_QKV * GK];
__device__ ushort_t g_pwh[M_PROJ * GK];
__device__ ushort_t g_pwl[M_PROJ * GK];

// ---------------- helpers ----------------
__device__ __forceinline__ uint32_t bfp(float lo_el, float hi_el) {
    uint32_t r;
    asm("cvt.rn.bf16x2.f32 %0, %1, %2;" : "=r"(r) : "f"(hi_el), "f"(lo_el));
    return r;
}
__device__ __forceinline__ float bflo(uint32_t p) { return __uint_as_float(p << 16); }
__device__ __forceinline__ float bfhi(uint32_t p) { return __uint_as_float(p & 0xFFFF0000u); }

__device__ __forceinline__ uint32_t s2u(const void* p) {
    uint32_t a;
    asm("{ .reg .u64 t; cvta.to.shared.u64 t, %1; cvt.u32.u64 %0, t; }" : "=r"(a) : "l"(p));
    return a;
}
__device__ __forceinline__ float ex2f(float x) {
    float r;
    asm("ex2.approx.f32 %0, %1;" : "=f"(r) : "f"(x));
    return r;
}
__device__ __forceinline__ uint32_t hfp(float lo_el, float hi_el) {
    uint32_t r;
    asm("cvt.rn.f16x2.f32 %0, %1, %2;" : "=r"(r) : "f"(hi_el), "f"(lo_el));
    return r;
}

__device__ __forceinline__ void mma_bf16(float* c,
    uint32_t a0, uint32_t a1, uint32_t a2, uint32_t a3,
    uint32_t b0, uint32_t b1)
{
    asm volatile("mma.sync.aligned.m16n8k16.row.col.f32.bf16.bf16.f32 "
        "{%0,%1,%2,%3}, {%4,%5,%6,%7}, {%8,%9}, {%0,%1,%2,%3};"
        : "+f"(c[0]), "+f"(c[1]), "+f"(c[2]), "+f"(c[3])
        : "r"(a0), "r"(a1), "r"(a2), "r"(a3), "r"(b0), "r"(b1));
}
__device__ __forceinline__ void mma_f16(float* c,
    uint32_t a0, uint32_t a1, uint32_t a2, uint32_t a3,
    uint32_t b0, uint32_t b1)
{
    asm volatile("mma.sync.aligned.m16n8k16.row.col.f32.f16.f16.f32 "
        "{%0,%1,%2,%3}, {%4,%5,%6,%7}, {%8,%9}, {%0,%1,%2,%3};"
        : "+f"(c[0]), "+f"(c[1]), "+f"(c[2]), "+f"(c[3])
        : "r"(a0), "r"(a1), "r"(a2), "r"(a3), "r"(b0), "r"(b1));
}
__device__ __forceinline__ void mma_f16_k8(float* c,
    uint32_t a0, uint32_t a1, uint32_t b0)
{
    asm volatile("mma.sync.aligned.m16n8k8.row.col.f32.f16.f16.f32 "
        "{%0,%1,%2,%3}, {%4,%5}, {%6}, {%0,%1,%2,%3};"
        : "+f"(c[0]), "+f"(c[1]), "+f"(c[2]), "+f"(c[3])
        : "r"(a0), "r"(a1), "r"(b0));
}

__device__ __forceinline__ void ldsm4t(uint32_t& r0, uint32_t& r1,
                                       uint32_t& r2, uint32_t& r3, uint32_t a)
{
    asm volatile("ldmatrix.sync.aligned.m8n8.x4.trans.shared.b16 {%0,%1,%2,%3}, [%4];"
        : "=r"(r0), "=r"(r1), "=r"(r2), "=r"(r3) : "r"(a));
}
__device__ __forceinline__ void ldsm4(uint32_t& r0, uint32_t& r1,
                                      uint32_t& r2, uint32_t& r3, uint32_t a)
{
    asm volatile("ldmatrix.sync.aligned.m8n8.x4.shared.b16 {%0,%1,%2,%3}, [%4];"
        : "=r"(r0), "=r"(r1), "=r"(r2), "=r"(r3) : "r"(a));
}
__device__ __forceinline__ void ldsm2(uint32_t& r0, uint32_t& r1, uint32_t a)
{
    asm volatile("ldmatrix.sync.aligned.m8n8.x2.shared.b16 {%0,%1}, [%2];"
        : "=r"(r0), "=r"(r1) : "r"(a));
}

#define CPA16(dst, src) asm volatile("cp.async.ca.shared.global [%0], [%1], 16;" :: "r"(dst), "l"(src) : "memory")
#define CPC()  asm volatile("cp.async.commit_group;" ::: "memory")
#define CPW1() asm volatile("cp.async.wait_group 1;" ::: "memory")
#define CPW0() asm volatile("cp.async.wait_group 0;" ::: "memory")

// ---------------- combined split: x + 3 weights, one launch ----------------
__global__ __launch_bounds__(256) void split_all(
    const float4* __restrict__ sx, uint2* __restrict__ xh, uint2* __restrict__ xl, int n0,
    const float4* __restrict__ w1, uint2* __restrict__ h1p, uint2* __restrict__ l1p, int n1,
    const float4* __restrict__ w2, uint2* __restrict__ h2p, uint2* __restrict__ l2p, int n2,
    const float4* __restrict__ w3, uint2* __restrict__ h3p, uint2* __restrict__ l3p, int n3)
{
    int i = blockIdx.x * blockDim.x + threadIdx.x;
    const float4* src; uint2 *hd, *ld; int j = i;
    if (j < n0) { src = sx; hd = xh; ld = xl; }
    else if ((j -= n0) < n1) { src = w1; hd = h1p; ld = l1p; }
    else if ((j -= n1) < n2) { src = w2; hd = h2p; ld = l2p; }
    else if ((j -= n2) < n3) { src = w3; hd = h3p; ld = l3p; }
    else return;
    float4 v = src[j];
    uint32_t h0 = bfp(v.x, v.y);
    uint32_t h1 = bfp(v.z, v.w);
    uint32_t l0 = bfp(v.x - bflo(h0), v.y - bfhi(h0));
    uint32_t l1 = bfp(v.z - bflo(h1), v.w - bfhi(h1));
    hd[j] = make_uint2(h0, h1);
    ld[j] = make_uint2(l0, l1);
}

// ---------------- hi/lo bf16 mma GEMM, z-select A/bias/C ----------------
#define G_SBH 0
#define G_SBL 8704
#define G_SAH 17408
#define G_SAL 22528
#define G_BSTR 136
#define G_BBUF 4352
#define G_ASTR 40
#define G_ABUF 2560
#define G_TOTAL_BYTES 55296

__global__ __launch_bounds__(256) void gemm_mma(
    const ushort_t* __restrict__ Ah0, const ushort_t* __restrict__ Al0,
    const ushort_t* __restrict__ Ah1, const ushort_t* __restrict__ Al1,
    const ushort_t* __restrict__ Bhi, const ushort_t* __restrict__ Blo,
    const float* __restrict__ bias0, const float* __restrict__ bias1,
    float* __restrict__ C0, float* __restrict__ C1)
{
    extern __shared__ ushort_t gsm[];
    const ushort_t* __restrict__ Ahi = blockIdx.z ? Ah1 : Ah0;
    const ushort_t* __restrict__ Alo = blockIdx.z ? Al1 : Al0;
    const float* __restrict__ bias = blockIdx.z ? bias1 : bias0;
    float* __restrict__ C = blockIdx.z ? C1 : C0;

    const int tid = threadIdx.x;
    const int bn = blockIdx.x * 128, bm = blockIdx.y * 64;
    const int wid = tid >> 5, lane = tid & 31;
    const int wm = wid & 3, wn = wid >> 2;
    const int g = lane >> 2, q = lane & 3;
    const int wc = wn * 64;
    const int row0 = bm + wm * 16 + g;
    const int row1 = row0 + 8;

    float acc[8][4];
    #pragma unroll
    for (int i = 0; i < 8; i++)
        #pragma unroll
        for (int j = 0; j < 4; j++) acc[i][j] = 0.f;

    const int rB = tid >> 3;
    const int cB = (tid & 7) * 8;
    const int rA = tid >> 2;
    const int cA = (tid & 3) * 8;

    uint32_t smb = s2u(gsm);
    uint32_t dstBh[2], dstBl[2], dstAh[2], dstAl[2];
    #pragma unroll
    for (int b = 0; b < 2; b++) {
        dstBh[b] = smb + (uint32_t)((G_SBH + b * G_BBUF + rB * G_BSTR + cB) * 2);
        dstBl[b] = smb + (uint32_t)((G_SBL + b * G_BBUF + rB * G_BSTR + cB) * 2);
        dstAh[b] = smb + (uint32_t)((G_SAH + b * G_ABUF + rA * G_ASTR + cA) * 2);
        dstAl[b] = smb + (uint32_t)((G_SAL + b * G_ABUF + rA * G_ASTR + cA) * 2);
    }

    const int lm = lane >> 3, lr = lane & 7;
    const int lkrow = (lm & 1) * 8 + lr;
    const int lncol = wc + (lm >> 1) * 8;
    uint32_t sbh_base[2], sbl_base[2];
    const int arow = wm * 16 + (lm & 1) * 8 + lr;
    const int acol = (lane >> 4) * 8;
    uint32_t sah_base[2], sal_base[2];
    #pragma unroll
    for (int b = 0; b < 2; b++) {
        sbh_base[b] = smb + (uint32_t)((G_SBH + b * G_BBUF + lkrow * G_BSTR + lncol) * 2);
        sbl_base[b] = smb + (uint32_t)((G_SBL + b * G_BBUF + lkrow * G_BSTR + lncol) * 2);
        sah_base[b] = smb + (uint32_t)((G_SAH + b * G_ABUF + arow * G_ASTR + acol) * 2);
        sal_base[b] = smb + (uint32_t)((G_SAL + b * G_ABUF + arow * G_ASTR + acol) * 2);
    }

    {
        const ushort_t* bh = &Bhi[rB * NPIX + bn + cB];
        const ushort_t* bl = &Blo[rB * NPIX + bn + cB];
        CPA16(dstBh[0], bh); CPA16(dstBh[0] + 128, bh + 64);
        CPA16(dstBl[0], bl); CPA16(dstBl[0] + 128, bl + 64);
        CPA16(dstAh[0], &Ahi[(bm + rA) * GK + cA]);
        CPA16(dstAl[0], &Alo[(bm + rA) * GK + cA]);
        CPC();
    }

    #pragma unroll
    for (int ki = 0; ki < 6; ki++) {
        if (ki < 5) {
            const int kn = (ki + 1) * 32;
            const int bf = (ki + 1) & 1;
            const ushort_t* bh = &Bhi[(kn + rB) * NPIX + bn + cB];
            const ushort_t* bl = &Blo[(kn + rB) * NPIX + bn + cB];
            CPA16(dstBh[bf], bh); CPA16(dstBh[bf] + 128, bh + 64);
            CPA16(dstBl[bf], bl); CPA16(dstBl[bf] + 128, bl + 64);
            CPA16(dstAh[bf], &Ahi[(bm + rA) * GK + kn + cA]);
            CPA16(dstAl[bf], &Alo[(bm + rA) * GK + kn + cA]);
            CPC();
            CPW1();
        } else {
            CPW0();
        }
        __syncthreads();

        const int buf = ki & 1;
        #pragma unroll
        for (int hh = 0; hh < 2; hh++) {
            uint32_t ah[4], al[4];
            ldsm4(ah[0], ah[1], ah[2], ah[3], sah_base[buf] + hh * 32);
            ldsm4(al[0], al[1], al[2], al[3], sal_base[buf] + hh * 32);

            const uint32_t hoff = (uint32_t)(hh * 16 * G_BSTR) * 2;
            #pragma unroll
            for (int j = 0; j < 4; j++) {
                uint32_t off = hoff + (uint32_t)(j * 16) * 2;
                uint32_t bh0, bh1, bh2, bh3, bl0, bl1, bl2, bl3;
                ldsm4t(bh0, bh1, bh2, bh3, sbh_base[buf] + off);
                ldsm4t(bl0, bl1, bl2, bl3, sbl_base[buf] + off);
                float* c0 = acc[2 * j];
                float* c1 = acc[2 * j + 1];
                mma_bf16(c0, ah[0], ah[1], ah[2], ah[3], bh0, bh1);
                mma_bf16(c0, al[0], al[1], al[2], al[3], bh0, bh1);
                mma_bf16(c0, ah[0], ah[1], ah[2], ah[3], bl0, bl1);
                mma_bf16(c1, ah[0], ah[1], ah[2], ah[3], bh2, bh3);
                mma_bf16(c1, al[0], al[1], al[2], al[3], bh2, bh3);
                mma_bf16(c1, ah[0], ah[1], ah[2], ah[3], bl2, bl3);
            }
        }
        __syncthreads();
    }

    const float b0 = bias[row0], b1 = bias[row1];
    #pragma unroll
    for (int nf = 0; nf < 8; nf++) {
        int col = bn + wc + nf * 8 + 2 * q;
        *(float2*)&C[row0 * NPIX + col] = make_float2(acc[nf][0] + b0, acc[nf][1] + b0);
        *(float2*)&C[row1 * NPIX + col] = make_float2(acc[nf][2] + b1, acc[nf][3] + b1);
    }
}

// ============================================================================
// fp16 flash attention — K/V resident, S single-term (Qhi·Khi), PV 2-term.
// SMEM ~101 KB -> 2 CTAs/SM; __launch_bounds__(512, 2).
// ============================================================================
#define KSTR 40
#define VSTRF 792
#define NW    16
#define NTHR  512

#define A_SKH 0
#define A_SVH (A_SKH + LTOK * KSTR * 2)          // 62720
#define A_SB  (A_SVH + HDIM * VSTRF * 2)         // 100736
#define A_TOTAL (A_SB + 256)

__global__ __launch_bounds__(NTHR, 2) void attn_mma(
    const float* __restrict__ tab_h, const float* __restrict__ tab_v)
{
    extern __shared__ char asm_[];
    ushort_t* sKhi = (ushort_t*)(asm_ + A_SKH);
    ushort_t* sVhi = (ushort_t*)(asm_ + A_SVH);
    float* sb = (float*)(asm_ + A_SB);

    const int tid = threadIdx.x;
    const int w = blockIdx.x, h = blockIdx.y, br = blockIdx.z;
    const float* __restrict__ qkv = br ? g_qkv_v : g_qkv_h;
    float* __restrict__ outp = br ? g_att_v : g_att_h;
    const float* __restrict__ tab = br ? tab_v : tab_h;

    if (tid < 49) {
        int r1 = tid / 7, r2 = tid % 7, off = r1 - r2 + 6;
        float bv = br ? tab[(6 * 13 + off) * NHEAD + h]
                      : tab[(off * 13 + 6) * NHEAD + h];
        sb[tid] = bv * LOG2E;
    }
    // zero K pad dims 24..31, V pad keys 784..791
    for (int i = tid; i < LTOK * 8; i += NTHR) {
        int k = i >> 3, d = 24 + (i & 7);
        sKhi[k * KSTR + d] = 0;
    }
    if (tid < HDIM * 8) {
        int d = tid >> 3, k = LTOK + (tid & 7);
        sVhi[d * VSTRF + k] = 0;
    }
    for (int idx = tid; idx < LTOK * HDIM; idx += NTHR) {
        int d = idx / LTOK, k = idx - d * LTOK;
        int pix = br ? ((k / 7) * 112 + w * 7 + (k % 7)) : (w * LTOK + k);
        float kv = qkv[(192 + h * HDIM + d) * HWPIX + pix];
        float vv = qkv[(384 + h * HDIM + d) * HWPIX + pix];
        sKhi[k * KSTR + d] = __half_as_ushort(__float2half_rn(kv));
        sVhi[d * VSTRF + k] = __half_as_ushort(__float2half_rn(vv));
    }
    __syncthreads();

    const int warp = tid >> 5, lane = tid & 31;
    const int g = lane >> 2, q = lane & 3;
    const int d0 = 2 * q;
    const int lr = lane & 7;

    const uint32_t kln = (uint32_t)((lr * KSTR + (lane >> 3) * 8) * 2);
    const uint32_t skh_b = s2u(sKhi) + kln;
    const int vko = ((lane >> 3) & 1) * 8;
    const int vdh = ((lane >> 4) & 1) * 8 + lr;
    const uint32_t sv4 = s2u(sVhi) + (uint32_t)((vdh * VSTRF + vko) * 2);
    const uint32_t sv2a = s2u(sVhi) + (uint32_t)(((16 + lr) * VSTRF + vko) * 2);

    const float qscale = SCALE_F * LOG2E;

    for (int mt = warp; mt < 49; mt += NW) {
        const int r0 = mt * 16 + g, r1 = r0 + 8;
        const int pix0 = br ? ((r0 / 7) * 112 + w * 7 + (r0 % 7)) : (w * LTOK + r0);
        const int pix1 = br ? ((r1 / 7) * 112 + w * 7 + (r1 % 7)) : (w * LTOK + r1);
        const int bro0 = (br ? (r0 % 7) : (r0 / 112)) * 7;
        const int bro1 = (br ? (r1 % 7) : (r1 / 112)) * 7;

        uint32_t qh[6];
        #pragma unroll
        for (int p = 0; p < 3; p++) {
            int d = d0 + 8 * p;
            float a0v = qkv[(h * HDIM + d)     * HWPIX + pix0] * qscale;
            float a1v = qkv[(h * HDIM + d + 1) * HWPIX + pix0] * qscale;
            float b0v = qkv[(h * HDIM + d)     * HWPIX + pix1] * qscale;
            float b1v = qkv[(h * HDIM + d + 1) * HWPIX + pix1] * qscale;
            qh[2 * p]     = hfp(a0v, a1v);
            qh[2 * p + 1] = hfp(b0v, b1v);
        }

        float o[3][4];
        #pragma unroll
        for (int nd = 0; nd < 3; nd++)
            #pragma unroll
            for (int i = 0; i < 4; i++) o[nd][i] = 0.f;
        float rs0 = 0.f, rs1 = 0.f;

        for (int kt = 0; kt < 14; kt++) {
            float bh0 = 0.f, bh1 = 0.f;
            if (!br) { bh0 = sb[bro0 + (kt >> 1)]; bh1 = sb[bro1 + (kt >> 1)]; }
            const int kbase = kt * 56;

            #pragma unroll
            for (int ks = 0; ks < 4; ks++) {
                const int nt0 = 2 * ks, nt1 = nt0 + 1;
                const bool has1 = (nt1 < 7);
                float sA[4] = {0.f, 0.f, 0.f, 0.f};
                float sB[4] = {0.f, 0.f, 0.f, 0.f};

                {
                    uint32_t ko = (uint32_t)((kbase + nt0 * 8) * KSTR * 2);
                    uint32_t h0, h1, h2, h3;
                    ldsm4(h0, h1, h2, h3, skh_b + ko);
                    mma_f16(sA, qh[0], qh[1], qh[2], qh[3], h0, h1);
                    mma_f16_k8(sA, qh[4], qh[5], h2);
                }
                if (has1) {
                    uint32_t ko = (uint32_t)((kbase + nt1 * 8) * KSTR * 2);
                    uint32_t h0, h1, h2, h3;
                    ldsm4(h0, h1, h2, h3, skh_b + ko);
                    mma_f16(sB, qh[0], qh[1], qh[2], qh[3], h0, h1);
                    mma_f16_k8(sB, qh[4], qh[5], h2);
                }

                float eA0, eA1, eA2, eA3, eB0 = 0.f, eB1 = 0.f, eB2 = 0.f, eB3 = 0.f;
                if (!br) {
                    eA0 = ex2f(sA[0] + bh0); eA1 = ex2f(sA[1] + bh0);
                    eA2 = ex2f(sA[2] + bh1); eA3 = ex2f(sA[3] + bh1);
                    if (has1) {
                        eB0 = ex2f(sB[0] + bh0); eB1 = ex2f(sB[1] + bh0);
                        eB2 = ex2f(sB[2] + bh1); eB3 = ex2f(sB[3] + bh1);
                    }
                } else {
                    int i0 = (nt0 + d0) % 7;
                    int i1 = i0 + 1; if (i1 == 7) i1 = 0;
                    int j1 = i1 + 1; if (j1 == 7) j1 = 0;
                    eA0 = ex2f(sA[0] + sb[bro0 + i0]); eA1 = ex2f(sA[1] + sb[bro0 + i1]);
                    eA2 = ex2f(sA[2] + sb[bro1 + i0]); eA3 = ex2f(sA[3] + sb[bro1 + i1]);
                    if (has1) {
                        eB0 = ex2f(sB[0] + sb[bro0 + i1]); eB1 = ex2f(sB[1] + sb[bro0 + j1]);
                        eB2 = ex2f(sB[2] + sb[bro1 + i1]); eB3 = ex2f(sB[3] + sb[bro1 + j1]);
                    }
                }
                rs0 += eA0 + eA1 + eB0 + eB1;
                rs1 += eA2 + eA3 + eB2 + eB3;

                uint32_t pa0 = hfp(eA0, eA1), pa1 = hfp(eA2, eA3);
                uint32_t pa2 = has1 ? hfp(eB0, eB1) : 0u;
                uint32_t pa3 = has1 ? hfp(eB2, eB3) : 0u;
                uint32_t pl0 = hfp(eA0 - __half2float(__ushort_as_half((ushort_t)pa0)),
                                   eA1 - __half2float(__ushort_as_half((ushort_t)(pa0 >> 16))));
                uint32_t pl1 = hfp(eA2 - __half2float(__ushort_as_half((ushort_t)pa1)),
                                   eA3 - __half2float(__ushort_as_half((ushort_t)(pa1 >> 16))));
                uint32_t pl2 = has1 ? hfp(eB0 - __half2float(__ushort_as_half((ushort_t)pa2)),
                                          eB1 - __half2float(__ushort_as_half((ushort_t)(pa2 >> 16)))) : 0u;
                uint32_t pl3 = has1 ? hfp(eB2 - __half2float(__ushort_as_half((ushort_t)pa3)),
                                          eB3 - __half2float(__ushort_as_half((ushort_t)(pa3 >> 16)))) : 0u;

                {
                    uint32_t vo = (uint32_t)((kbase + ks * 16) * 2);
                    uint32_t va0, va1, va2, va3, vx0, vx1;
                    ldsm4(va0, va1, va2, va3, sv4 + vo);
                    ldsm2(vx0, vx1, sv2a + vo);
                    mma_f16(o[0], pa0, pa1, pa2, pa3, va0, va1);
                    mma_f16(o[0], pl0, pl1, pl2, pl3, va0, va1);
                    mma_f16(o[1], pa0, pa1, pa2, pa3, va2, va3);
                    mma_f16(o[1], pl0, pl1, pl2, pl3, va2, va3);
                    mma_f16(o[2], pa0, pa1, pa2, pa3, vx0, vx1);
                    mma_f16(o[2], pl0, pl1, pl2, pl3, vx0, vx1);
                }
            }
        }

        float a0 = rs0, a1 = rs1;
        a0 += __shfl_xor_sync(0xFFFFFFFFu, a0, 1);
        a0 += __shfl_xor_sync(0xFFFFFFFFu, a0, 2);
        a1 += __shfl_xor_sync(0xFFFFFFFFu, a1, 1);
        a1 += __shfl_xor_sync(0xFFFFFFFFu, a1, 2);
        float inv0 = 1.f / a0, inv1 = 1.f / a1;
        #pragma unroll
        for (int nd = 0; nd < 3; nd++) {
            int d = nd * 8 + d0;
            outp[(h * HDIM + d)     * HWPIX + pix0] = o[nd][0] * inv0;
            outp[(h * HDIM + d + 1) * HWPIX + pix0] = o[nd][1] * inv0;
            outp[(h * HDIM + d)     * HWPIX + pix1] = o[nd][2] * inv1;
            outp[(h * HDIM + d + 1) * HWPIX + pix1] = o[nd][3] * inv1;
        }
    }
}

// ---------------- fused dual LePE -> 0.5*(h+v) -> bf16 hi/lo planes ----------------
__global__ __launch_bounds__(256) void lepe_fused(
    const float* __restrict__ attH, const float* __restrict__ attV,
    const float* __restrict__ wH, const float* __restrict__ bH,
    const float* __restrict__ wV, const float* __restrict__ bV,
    ushort_t* __restrict__ phi, ushort_t* __restrict__ plo)
{
    int t = blockIdx.x * blockDim.x + threadIdx.x;
    if (t >= Cdim * (HWPIX / 4)) return;
    int c = t / (HWPIX / 4);
    int r = t % (HWPIX / 4);
    int y = r / 28, x4 = (r % 28) * 4;
    const float* baseH = attH + c * HWPIX;
    const float* baseV = attV + c * HWPIX;

    float wvh[9], wvv[9];
    #pragma unroll
    for (int i = 0; i < 9; i++) { wvh[i] = wH[c * 9 + i]; wvv[i] = wV[c * 9 + i]; }
    float ah0 = bH[c], ah1 = ah0, ah2 = ah0, ah3 = ah0;
    float av0 = bV[c], av1 = av0, av2 = av0, av3 = av0;

    #pragma unroll
    for (int ky = 0; ky < 3; ky++) {
        int yy = y + ky - 1;
        if (yy < 0 || yy >= 112) continue;
        const float* rpH = baseH + yy * 112 + x4;
        const float* rpV = baseV + yy * 112 + x4;
        float4 mH = *(const float4*)rpH;
        float4 mV = *(const float4*)rpV;
        float lfH = (x4 > 0)   ? rpH[-1] : 0.f;
        float rtH = (x4 < 108) ? rpH[4]  : 0.f;
        float lfV = (x4 > 0)   ? rpV[-1] : 0.f;
        float rtV = (x4 < 108) ? rpV[4]  : 0.f;
        float h0 = wvh[ky*3], h1 = wvh[ky*3+1], h2 = wvh[ky*3+2];
        float v0 = wvv[ky*3], v1 = wvv[ky*3+1], v2 = wvv[ky*3+2];
        ah0 += h0 * lfH  + h1 * mH.x + h2 * mH.y;
        ah1 += h0 * mH.x + h1 * mH.y + h2 * mH.z;
        ah2 += h0 * mH.y + h1 * mH.z + h2 * mH.w;
        ah3 += h0 * mH.z + h1 * mH.w + h2 * rtH;
        av0 += v0 * lfV  + v1 * mV.x + v2 * mV.y;
        av1 += v0 * mV.x + v1 * mV.y + v2 * mV.z;
        av2 += v0 * mV.y + v1 * mV.z + v2 * mV.w;
        av3 += v0 * mV.z + v1 * mV.w + v2 * rtV;
    }

    float4 inH = *(const float4*)(baseH + y * 112 + x4);
    float4 inV = *(const float4*)(baseV + y * 112 + x4);
    const float RS2 = 0.70710678118654752f;
    float oh0 = inH.x + 0.5f * ah0 * (1.f + erff(ah0 * RS2));
    float oh1 = inH.y + 0.5f * ah1 * (1.f + erff(ah1 * RS2));
    float oh2 = inH.z + 0.5f * ah2 * (1.f + erff(ah2 * RS2));
    float oh3 = inH.w + 0.5f * ah3 * (1.f + erff(ah3 * RS2));
    float ov0 = inV.x + 0.5f * av0 * (1.f + erff(av0 * RS2));
    float ov1 = inV.y + 0.5f * av1 * (1.f + erff(av1 * RS2));
    float ov2 = inV.z + 0.5f * av2 * (1.f + erff(av2 * RS2));
    float ov3 = inV.w + 0.5f * av3 * (1.f + erff(av3 * RS2));

    float p0 = 0.5f * (oh0 + ov0);
    float p1 = 0.5f * (oh1 + ov1);
    float p2 = 0.5f * (oh2 + ov2);
    float p3 = 0.5f * (oh3 + ov3);

    uint32_t h0w = bfp(p0, p1), h1w = bfp(p2, p3);
    uint32_t l0w = bfp(p0 - bflo(h0w), p1 - bfhi(h0w));
    uint32_t l1w = bfp(p2 - bflo(h1w), p3 - bfhi(h1w));
    int idx = c * HWPIX + y * 112 + x4;
    *(uint2*)&phi[idx] = make_uint2(h0w, h1w);
    *(uint2*)&plo[idx] = make_uint2(l0w, l1w);
}

// ---------------- launch ----------------
extern "C" void kernel_launch(void* const* d_in, const int* in_sizes, int n_in,
                              void* d_out, int out_size)
{
    const float* x        = (const float*)d_in[0];
    const float* qkv_h_w  = (const float*)d_in[1];
    const float* qkv_h_b  = (const float*)d_in[2];
    const float* qkv_v_w  = (const float*)d_in[3];
    const float* qkv_v_b  = (const float*)d_in[4];
    const float* proj_w   = (const float*)d_in[5];
    const float* proj_b   = (const float*)d_in[6];
    const float* lepe_h_w = (const float*)d_in[7];
    const float* lepe_h_b = (const float*)d_in[8];
    const float* lepe_v_w = (const float*)d_in[9];
    const float* lepe_v_b = (const float*)d_in[10];
    const float* tab_h    = (const float*)d_in[11];
    const float* tab_v    = (const float*)d_in[12];
    float* out = (float*)d_out;

    float *qh, *qv, *ah, *av;
    ushort_t *xhi, *xlo, *phi, *plo, *whh, *whl, *wvh, *wvl, *pwh, *pwl;
    cudaGetSymbolAddress((void**)&qh, g_qkv_h);
    cudaGetSymbolAddress((void**)&qv, g_qkv_v);
    cudaGetSymbolAddress((void**)&ah, g_att_h);
    cudaGetSymbolAddress((void**)&av, g_att_v);
    cudaGetSymbolAddress((void**)&xhi, g_xhi);
    cudaGetSymbolAddress((void**)&xlo, g_xlo);
    cudaGetSymbolAddress((void**)&phi, g_phi);
    cudaGetSymbolAddress((void**)&plo, g_plo);
    cudaGetSymbolAddress((void**)&whh, g_whh);
    cudaGetSymbolAddress((void**)&whl, g_whl);
    cudaGetSymbolAddress((void**)&wvh, g_wvh);
    cudaGetSymbolAddress((void**)&wvl, g_wvl);
    cudaGetSymbolAddress((void**)&pwh, g_pwh);
    cudaGetSymbolAddress((void**)&pwl, g_pwl);

    int nx4 = GK * NPIX / 4;
    int nw4 = M_QKV * GK / 4;
    int np4 = M_PROJ * GK / 4;
    int ntot = nx4 + nw4 * 2 + np4;
    split_all<<<(ntot + 255) / 256, 256>>>(
        (const float4*)x,       (uint2*)xhi, (uint2*)xlo, nx4,
        (const float4*)qkv_h_w, (uint2*)whh, (uint2*)whl, nw4,
        (const float4*)qkv_v_w, (uint2*)wvh, (uint2*)wvl, nw4,
        (const float4*)proj_w,  (uint2*)pwh, (uint2*)pwl, np4);

    cudaFuncSetAttribute(gemm_mma,
                         cudaFuncAttributeMaxDynamicSharedMemorySize, G_TOTAL_BYTES);
    dim3 gq(NPIX / 128, M_QKV / 64, 2);
    gemm_mma<<<gq, 256, G_TOTAL_BYTES>>>(whh, whl, wvh, wvl, xhi, xlo,
                                         qkv_h_b, qkv_v_b, qh, qv);

    cudaFuncSetAttribute(attn_mma,
                         cudaFuncAttributeMaxDynamicSharedMemorySize, A_TOTAL);
    dim3 ga(16, NHEAD, 2);
    attn_mma<<<ga, NTHR, A_TOTAL>>>(tab_h, tab_v);

    int nthr = Cdim * (HWPIX / 4);
    lepe_fused<<<(nthr + 255) / 256, 256>>>(ah, av, lepe_h_w, lepe_h_b,
                                            lepe_v_w, lepe_v_b, phi, plo);

    dim3 gp(NPIX / 128, M_PROJ / 64, 1);
    gemm_mma<<<gp, 256, G_TOTAL_BYTES>>>(pwh, pwl, pwh, pwl, phi, plo,
                                         proj_b, proj_b, out, out);
}

// round 13
// speedup vs baseline: 1.5897x; 1.0993x over previous
#include <cuda_runtime.h>
#include <cuda_bf16.h>
#include <cuda_fp16.h>
#include <cstdint>
#include <math.h>

#define Cdim   192
#define NHEAD  8
#define HDIM   24
#define HWPIX  12544          // 112*112
#define LTOK   784            // 7*112
#define GK     192            // gemm K
#define NPIX   12544
#define M_QKV  576
#define M_PROJ 192
#define SCALE_F 0.20412414523193154f  // 24^-0.5
#define LOG2E   1.44269504088896340736f

typedef unsigned short ushort_t;

// ---------------- scratch (device globals; no allocation) ----------------
__device__ float g_qkv_h[M_QKV * HWPIX];
__device__ float g_qkv_v[M_QKV * HWPIX];
__device__ float g_att_h[Cdim * HWPIX];
__device__ float g_att_v[Cdim * HWPIX];
__device__ ushort_t g_xhi[GK * NPIX];
__device__ ushort_t g_xlo[GK * NPIX];
__device__ ushort_t g_phi[GK * NPIX];
__device__ ushort_t g_plo[GK * NPIX];
__device__ ushort_t g_whh[M_QKV * GK];
__device__ ushort_t g_whl[M_QKV * GK];
__device__ ushort_t g_wvh[M_QKV * GK];
__device__ ushort_t g_wvl[M_QKV * GK];
__device__ ushort_t g_pwh[M_PROJ * GK];
__device__ ushort_t g_pwl[M_PROJ * GK];

// ---------------- helpers ----------------
__device__ __forceinline__ uint32_t bfp(float lo_el, float hi_el) {
    uint32_t r;
    asm("cvt.rn.bf16x2.f32 %0, %1, %2;" : "=r"(r) : "f"(hi_el), "f"(lo_el));
    return r;
}
__device__ __forceinline__ float bflo(uint32_t p) { return __uint_as_float(p << 16); }
__device__ __forceinline__ float bfhi(uint32_t p) { return __uint_as_float(p & 0xFFFF0000u); }

__device__ __forceinline__ uint32_t s2u(const void* p) {
    uint32_t a;
    asm("{ .reg .u64 t; cvta.to.shared.u64 t, %1; cvt.u32.u64 %0, t; }" : "=r"(a) : "l"(p));
    return a;
}
__device__ __forceinline__ float ex2f(float x) {
    float r;
    asm("ex2.approx.f32 %0, %1;" : "=f"(r) : "f"(x));
    return r;
}
__device__ __forceinline__ uint32_t hfp(float lo_el, float hi_el) {
    uint32_t r;
    asm("cvt.rn.f16x2.f32 %0, %1, %2;" : "=r"(r) : "f"(hi_el), "f"(lo_el));
    return r;
}

__device__ __forceinline__ void mma_bf16(float* c,
    uint32_t a0, uint32_t a1, uint32_t a2, uint32_t a3,
    uint32_t b0, uint32_t b1)
{
    asm volatile("mma.sync.aligned.m16n8k16.row.col.f32.bf16.bf16.f32 "
        "{%0,%1,%2,%3}, {%4,%5,%6,%7}, {%8,%9}, {%0,%1,%2,%3};"
        : "+f"(c[0]), "+f"(c[1]), "+f"(c[2]), "+f"(c[3])
        : "r"(a0), "r"(a1), "r"(a2), "r"(a3), "r"(b0), "r"(b1));
}
__device__ __forceinline__ void mma_f16(float* c,
    uint32_t a0, uint32_t a1, uint32_t a2, uint32_t a3,
    uint32_t b0, uint32_t b1)
{
    asm volatile("mma.sync.aligned.m16n8k16.row.col.f32.f16.f16.f32 "
        "{%0,%1,%2,%3}, {%4,%5,%6,%7}, {%8,%9}, {%0,%1,%2,%3};"
        : "+f"(c[0]), "+f"(c[1]), "+f"(c[2]), "+f"(c[3])
        : "r"(a0), "r"(a1), "r"(a2), "r"(a3), "r"(b0), "r"(b1));
}
__device__ __forceinline__ void mma_f16_k8(float* c,
    uint32_t a0, uint32_t a1, uint32_t b0)
{
    asm volatile("mma.sync.aligned.m16n8k8.row.col.f32.f16.f16.f32 "
        "{%0,%1,%2,%3}, {%4,%5}, {%6}, {%0,%1,%2,%3};"
        : "+f"(c[0]), "+f"(c[1]), "+f"(c[2]), "+f"(c[3])
        : "r"(a0), "r"(a1), "r"(b0));
}

__device__ __forceinline__ void ldsm4t(uint32_t& r0, uint32_t& r1,
                                       uint32_t& r2, uint32_t& r3, uint32_t a)
{
    asm volatile("ldmatrix.sync.aligned.m8n8.x4.trans.shared.b16 {%0,%1,%2,%3}, [%4];"
        : "=r"(r0), "=r"(r1), "=r"(r2), "=r"(r3) : "r"(a));
}
__device__ __forceinline__ void ldsm4(uint32_t& r0, uint32_t& r1,
                                      uint32_t& r2, uint32_t& r3, uint32_t a)
{
    asm volatile("ldmatrix.sync.aligned.m8n8.x4.shared.b16 {%0,%1,%2,%3}, [%4];"
        : "=r"(r0), "=r"(r1), "=r"(r2), "=r"(r3) : "r"(a));
}
__device__ __forceinline__ void ldsm2(uint32_t& r0, uint32_t& r1, uint32_t a)
{
    asm volatile("ldmatrix.sync.aligned.m8n8.x2.shared.b16 {%0,%1}, [%2];"
        : "=r"(r0), "=r"(r1) : "r"(a));
}

#define CPA16(dst, src) asm volatile("cp.async.ca.shared.global [%0], [%1], 16;" :: "r"(dst), "l"(src) : "memory")
#define CPC()  asm volatile("cp.async.commit_group;" ::: "memory")
#define CPW1() asm volatile("cp.async.wait_group 1;" ::: "memory")
#define CPW0() asm volatile("cp.async.wait_group 0;" ::: "memory")

// ---------------- combined split: x + 3 weights, one launch ----------------
__global__ __launch_bounds__(256) void split_all(
    const float4* __restrict__ sx, uint2* __restrict__ xh, uint2* __restrict__ xl, int n0,
    const float4* __restrict__ w1, uint2* __restrict__ h1p, uint2* __restrict__ l1p, int n1,
    const float4* __restrict__ w2, uint2* __restrict__ h2p, uint2* __restrict__ l2p, int n2,
    const float4* __restrict__ w3, uint2* __restrict__ h3p, uint2* __restrict__ l3p, int n3)
{
    int i = blockIdx.x * blockDim.x + threadIdx.x;
    const float4* src; uint2 *hd, *ld; int j = i;
    if (j < n0) { src = sx; hd = xh; ld = xl; }
    else if ((j -= n0) < n1) { src = w1; hd = h1p; ld = l1p; }
    else if ((j -= n1) < n2) { src = w2; hd = h2p; ld = l2p; }
    else if ((j -= n2) < n3) { src = w3; hd = h3p; ld = l3p; }
    else return;
    float4 v = src[j];
    uint32_t h0 = bfp(v.x, v.y);
    uint32_t h1 = bfp(v.z, v.w);
    uint32_t l0 = bfp(v.x - bflo(h0), v.y - bfhi(h0));
    uint32_t l1 = bfp(v.z - bflo(h1), v.w - bfhi(h1));
    hd[j] = make_uint2(h0, h1);
    ld[j] = make_uint2(l0, l1);
}

// ---------------- hi/lo bf16 mma GEMM, z-select A/bias/C ----------------
#define G_SBH 0
#define G_SBL 8704
#define G_SAH 17408
#define G_SAL 22528
#define G_BSTR 136
#define G_BBUF 4352
#define G_ASTR 40
#define G_ABUF 2560
#define G_TOTAL_BYTES 55296

__global__ __launch_bounds__(256) void gemm_mma(
    const ushort_t* __restrict__ Ah0, const ushort_t* __restrict__ Al0,
    const ushort_t* __restrict__ Ah1, const ushort_t* __restrict__ Al1,
    const ushort_t* __restrict__ Bhi, const ushort_t* __restrict__ Blo,
    const float* __restrict__ bias0, const float* __restrict__ bias1,
    float* __restrict__ C0, float* __restrict__ C1)
{
    extern __shared__ ushort_t gsm[];
    const ushort_t* __restrict__ Ahi = blockIdx.z ? Ah1 : Ah0;
    const ushort_t* __restrict__ Alo = blockIdx.z ? Al1 : Al0;
    const float* __restrict__ bias = blockIdx.z ? bias1 : bias0;
    float* __restrict__ C = blockIdx.z ? C1 : C0;

    const int tid = threadIdx.x;
    const int bn = blockIdx.x * 128, bm = blockIdx.y * 64;
    const int wid = tid >> 5, lane = tid & 31;
    const int wm = wid & 3, wn = wid >> 2;
    const int g = lane >> 2, q = lane & 3;
    const int wc = wn * 64;
    const int row0 = bm + wm * 16 + g;
    const int row1 = row0 + 8;

    float acc[8][4];
    #pragma unroll
    for (int i = 0; i < 8; i++)
        #pragma unroll
        for (int j = 0; j < 4; j++) acc[i][j] = 0.f;

    const int rB = tid >> 3;
    const int cB = (tid & 7) * 8;
    const int rA = tid >> 2;
    const int cA = (tid & 3) * 8;

    uint32_t smb = s2u(gsm);
    uint32_t dstBh[2], dstBl[2], dstAh[2], dstAl[2];
    #pragma unroll
    for (int b = 0; b < 2; b++) {
        dstBh[b] = smb + (uint32_t)((G_SBH + b * G_BBUF + rB * G_BSTR + cB) * 2);
        dstBl[b] = smb + (uint32_t)((G_SBL + b * G_BBUF + rB * G_BSTR + cB) * 2);
        dstAh[b] = smb + (uint32_t)((G_SAH + b * G_ABUF + rA * G_ASTR + cA) * 2);
        dstAl[b] = smb + (uint32_t)((G_SAL + b * G_ABUF + rA * G_ASTR + cA) * 2);
    }

    const int lm = lane >> 3, lr = lane & 7;
    const int lkrow = (lm & 1) * 8 + lr;
    const int lncol = wc + (lm >> 1) * 8;
    uint32_t sbh_base[2], sbl_base[2];
    const int arow = wm * 16 + (lm & 1) * 8 + lr;
    const int acol = (lane >> 4) * 8;
    uint32_t sah_base[2], sal_base[2];
    #pragma unroll
    for (int b = 0; b < 2; b++) {
        sbh_base[b] = smb + (uint32_t)((G_SBH + b * G_BBUF + lkrow * G_BSTR + lncol) * 2);
        sbl_base[b] = smb + (uint32_t)((G_SBL + b * G_BBUF + lkrow * G_BSTR + lncol) * 2);
        sah_base[b] = smb + (uint32_t)((G_SAH + b * G_ABUF + arow * G_ASTR + acol) * 2);
        sal_base[b] = smb + (uint32_t)((G_SAL + b * G_ABUF + arow * G_ASTR + acol) * 2);
    }

    {
        const ushort_t* bh = &Bhi[rB * NPIX + bn + cB];
        const ushort_t* bl = &Blo[rB * NPIX + bn + cB];
        CPA16(dstBh[0], bh); CPA16(dstBh[0] + 128, bh + 64);
        CPA16(dstBl[0], bl); CPA16(dstBl[0] + 128, bl + 64);
        CPA16(dstAh[0], &Ahi[(bm + rA) * GK + cA]);
        CPA16(dstAl[0], &Alo[(bm + rA) * GK + cA]);
        CPC();
    }

    #pragma unroll
    for (int ki = 0; ki < 6; ki++) {
        if (ki < 5) {
            const int kn = (ki + 1) * 32;
            const int bf = (ki + 1) & 1;
            const ushort_t* bh = &Bhi[(kn + rB) * NPIX + bn + cB];
            const ushort_t* bl = &Blo[(kn + rB) * NPIX + bn + cB];
            CPA16(dstBh[bf], bh); CPA16(dstBh[bf] + 128, bh + 64);
            CPA16(dstBl[bf], bl); CPA16(dstBl[bf] + 128, bl + 64);
            CPA16(dstAh[bf], &Ahi[(bm + rA) * GK + kn + cA]);
            CPA16(dstAl[bf], &Alo[(bm + rA) * GK + kn + cA]);
            CPC();
            CPW1();
        } else {
            CPW0();
        }
        __syncthreads();

        const int buf = ki & 1;
        #pragma unroll
        for (int hh = 0; hh < 2; hh++) {
            uint32_t ah[4], al[4];
            ldsm4(ah[0], ah[1], ah[2], ah[3], sah_base[buf] + hh * 32);
            ldsm4(al[0], al[1], al[2], al[3], sal_base[buf] + hh * 32);

            const uint32_t hoff = (uint32_t)(hh * 16 * G_BSTR) * 2;
            #pragma unroll
            for (int j = 0; j < 4; j++) {
                uint32_t off = hoff + (uint32_t)(j * 16) * 2;
                uint32_t bh0, bh1, bh2, bh3, bl0, bl1, bl2, bl3;
                ldsm4t(bh0, bh1, bh2, bh3, sbh_base[buf] + off);
                ldsm4t(bl0, bl1, bl2, bl3, sbl_base[buf] + off);
                float* c0 = acc[2 * j];
                float* c1 = acc[2 * j + 1];
                mma_bf16(c0, ah[0], ah[1], ah[2], ah[3], bh0, bh1);
                mma_bf16(c0, al[0], al[1], al[2], al[3], bh0, bh1);
                mma_bf16(c0, ah[0], ah[1], ah[2], ah[3], bl0, bl1);
                mma_bf16(c1, ah[0], ah[1], ah[2], ah[3], bh2, bh3);
                mma_bf16(c1, al[0], al[1], al[2], al[3], bh2, bh3);
                mma_bf16(c1, ah[0], ah[1], ah[2], ah[3], bl2, bl3);
            }
        }
        __syncthreads();
    }

    const float b0 = bias[row0], b1 = bias[row1];
    #pragma unroll
    for (int nf = 0; nf < 8; nf++) {
        int col = bn + wc + nf * 8 + 2 * q;
        *(float2*)&C[row0 * NPIX + col] = make_float2(acc[nf][0] + b0, acc[nf][1] + b0);
        *(float2*)&C[row1 * NPIX + col] = make_float2(acc[nf][2] + b1, acc[nf][3] + b1);
    }
}

// ============================================================================
// fp16 flash attention — K/V resident, S single-term, PV single-term (P·Vhi).
// SMEM ~101 KB -> 2 CTAs/SM.
// ============================================================================
#define KSTR 40
#define VSTRF 792
#define NW    16
#define NTHR  512

#define A_SKH 0
#define A_SVH (A_SKH + LTOK * KSTR * 2)          // 62720
#define A_SB  (A_SVH + HDIM * VSTRF * 2)         // 100736
#define A_TOTAL (A_SB + 256)

__global__ __launch_bounds__(NTHR, 2) void attn_mma(
    const float* __restrict__ tab_h, const float* __restrict__ tab_v)
{
    extern __shared__ char asm_[];
    ushort_t* sKhi = (ushort_t*)(asm_ + A_SKH);
    ushort_t* sVhi = (ushort_t*)(asm_ + A_SVH);
    float* sb = (float*)(asm_ + A_SB);

    const int tid = threadIdx.x;
    const int w = blockIdx.x, h = blockIdx.y, br = blockIdx.z;
    const float* __restrict__ qkv = br ? g_qkv_v : g_qkv_h;
    float* __restrict__ outp = br ? g_att_v : g_att_h;
    const float* __restrict__ tab = br ? tab_v : tab_h;

    if (tid < 49) {
        int r1 = tid / 7, r2 = tid % 7, off = r1 - r2 + 6;
        float bv = br ? tab[(6 * 13 + off) * NHEAD + h]
                      : tab[(off * 13 + 6) * NHEAD + h];
        sb[tid] = bv * LOG2E;
    }
    for (int i = tid; i < LTOK * 8; i += NTHR) {
        int k = i >> 3, d = 24 + (i & 7);
        sKhi[k * KSTR + d] = 0;
    }
    if (tid < HDIM * 8) {
        int d = tid >> 3, k = LTOK + (tid & 7);
        sVhi[d * VSTRF + k] = 0;
    }
    for (int idx = tid; idx < LTOK * HDIM; idx += NTHR) {
        int d = idx / LTOK, k = idx - d * LTOK;
        int pix = br ? ((k / 7) * 112 + w * 7 + (k % 7)) : (w * LTOK + k);
        float kv = qkv[(192 + h * HDIM + d) * HWPIX + pix];
        float vv = qkv[(384 + h * HDIM + d) * HWPIX + pix];
        sKhi[k * KSTR + d] = __half_as_ushort(__float2half_rn(kv));
        sVhi[d * VSTRF + k] = __half_as_ushort(__float2half_rn(vv));
    }
    __syncthreads();

    const int warp = tid >> 5, lane = tid & 31;
    const int g = lane >> 2, q = lane & 3;
    const int d0 = 2 * q;
    const int lr = lane & 7;

    const uint32_t kln = (uint32_t)((lr * KSTR + (lane >> 3) * 8) * 2);
    const uint32_t skh_b = s2u(sKhi) + kln;
    const int vko = ((lane >> 3) & 1) * 8;
    const int vdh = ((lane >> 4) & 1) * 8 + lr;
    const uint32_t sv4 = s2u(sVhi) + (uint32_t)((vdh * VSTRF + vko) * 2);
    const uint32_t sv2a = s2u(sVhi) + (uint32_t)(((16 + lr) * VSTRF + vko) * 2);

    const float qscale = SCALE_F * LOG2E;

    for (int mt = warp; mt < 49; mt += NW) {
        const int r0 = mt * 16 + g, r1 = r0 + 8;
        const int pix0 = br ? ((r0 / 7) * 112 + w * 7 + (r0 % 7)) : (w * LTOK + r0);
        const int pix1 = br ? ((r1 / 7) * 112 + w * 7 + (r1 % 7)) : (w * LTOK + r1);
        const int bro0 = (br ? (r0 % 7) : (r0 / 112)) * 7;
        const int bro1 = (br ? (r1 % 7) : (r1 / 112)) * 7;

        uint32_t qh[6];
        #pragma unroll
        for (int p = 0; p < 3; p++) {
            int d = d0 + 8 * p;
            float a0v = qkv[(h * HDIM + d)     * HWPIX + pix0] * qscale;
            float a1v = qkv[(h * HDIM + d + 1) * HWPIX + pix0] * qscale;
            float b0v = qkv[(h * HDIM + d)     * HWPIX + pix1] * qscale;
            float b1v = qkv[(h * HDIM + d + 1) * HWPIX + pix1] * qscale;
            qh[2 * p]     = hfp(a0v, a1v);
            qh[2 * p + 1] = hfp(b0v, b1v);
        }

        float o[3][4];
        #pragma unroll
        for (int nd = 0; nd < 3; nd++)
            #pragma unroll
            for (int i = 0; i < 4; i++) o[nd][i] = 0.f;
        float rs0 = 0.f, rs1 = 0.f;

        for (int kt = 0; kt < 14; kt++) {
            float bh0 = 0.f, bh1 = 0.f;
            if (!br) { bh0 = sb[bro0 + (kt >> 1)]; bh1 = sb[bro1 + (kt >> 1)]; }
            const int kbase = kt * 56;

            #pragma unroll
            for (int ks = 0; ks < 4; ks++) {
                const int nt0 = 2 * ks, nt1 = nt0 + 1;
                const bool has1 = (nt1 < 7);
                float sA[4] = {0.f, 0.f, 0.f, 0.f};
                float sB[4] = {0.f, 0.f, 0.f, 0.f};

                {
                    uint32_t ko = (uint32_t)((kbase + nt0 * 8) * KSTR * 2);
                    uint32_t h0, h1, h2, h3;
                    ldsm4(h0, h1, h2, h3, skh_b + ko);
                    mma_f16(sA, qh[0], qh[1], qh[2], qh[3], h0, h1);
                    mma_f16_k8(sA, qh[4], qh[5], h2);
                }
                if (has1) {
                    uint32_t ko = (uint32_t)((kbase + nt1 * 8) * KSTR * 2);
                    uint32_t h0, h1, h2, h3;
                    ldsm4(h0, h1, h2, h3, skh_b + ko);
                    mma_f16(sB, qh[0], qh[1], qh[2], qh[3], h0, h1);
                    mma_f16_k8(sB, qh[4], qh[5], h2);
                }

                float eA0, eA1, eA2, eA3, eB0 = 0.f, eB1 = 0.f, eB2 = 0.f, eB3 = 0.f;
                if (!br) {
                    eA0 = ex2f(sA[0] + bh0); eA1 = ex2f(sA[1] + bh0);
                    eA2 = ex2f(sA[2] + bh1); eA3 = ex2f(sA[3] + bh1);
                    if (has1) {
                        eB0 = ex2f(sB[0] + bh0); eB1 = ex2f(sB[1] + bh0);
                        eB2 = ex2f(sB[2] + bh1); eB3 = ex2f(sB[3] + bh1);
                    }
                } else {
                    int i0 = (nt0 + d0) % 7;
                    int i1 = i0 + 1; if (i1 == 7) i1 = 0;
                    int j1 = i1 + 1; if (j1 == 7) j1 = 0;
                    eA0 = ex2f(sA[0] + sb[bro0 + i0]); eA1 = ex2f(sA[1] + sb[bro0 + i1]);
                    eA2 = ex2f(sA[2] + sb[bro1 + i0]); eA3 = ex2f(sA[3] + sb[bro1 + i1]);
                    if (has1) {
                        eB0 = ex2f(sB[0] + sb[bro0 + i1]); eB1 = ex2f(sB[1] + sb[bro0 + j1]);
                        eB2 = ex2f(sB[2] + sb[bro1 + i1]); eB3 = ex2f(sB[3] + sb[bro1 + j1]);
                    }
                }
                rs0 += eA0 + eA1 + eB0 + eB1;
                rs1 += eA2 + eA3 + eB2 + eB3;

                uint32_t pa0 = hfp(eA0, eA1), pa1 = hfp(eA2, eA3);
                uint32_t pa2 = has1 ? hfp(eB0, eB1) : 0u;
                uint32_t pa3 = has1 ? hfp(eB2, eB3) : 0u;

                {
                    uint32_t vo = (uint32_t)((kbase + ks * 16) * 2);
                    uint32_t va0, va1, va2, va3, vx0, vx1;
                    ldsm4(va0, va1, va2, va3, sv4 + vo);
                    ldsm2(vx0, vx1, sv2a + vo);
                    mma_f16(o[0], pa0, pa1, pa2, pa3, va0, va1);
                    mma_f16(o[1], pa0, pa1, pa2, pa3, va2, va3);
                    mma_f16(o[2], pa0, pa1, pa2, pa3, vx0, vx1);
                }
            }
        }

        float a0 = rs0, a1 = rs1;
        a0 += __shfl_xor_sync(0xFFFFFFFFu, a0, 1);
        a0 += __shfl_xor_sync(0xFFFFFFFFu, a0, 2);
        a1 += __shfl_xor_sync(0xFFFFFFFFu, a1, 1);
        a1 += __shfl_xor_sync(0xFFFFFFFFu, a1, 2);
        float inv0 = 1.f / a0, inv1 = 1.f / a1;
        #pragma unroll
        for (int nd = 0; nd < 3; nd++) {
            int d = nd * 8 + d0;
            outp[(h * HDIM + d)     * HWPIX + pix0] = o[nd][0] * inv0;
            outp[(h * HDIM + d + 1) * HWPIX + pix0] = o[nd][1] * inv0;
            outp[(h * HDIM + d)     * HWPIX + pix1] = o[nd][2] * inv1;
            outp[(h * HDIM + d + 1) * HWPIX + pix1] = o[nd][3] * inv1;
        }
    }
}

// ---------------- fused dual LePE -> 0.5*(h+v) -> bf16 hi/lo planes ----------------
__global__ __launch_bounds__(256) void lepe_fused(
    const float* __restrict__ attH, const float* __restrict__ attV,
    const float* __restrict__ wH, const float* __restrict__ bH,
    const float* __restrict__ wV, const float* __restrict__ bV,
    ushort_t* __restrict__ phi, ushort_t* __restrict__ plo)
{
    int t = blockIdx.x * blockDim.x + threadIdx.x;
    if (t >= Cdim * (HWPIX / 4)) return;
    int c = t / (HWPIX / 4);
    int r = t % (HWPIX / 4);
    int y = r / 28, x4 = (r % 28) * 4;
    const float* baseH = attH + c * HWPIX;
    const float* baseV = attV + c * HWPIX;

    float wvh[9], wvv[9];
    #pragma unroll
    for (int i = 0; i < 9; i++) { wvh[i] = wH[c * 9 + i]; wvv[i] = wV[c * 9 + i]; }
    float ah0 = bH[c], ah1 = ah0, ah2 = ah0, ah3 = ah0;
    float av0 = bV[c], av1 = av0, av2 = av0, av3 = av0;

    #pragma unroll
    for (int ky = 0; ky < 3; ky++) {
        int yy = y + ky - 1;
        if (yy < 0 || yy >= 112) continue;
        const float* rpH = baseH + yy * 112 + x4;
        const float* rpV = baseV + yy * 112 + x4;
        float4 mH = *(const float4*)rpH;
        float4 mV = *(const float4*)rpV;
        float lfH = (x4 > 0)   ? rpH[-1] : 0.f;
        float rtH = (x4 < 108) ? rpH[4]  : 0.f;
        float lfV = (x4 > 0)   ? rpV[-1] : 0.f;
        float rtV = (x4 < 108) ? rpV[4]  : 0.f;
        float h0 = wvh[ky*3], h1 = wvh[ky*3+1], h2 = wvh[ky*3+2];
        float v0 = wvv[ky*3], v1 = wvv[ky*3+1], v2 = wvv[ky*3+2];
        ah0 += h0 * lfH  + h1 * mH.x + h2 * mH.y;
        ah1 += h0 * mH.x + h1 * mH.y + h2 * mH.z;
        ah2 += h0 * mH.y + h1 * mH.z + h2 * mH.w;
        ah3 += h0 * mH.z + h1 * mH.w + h2 * rtH;
        av0 += v0 * lfV  + v1 * mV.x + v2 * mV.y;
        av1 += v0 * mV.x + v1 * mV.y + v2 * mV.z;
        av2 += v0 * mV.y + v1 * mV.z + v2 * mV.w;
        av3 += v0 * mV.z + v1 * mV.w + v2 * rtV;
    }

    float4 inH = *(const float4*)(baseH + y * 112 + x4);
    float4 inV = *(const float4*)(baseV + y * 112 + x4);
    const float RS2 = 0.70710678118654752f;
    float oh0 = inH.x + 0.5f * ah0 * (1.f + erff(ah0 * RS2));
    float oh1 = inH.y + 0.5f * ah1 * (1.f + erff(ah1 * RS2));
    float oh2 = inH.z + 0.5f * ah2 * (1.f + erff(ah2 * RS2));
    float oh3 = inH.w + 0.5f * ah3 * (1.f + erff(ah3 * RS2));
    float ov0 = inV.x + 0.5f * av0 * (1.f + erff(av0 * RS2));
    float ov1 = inV.y + 0.5f * av1 * (1.f + erff(av1 * RS2));
    float ov2 = inV.z + 0.5f * av2 * (1.f + erff(av2 * RS2));
    float ov3 = inV.w + 0.5f * av3 * (1.f + erff(av3 * RS2));

    float p0 = 0.5f * (oh0 + ov0);
    float p1 = 0.5f * (oh1 + ov1);
    float p2 = 0.5f * (oh2 + ov2);
    float p3 = 0.5f * (oh3 + ov3);

    uint32_t h0w = bfp(p0, p1), h1w = bfp(p2, p3);
    uint32_t l0w = bfp(p0 - bflo(h0w), p1 - bfhi(h0w));
    uint32_t l1w = bfp(p2 - bflo(h1w), p3 - bfhi(h1w));
    int idx = c * HWPIX + y * 112 + x4;
    *(uint2*)&phi[idx] = make_uint2(h0w, h1w);
    *(uint2*)&plo[idx] = make_uint2(l0w, l1w);
}

// ---------------- launch ----------------
extern "C" void kernel_launch(void* const* d_in, const int* in_sizes, int n_in,
                              void* d_out, int out_size)
{
    const float* x        = (const float*)d_in[0];
    const float* qkv_h_w  = (const float*)d_in[1];
    const float* qkv_h_b  = (const float*)d_in[2];
    const float* qkv_v_w  = (const float*)d_in[3];
    const float* qkv_v_b  = (const float*)d_in[4];
    const float* proj_w   = (const float*)d_in[5];
    const float* proj_b   = (const float*)d_in[6];
    const float* lepe_h_w = (const float*)d_in[7];
    const float* lepe_h_b = (const float*)d_in[8];
    const float* lepe_v_w = (const float*)d_in[9];
    const float* lepe_v_b = (const float*)d_in[10];
    const float* tab_h    = (const float*)d_in[11];
    const float* tab_v    = (const float*)d_in[12];
    float* out = (float*)d_out;

    float *qh, *qv, *ah, *av;
    ushort_t *xhi, *xlo, *phi, *plo, *whh, *whl, *wvh, *wvl, *pwh, *pwl;
    cudaGetSymbolAddress((void**)&qh, g_qkv_h);
    cudaGetSymbolAddress((void**)&qv, g_qkv_v);
    cudaGetSymbolAddress((void**)&ah, g_att_h);
    cudaGetSymbolAddress((void**)&av, g_att_v);
    cudaGetSymbolAddress((void**)&xhi, g_xhi);
    cudaGetSymbolAddress((void**)&xlo, g_xlo);
    cudaGetSymbolAddress((void**)&phi, g_phi);
    cudaGetSymbolAddress((void**)&plo, g_plo);
    cudaGetSymbolAddress((void**)&whh, g_whh);
    cudaGetSymbolAddress((void**)&whl, g_whl);
    cudaGetSymbolAddress((void**)&wvh, g_wvh);
    cudaGetSymbolAddress((void**)&wvl, g_wvl);
    cudaGetSymbolAddress((void**)&pwh, g_pwh);
    cudaGetSymbolAddress((void**)&pwl, g_pwl);

    int nx4 = GK * NPIX / 4;
    int nw4 = M_QKV * GK / 4;
    int np4 = M_PROJ * GK / 4;
    int ntot = nx4 + nw4 * 2 + np4;
    split_all<<<(ntot + 255) / 256, 256>>>(
        (const float4*)x,       (uint2*)xhi, (uint2*)xlo, nx4,
        (const float4*)qkv_h_w, (uint2*)whh, (uint2*)whl, nw4,
        (const float4*)qkv_v_w, (uint2*)wvh, (uint2*)wvl, nw4,
        (const float4*)proj_w,  (uint2*)pwh, (uint2*)pwl, np4);

    cudaFuncSetAttribute(gemm_mma,
                         cudaFuncAttributeMaxDynamicSharedMemorySize, G_TOTAL_BYTES);
    dim3 gq(NPIX / 128, M_QKV / 64, 2);
    gemm_mma<<<gq, 256, G_TOTAL_BYTES>>>(whh, whl, wvh, wvl, xhi, xlo,
                                         qkv_h_b, qkv_v_b, qh, qv);

    cudaFuncSetAttribute(attn_mma,
                         cudaFuncAttributeMaxDynamicSharedMemorySize, A_TOTAL);
    dim3 ga(16, NHEAD, 2);
    attn_mma<<<ga, NTHR, A_TOTAL>>>(tab_h, tab_v);

    int nthr = Cdim * (HWPIX / 4);
    lepe_fused<<<(nthr + 255) / 256, 256>>>(ah, av, lepe_h_w, lepe_h_b,
                                            lepe_v_w, lepe_v_b, phi, plo);

    dim3 gp(NPIX / 128, M_PROJ / 64, 1);
    gemm_mma<<<gp, 256, G_TOTAL_BYTES>>>(pwh, pwl, pwh, pwl, phi, plo,
                                         proj_b, proj_b, out, out);
}

// round 14
// speedup vs baseline: 1.7831x; 1.1217x over previous
#include <cuda_runtime.h>
#include <cuda_bf16.h>
#include <cuda_fp16.h>
#include <cstdint>
#include <math.h>

#define Cdim   192
#define NHEAD  8
#define HDIM   24
#define HWPIX  12544          // 112*112
#define LTOK   784            // 7*112
#define GK     192            // gemm K
#define NPIX   12544
#define M_QKV  576
#define M_PROJ 192
#define SCALE_F 0.20412414523193154f  // 24^-0.5
#define LOG2E   1.44269504088896340736f

typedef unsigned short ushort_t;

// ---------------- scratch (device globals; no allocation) ----------------
__device__ float g_qkv_h[M_QKV * HWPIX];
__device__ float g_qkv_v[M_QKV * HWPIX];
__device__ float g_att_h[Cdim * HWPIX];
__device__ float g_att_v[Cdim * HWPIX];
__device__ ushort_t g_xhi[GK * NPIX];           // fp16
__device__ ushort_t g_phi[GK * NPIX];           // bf16 (lepe out)
__device__ ushort_t g_plo[GK * NPIX];
__device__ ushort_t g_whh[M_QKV * GK];          // fp16 hi
__device__ ushort_t g_whl[M_QKV * GK];          // fp16 lo
__device__ ushort_t g_wvh[M_QKV * GK];
__device__ ushort_t g_wvl[M_QKV * GK];
__device__ ushort_t g_pwh[M_PROJ * GK];         // bf16 hi
__device__ ushort_t g_pwl[M_PROJ * GK];

// ---------------- helpers ----------------
__device__ __forceinline__ uint32_t bfp(float lo_el, float hi_el) {
    uint32_t r;
    asm("cvt.rn.bf16x2.f32 %0, %1, %2;" : "=r"(r) : "f"(hi_el), "f"(lo_el));
    return r;
}
__device__ __forceinline__ float bflo(uint32_t p) { return __uint_as_float(p << 16); }
__device__ __forceinline__ float bfhi(uint32_t p) { return __uint_as_float(p & 0xFFFF0000u); }

__device__ __forceinline__ uint32_t s2u(const void* p) {
    uint32_t a;
    asm("{ .reg .u64 t; cvta.to.shared.u64 t, %1; cvt.u32.u64 %0, t; }" : "=r"(a) : "l"(p));
    return a;
}
__device__ __forceinline__ float ex2f(float x) {
    float r;
    asm("ex2.approx.f32 %0, %1;" : "=f"(r) : "f"(x));
    return r;
}
__device__ __forceinline__ uint32_t hfp(float lo_el, float hi_el) {
    uint32_t r;
    asm("cvt.rn.f16x2.f32 %0, %1, %2;" : "=r"(r) : "f"(hi_el), "f"(lo_el));
    return r;
}

__device__ __forceinline__ void mma_bf16(float* c,
    uint32_t a0, uint32_t a1, uint32_t a2, uint32_t a3,
    uint32_t b0, uint32_t b1)
{
    asm volatile("mma.sync.aligned.m16n8k16.row.col.f32.bf16.bf16.f32 "
        "{%0,%1,%2,%3}, {%4,%5,%6,%7}, {%8,%9}, {%0,%1,%2,%3};"
        : "+f"(c[0]), "+f"(c[1]), "+f"(c[2]), "+f"(c[3])
        : "r"(a0), "r"(a1), "r"(a2), "r"(a3), "r"(b0), "r"(b1));
}
__device__ __forceinline__ void mma_f16(float* c,
    uint32_t a0, uint32_t a1, uint32_t a2, uint32_t a3,
    uint32_t b0, uint32_t b1)
{
    asm volatile("mma.sync.aligned.m16n8k16.row.col.f32.f16.f16.f32 "
        "{%0,%1,%2,%3}, {%4,%5,%6,%7}, {%8,%9}, {%0,%1,%2,%3};"
        : "+f"(c[0]), "+f"(c[1]), "+f"(c[2]), "+f"(c[3])
        : "r"(a0), "r"(a1), "r"(a2), "r"(a3), "r"(b0), "r"(b1));
}
__device__ __forceinline__ void mma_f16_k8(float* c,
    uint32_t a0, uint32_t a1, uint32_t b0)
{
    asm volatile("mma.sync.aligned.m16n8k8.row.col.f32.f16.f16.f32 "
        "{%0,%1,%2,%3}, {%4,%5}, {%6}, {%0,%1,%2,%3};"
        : "+f"(c[0]), "+f"(c[1]), "+f"(c[2]), "+f"(c[3])
        : "r"(a0), "r"(a1), "r"(b0));
}

__device__ __forceinline__ void ldsm4t(uint32_t& r0, uint32_t& r1,
                                       uint32_t& r2, uint32_t& r3, uint32_t a)
{
    asm volatile("ldmatrix.sync.aligned.m8n8.x4.trans.shared.b16 {%0,%1,%2,%3}, [%4];"
        : "=r"(r0), "=r"(r1), "=r"(r2), "=r"(r3) : "r"(a));
}
__device__ __forceinline__ void ldsm4(uint32_t& r0, uint32_t& r1,
                                      uint32_t& r2, uint32_t& r3, uint32_t a)
{
    asm volatile("ldmatrix.sync.aligned.m8n8.x4.shared.b16 {%0,%1,%2,%3}, [%4];"
        : "=r"(r0), "=r"(r1), "=r"(r2), "=r"(r3) : "r"(a));
}
__device__ __forceinline__ void ldsm2(uint32_t& r0, uint32_t& r1, uint32_t a)
{
    asm volatile("ldmatrix.sync.aligned.m8n8.x2.shared.b16 {%0,%1}, [%2];"
        : "=r"(r0), "=r"(r1) : "r"(a));
}

#define CPA16(dst, src) asm volatile("cp.async.ca.shared.global [%0], [%1], 16;" :: "r"(dst), "l"(src) : "memory")
#define CPC()  asm volatile("cp.async.commit_group;" ::: "memory")
#define CPW1() asm volatile("cp.async.wait_group 1;" ::: "memory")
#define CPW0() asm volatile("cp.async.wait_group 0;" ::: "memory")

// ---------------- combined split (one launch) ----------------
// seg0: x -> fp16 hi only; seg1/2: qkv weights -> fp16 hi/lo; seg3: proj w -> bf16 hi/lo
__global__ __launch_bounds__(256) void split_all(
    const float4* __restrict__ sx, uint2* __restrict__ xh, int n0,
    const float4* __restrict__ w1, uint2* __restrict__ h1p, uint2* __restrict__ l1p, int n1,
    const float4* __restrict__ w2, uint2* __restrict__ h2p, uint2* __restrict__ l2p, int n2,
    const float4* __restrict__ w3, uint2* __restrict__ h3p, uint2* __restrict__ l3p, int n3)
{
    int i = blockIdx.x * blockDim.x + threadIdx.x;
    int j = i;
    if (j < n0) {
        float4 v = sx[j];
        xh[j] = make_uint2(hfp(v.x, v.y), hfp(v.z, v.w));
        return;
    }
    j -= n0;
    if (j < n1 + n2) {
        const float4* src; uint2 *hd, *ld;
        if (j < n1) { src = w1; hd = h1p; ld = l1p; }
        else { j -= n1; src = w2; hd = h2p; ld = l2p; }
        float4 v = src[j];
        uint32_t h0 = hfp(v.x, v.y);
        uint32_t h1 = hfp(v.z, v.w);
        float r0 = v.x - __half2float(__ushort_as_half((ushort_t)h0));
        float r1 = v.y - __half2float(__ushort_as_half((ushort_t)(h0 >> 16)));
        float r2 = v.z - __half2float(__ushort_as_half((ushort_t)h1));
        float r3 = v.w - __half2float(__ushort_as_half((ushort_t)(h1 >> 16)));
        hd[j] = make_uint2(h0, h1);
        ld[j] = make_uint2(hfp(r0, r1), hfp(r2, r3));
        return;
    }
    j -= n1 + n2;
    if (j < n3) {
        float4 v = w3[j];
        uint32_t h0 = bfp(v.x, v.y);
        uint32_t h1 = bfp(v.z, v.w);
        uint32_t l0 = bfp(v.x - bflo(h0), v.y - bfhi(h0));
        uint32_t l1 = bfp(v.z - bflo(h1), v.w - bfhi(h1));
        h3p[j] = make_uint2(h0, h1);
        l3p[j] = make_uint2(l0, l1);
    }
}

// ---------------- QKV GEMM: fp16 2-term (Whi+Wlo)·Xhi, B hi-only ----------------
#define Q_SBH 0
#define Q_SAH 8704
#define Q_SAL 13824
#define Q_BSTR 136
#define Q_BBUF 4352
#define Q_ASTR 40
#define Q_ABUF 2560
#define Q_TOTAL_BYTES 37888

__global__ __launch_bounds__(256) void gemm_qkv(
    const ushort_t* __restrict__ Ah0, const ushort_t* __restrict__ Al0,
    const ushort_t* __restrict__ Ah1, const ushort_t* __restrict__ Al1,
    const ushort_t* __restrict__ Bhi,
    const float* __restrict__ bias0, const float* __restrict__ bias1,
    float* __restrict__ C0, float* __restrict__ C1)
{
    extern __shared__ ushort_t gsm[];
    const ushort_t* __restrict__ Ahi = blockIdx.z ? Ah1 : Ah0;
    const ushort_t* __restrict__ Alo = blockIdx.z ? Al1 : Al0;
    const float* __restrict__ bias = blockIdx.z ? bias1 : bias0;
    float* __restrict__ C = blockIdx.z ? C1 : C0;

    const int tid = threadIdx.x;
    const int bn = blockIdx.x * 128, bm = blockIdx.y * 64;
    const int wid = tid >> 5, lane = tid & 31;
    const int wm = wid & 3, wn = wid >> 2;
    const int g = lane >> 2, q = lane & 3;
    const int wc = wn * 64;
    const int row0 = bm + wm * 16 + g;
    const int row1 = row0 + 8;

    float acc[8][4];
    #pragma unroll
    for (int i = 0; i < 8; i++)
        #pragma unroll
        for (int j = 0; j < 4; j++) acc[i][j] = 0.f;

    const int rB = tid >> 3;
    const int cB = (tid & 7) * 8;
    const int rA = tid >> 2;
    const int cA = (tid & 3) * 8;

    uint32_t smb = s2u(gsm);
    uint32_t dstBh[2], dstAh[2], dstAl[2];
    #pragma unroll
    for (int b = 0; b < 2; b++) {
        dstBh[b] = smb + (uint32_t)((Q_SBH + b * Q_BBUF + rB * Q_BSTR + cB) * 2);
        dstAh[b] = smb + (uint32_t)((Q_SAH + b * Q_ABUF + rA * Q_ASTR + cA) * 2);
        dstAl[b] = smb + (uint32_t)((Q_SAL + b * Q_ABUF + rA * Q_ASTR + cA) * 2);
    }

    const int lm = lane >> 3, lr = lane & 7;
    const int lkrow = (lm & 1) * 8 + lr;
    const int lncol = wc + (lm >> 1) * 8;
    const int arow = wm * 16 + (lm & 1) * 8 + lr;
    const int acol = (lane >> 4) * 8;
    uint32_t sbh_base[2], sah_base[2], sal_base[2];
    #pragma unroll
    for (int b = 0; b < 2; b++) {
        sbh_base[b] = smb + (uint32_t)((Q_SBH + b * Q_BBUF + lkrow * Q_BSTR + lncol) * 2);
        sah_base[b] = smb + (uint32_t)((Q_SAH + b * Q_ABUF + arow * Q_ASTR + acol) * 2);
        sal_base[b] = smb + (uint32_t)((Q_SAL + b * Q_ABUF + arow * Q_ASTR + acol) * 2);
    }

    {
        const ushort_t* bh = &Bhi[rB * NPIX + bn + cB];
        CPA16(dstBh[0], bh); CPA16(dstBh[0] + 128, bh + 64);
        CPA16(dstAh[0], &Ahi[(bm + rA) * GK + cA]);
        CPA16(dstAl[0], &Alo[(bm + rA) * GK + cA]);
        CPC();
    }

    #pragma unroll
    for (int ki = 0; ki < 6; ki++) {
        if (ki < 5) {
            const int kn = (ki + 1) * 32;
            const int bf = (ki + 1) & 1;
            const ushort_t* bh = &Bhi[(kn + rB) * NPIX + bn + cB];
            CPA16(dstBh[bf], bh); CPA16(dstBh[bf] + 128, bh + 64);
            CPA16(dstAh[bf], &Ahi[(bm + rA) * GK + kn + cA]);
            CPA16(dstAl[bf], &Alo[(bm + rA) * GK + kn + cA]);
            CPC();
            CPW1();
        } else {
            CPW0();
        }
        __syncthreads();

        const int buf = ki & 1;
        #pragma unroll
        for (int hh = 0; hh < 2; hh++) {
            uint32_t ah[4], al[4];
            ldsm4(ah[0], ah[1], ah[2], ah[3], sah_base[buf] + hh * 32);
            ldsm4(al[0], al[1], al[2], al[3], sal_base[buf] + hh * 32);

            const uint32_t hoff = (uint32_t)(hh * 16 * Q_BSTR) * 2;
            #pragma unroll
            for (int j = 0; j < 4; j++) {
                uint32_t off = hoff + (uint32_t)(j * 16) * 2;
                uint32_t bh0, bh1, bh2, bh3;
                ldsm4t(bh0, bh1, bh2, bh3, sbh_base[buf] + off);
                float* c0 = acc[2 * j];
                float* c1 = acc[2 * j + 1];
                mma_f16(c0, ah[0], ah[1], ah[2], ah[3], bh0, bh1);
                mma_f16(c0, al[0], al[1], al[2], al[3], bh0, bh1);
                mma_f16(c1, ah[0], ah[1], ah[2], ah[3], bh2, bh3);
                mma_f16(c1, al[0], al[1], al[2], al[3], bh2, bh3);
            }
        }
        __syncthreads();
    }

    const float b0 = bias[row0], b1 = bias[row1];
    #pragma unroll
    for (int nf = 0; nf < 8; nf++) {
        int col = bn + wc + nf * 8 + 2 * q;
        *(float2*)&C[row0 * NPIX + col] = make_float2(acc[nf][0] + b0, acc[nf][1] + b0);
        *(float2*)&C[row1 * NPIX + col] = make_float2(acc[nf][2] + b1, acc[nf][3] + b1);
    }
}

// ---------------- proj GEMM: bf16 3-term (unchanged math) ----------------
#define G_SBH 0
#define G_SBL 8704
#define G_SAH 17408
#define G_SAL 22528
#define G_BSTR 136
#define G_BBUF 4352
#define G_ASTR 40
#define G_ABUF 2560
#define G_TOTAL_BYTES 55296

__global__ __launch_bounds__(256) void gemm_mma(
    const ushort_t* __restrict__ Ahi, const ushort_t* __restrict__ Alo,
    const ushort_t* __restrict__ Bhi, const ushort_t* __restrict__ Blo,
    const float* __restrict__ bias, float* __restrict__ C)
{
    extern __shared__ ushort_t gsm[];
    const int tid = threadIdx.x;
    const int bn = blockIdx.x * 128, bm = blockIdx.y * 64;
    const int wid = tid >> 5, lane = tid & 31;
    const int wm = wid & 3, wn = wid >> 2;
    const int g = lane >> 2, q = lane & 3;
    const int wc = wn * 64;
    const int row0 = bm + wm * 16 + g;
    const int row1 = row0 + 8;

    float acc[8][4];
    #pragma unroll
    for (int i = 0; i < 8; i++)
        #pragma unroll
        for (int j = 0; j < 4; j++) acc[i][j] = 0.f;

    const int rB = tid >> 3;
    const int cB = (tid & 7) * 8;
    const int rA = tid >> 2;
    const int cA = (tid & 3) * 8;

    uint32_t smb = s2u(gsm);
    uint32_t dstBh[2], dstBl[2], dstAh[2], dstAl[2];
    #pragma unroll
    for (int b = 0; b < 2; b++) {
        dstBh[b] = smb + (uint32_t)((G_SBH + b * G_BBUF + rB * G_BSTR + cB) * 2);
        dstBl[b] = smb + (uint32_t)((G_SBL + b * G_BBUF + rB * G_BSTR + cB) * 2);
        dstAh[b] = smb + (uint32_t)((G_SAH + b * G_ABUF + rA * G_ASTR + cA) * 2);
        dstAl[b] = smb + (uint32_t)((G_SAL + b * G_ABUF + rA * G_ASTR + cA) * 2);
    }

    const int lm = lane >> 3, lr = lane & 7;
    const int lkrow = (lm & 1) * 8 + lr;
    const int lncol = wc + (lm >> 1) * 8;
    const int arow = wm * 16 + (lm & 1) * 8 + lr;
    const int acol = (lane >> 4) * 8;
    uint32_t sbh_base[2], sbl_base[2], sah_base[2], sal_base[2];
    #pragma unroll
    for (int b = 0; b < 2; b++) {
        sbh_base[b] = smb + (uint32_t)((G_SBH + b * G_BBUF + lkrow * G_BSTR + lncol) * 2);
        sbl_base[b] = smb + (uint32_t)((G_SBL + b * G_BBUF + lkrow * G_BSTR + lncol) * 2);
        sah_base[b] = smb + (uint32_t)((G_SAH + b * G_ABUF + arow * G_ASTR + acol) * 2);
        sal_base[b] = smb + (uint32_t)((G_SAL + b * G_ABUF + arow * G_ASTR + acol) * 2);
    }

    {
        const ushort_t* bh = &Bhi[rB * NPIX + bn + cB];
        const ushort_t* bl = &Blo[rB * NPIX + bn + cB];
        CPA16(dstBh[0], bh); CPA16(dstBh[0] + 128, bh + 64);
        CPA16(dstBl[0], bl); CPA16(dstBl[0] + 128, bl + 64);
        CPA16(dstAh[0], &Ahi[(bm + rA) * GK + cA]);
        CPA16(dstAl[0], &Alo[(bm + rA) * GK + cA]);
        CPC();
    }

    #pragma unroll
    for (int ki = 0; ki < 6; ki++) {
        if (ki < 5) {
            const int kn = (ki + 1) * 32;
            const int bf = (ki + 1) & 1;
            const ushort_t* bh = &Bhi[(kn + rB) * NPIX + bn + cB];
            const ushort_t* bl = &Blo[(kn + rB) * NPIX + bn + cB];
            CPA16(dstBh[bf], bh); CPA16(dstBh[bf] + 128, bh + 64);
            CPA16(dstBl[bf], bl); CPA16(dstBl[bf] + 128, bl + 64);
            CPA16(dstAh[bf], &Ahi[(bm + rA) * GK + kn + cA]);
            CPA16(dstAl[bf], &Alo[(bm + rA) * GK + kn + cA]);
            CPC();
            CPW1();
        } else {
            CPW0();
        }
        __syncthreads();

        const int buf = ki & 1;
        #pragma unroll
        for (int hh = 0; hh < 2; hh++) {
            uint32_t ah[4], al[4];
            ldsm4(ah[0], ah[1], ah[2], ah[3], sah_base[buf] + hh * 32);
            ldsm4(al[0], al[1], al[2], al[3], sal_base[buf] + hh * 32);

            const uint32_t hoff = (uint32_t)(hh * 16 * G_BSTR) * 2;
            #pragma unroll
            for (int j = 0; j < 4; j++) {
                uint32_t off = hoff + (uint32_t)(j * 16) * 2;
                uint32_t bh0, bh1, bh2, bh3, bl0, bl1, bl2, bl3;
                ldsm4t(bh0, bh1, bh2, bh3, sbh_base[buf] + off);
                ldsm4t(bl0, bl1, bl2, bl3, sbl_base[buf] + off);
                float* c0 = acc[2 * j];
                float* c1 = acc[2 * j + 1];
                mma_bf16(c0, ah[0], ah[1], ah[2], ah[3], bh0, bh1);
                mma_bf16(c0, al[0], al[1], al[2], al[3], bh0, bh1);
                mma_bf16(c0, ah[0], ah[1], ah[2], ah[3], bl0, bl1);
                mma_bf16(c1, ah[0], ah[1], ah[2], ah[3], bh2, bh3);
                mma_bf16(c1, al[0], al[1], al[2], al[3], bh2, bh3);
                mma_bf16(c1, ah[0], ah[1], ah[2], ah[3], bl2, bl3);
            }
        }
        __syncthreads();
    }

    const float b0 = bias[row0], b1 = bias[row1];
    #pragma unroll
    for (int nf = 0; nf < 8; nf++) {
        int col = bn + wc + nf * 8 + 2 * q;
        *(float2*)&C[row0 * NPIX + col] = make_float2(acc[nf][0] + b0, acc[nf][1] + b0);
        *(float2*)&C[row1 * NPIX + col] = make_float2(acc[nf][2] + b1, acc[nf][3] + b1);
    }
}

// ============================================================================
// fp16 flash attention — software-pipelined S ahead of softmax/PV.
// 384 threads, 2 CTAs/SM.
// ============================================================================
#define KSTR 40
#define VSTRF 792
#define NW    12
#define NTHR  384

#define A_SKH 0
#define A_SVH (A_SKH + LTOK * KSTR * 2)          // 62720
#define A_SB  (A_SVH + HDIM * VSTRF * 2)         // 100736
#define A_TOTAL (A_SB + 256)

__global__ __launch_bounds__(NTHR, 2) void attn_mma(
    const float* __restrict__ tab_h, const float* __restrict__ tab_v)
{
    extern __shared__ char asm_[];
    ushort_t* sKhi = (ushort_t*)(asm_ + A_SKH);
    ushort_t* sVhi = (ushort_t*)(asm_ + A_SVH);
    float* sb = (float*)(asm_ + A_SB);

    const int tid = threadIdx.x;
    const int w = blockIdx.x, h = blockIdx.y, br = blockIdx.z;
    const float* __restrict__ qkv = br ? g_qkv_v : g_qkv_h;
    float* __restrict__ outp = br ? g_att_v : g_att_h;
    const float* __restrict__ tab = br ? tab_v : tab_h;

    if (tid < 49) {
        int r1 = tid / 7, r2 = tid % 7, off = r1 - r2 + 6;
        float bv = br ? tab[(6 * 13 + off) * NHEAD + h]
                      : tab[(off * 13 + 6) * NHEAD + h];
        sb[tid] = bv * LOG2E;
    }
    for (int i = tid; i < LTOK * 8; i += NTHR) {
        int k = i >> 3, d = 24 + (i & 7);
        sKhi[k * KSTR + d] = 0;
    }
    if (tid < HDIM * 8) {
        int d = tid >> 3, k = LTOK + (tid & 7);
        sVhi[d * VSTRF + k] = 0;
    }
    for (int idx = tid; idx < LTOK * HDIM; idx += NTHR) {
        int d = idx / LTOK, k = idx - d * LTOK;
        int pix = br ? ((k / 7) * 112 + w * 7 + (k % 7)) : (w * LTOK + k);
        float kv = qkv[(192 + h * HDIM + d) * HWPIX + pix];
        float vv = qkv[(384 + h * HDIM + d) * HWPIX + pix];
        sKhi[k * KSTR + d] = __half_as_ushort(__float2half_rn(kv));
        sVhi[d * VSTRF + k] = __half_as_ushort(__float2half_rn(vv));
    }
    __syncthreads();

    const int warp = tid >> 5, lane = tid & 31;
    const int g = lane >> 2, q = lane & 3;
    const int d0 = 2 * q;
    const int lr = lane & 7;

    const uint32_t kln = (uint32_t)((lr * KSTR + (lane >> 3) * 8) * 2);
    const uint32_t skh_b = s2u(sKhi) + kln;
    const int vko = ((lane >> 3) & 1) * 8;
    const int vdh = ((lane >> 4) & 1) * 8 + lr;
    const uint32_t sv4 = s2u(sVhi) + (uint32_t)((vdh * VSTRF + vko) * 2);
    const uint32_t sv2a = s2u(sVhi) + (uint32_t)(((16 + lr) * VSTRF + vko) * 2);

    const float qscale = SCALE_F * LOG2E;

    for (int mt = warp; mt < 49; mt += NW) {
        const int r0 = mt * 16 + g, r1 = r0 + 8;
        const int pix0 = br ? ((r0 / 7) * 112 + w * 7 + (r0 % 7)) : (w * LTOK + r0);
        const int pix1 = br ? ((r1 / 7) * 112 + w * 7 + (r1 % 7)) : (w * LTOK + r1);
        const int bro0 = (br ? (r0 % 7) : (r0 / 112)) * 7;
        const int bro1 = (br ? (r1 % 7) : (r1 / 112)) * 7;

        uint32_t qh[6];
        #pragma unroll
        for (int p = 0; p < 3; p++) {
            int d = d0 + 8 * p;
            float a0v = qkv[(h * HDIM + d)     * HWPIX + pix0] * qscale;
            float a1v = qkv[(h * HDIM + d + 1) * HWPIX + pix0] * qscale;
            float b0v = qkv[(h * HDIM + d)     * HWPIX + pix1] * qscale;
            float b1v = qkv[(h * HDIM + d + 1) * HWPIX + pix1] * qscale;
            qh[2 * p]     = hfp(a0v, a1v);
            qh[2 * p + 1] = hfp(b0v, b1v);
        }

        float o[3][4];
        #pragma unroll
        for (int nd = 0; nd < 3; nd++)
            #pragma unroll
            for (int i = 0; i < 4; i++) o[nd][i] = 0.f;
        float rs0 = 0.f, rs1 = 0.f;

        // prologue: S for step 0 (kt=0, nt0=0, nt1=1)
        float sA[4] = {0.f, 0.f, 0.f, 0.f};
        float sB[4] = {0.f, 0.f, 0.f, 0.f};
        {
            uint32_t h0, h1, h2, h3;
            ldsm4(h0, h1, h2, h3, skh_b);
            mma_f16(sA, qh[0], qh[1], qh[2], qh[3], h0, h1);
            mma_f16_k8(sA, qh[4], qh[5], h2);
            ldsm4(h0, h1, h2, h3, skh_b + (uint32_t)(8 * KSTR * 2));
            mma_f16(sB, qh[0], qh[1], qh[2], qh[3], h0, h1);
            mma_f16_k8(sB, qh[4], qh[5], h2);
        }

        #pragma unroll 4
        for (int s = 0; s < 56; s++) {
            const int kt = s >> 2, ks = s & 3;
            const int kbase = kt * 56;
            const int nt0 = 2 * ks;
            const bool has1 = (ks != 3);

            // prefetch S for step s+1 (overlaps with softmax/PV below)
            float nA[4] = {0.f, 0.f, 0.f, 0.f};
            float nB[4] = {0.f, 0.f, 0.f, 0.f};
            if (s < 55) {
                const int s1 = s + 1;
                const int kb1 = (s1 >> 2) * 56;
                const int ns0 = 2 * (s1 & 3);
                uint32_t ko = (uint32_t)((kb1 + ns0 * 8) * KSTR * 2);
                uint32_t h0, h1, h2, h3;
                ldsm4(h0, h1, h2, h3, skh_b + ko);
                mma_f16(nA, qh[0], qh[1], qh[2], qh[3], h0, h1);
                mma_f16_k8(nA, qh[4], qh[5], h2);
                if ((s1 & 3) != 3) {
                    ko = (uint32_t)((kb1 + (ns0 + 1) * 8) * KSTR * 2);
                    ldsm4(h0, h1, h2, h3, skh_b + ko);
                    mma_f16(nB, qh[0], qh[1], qh[2], qh[3], h0, h1);
                    mma_f16_k8(nB, qh[4], qh[5], h2);
                }
            }

            // softmax + PV on current S
            float eA0, eA1, eA2, eA3, eB0 = 0.f, eB1 = 0.f, eB2 = 0.f, eB3 = 0.f;
            if (!br) {
                float bh0 = sb[bro0 + (kt >> 1)];
                float bh1 = sb[bro1 + (kt >> 1)];
                eA0 = ex2f(sA[0] + bh0); eA1 = ex2f(sA[1] + bh0);
                eA2 = ex2f(sA[2] + bh1); eA3 = ex2f(sA[3] + bh1);
                if (has1) {
                    eB0 = ex2f(sB[0] + bh0); eB1 = ex2f(sB[1] + bh0);
                    eB2 = ex2f(sB[2] + bh1); eB3 = ex2f(sB[3] + bh1);
                }
            } else {
                int i0 = (nt0 + d0) % 7;
                int i1 = i0 + 1; if (i1 == 7) i1 = 0;
                int j1 = i1 + 1; if (j1 == 7) j1 = 0;
                eA0 = ex2f(sA[0] + sb[bro0 + i0]); eA1 = ex2f(sA[1] + sb[bro0 + i1]);
                eA2 = ex2f(sA[2] + sb[bro1 + i0]); eA3 = ex2f(sA[3] + sb[bro1 + i1]);
                if (has1) {
                    eB0 = ex2f(sB[0] + sb[bro0 + i1]); eB1 = ex2f(sB[1] + sb[bro0 + j1]);
                    eB2 = ex2f(sB[2] + sb[bro1 + i1]); eB3 = ex2f(sB[3] + sb[bro1 + j1]);
                }
            }
            rs0 += eA0 + eA1 + eB0 + eB1;
            rs1 += eA2 + eA3 + eB2 + eB3;

            uint32_t pa0 = hfp(eA0, eA1), pa1 = hfp(eA2, eA3);
            uint32_t pa2 = has1 ? hfp(eB0, eB1) : 0u;
            uint32_t pa3 = has1 ? hfp(eB2, eB3) : 0u;

            {
                uint32_t vo = (uint32_t)((kbase + ks * 16) * 2);
                uint32_t va0, va1, va2, va3, vx0, vx1;
                ldsm4(va0, va1, va2, va3, sv4 + vo);
                ldsm2(vx0, vx1, sv2a + vo);
                mma_f16(o[0], pa0, pa1, pa2, pa3, va0, va1);
                mma_f16(o[1], pa0, pa1, pa2, pa3, va2, va3);
                mma_f16(o[2], pa0, pa1, pa2, pa3, vx0, vx1);
            }

            #pragma unroll
            for (int i = 0; i < 4; i++) { sA[i] = nA[i]; sB[i] = nB[i]; }
        }

        float a0 = rs0, a1 = rs1;
        a0 += __shfl_xor_sync(0xFFFFFFFFu, a0, 1);
        a0 += __shfl_xor_sync(0xFFFFFFFFu, a0, 2);
        a1 += __shfl_xor_sync(0xFFFFFFFFu, a1, 1);
        a1 += __shfl_xor_sync(0xFFFFFFFFu, a1, 2);
        float inv0 = 1.f / a0, inv1 = 1.f / a1;
        #pragma unroll
        for (int nd = 0; nd < 3; nd++) {
            int d = nd * 8 + d0;
            outp[(h * HDIM + d)     * HWPIX + pix0] = o[nd][0] * inv0;
            outp[(h * HDIM + d + 1) * HWPIX + pix0] = o[nd][1] * inv0;
            outp[(h * HDIM + d)     * HWPIX + pix1] = o[nd][2] * inv1;
            outp[(h * HDIM + d + 1) * HWPIX + pix1] = o[nd][3] * inv1;
        }
    }
}

// ---------------- fused dual LePE -> 0.5*(h+v) -> bf16 hi/lo planes ----------------
__global__ __launch_bounds__(256) void lepe_fused(
    const float* __restrict__ attH, const float* __restrict__ attV,
    const float* __restrict__ wH, const float* __restrict__ bH,
    const float* __restrict__ wV, const float* __restrict__ bV,
    ushort_t* __restrict__ phi, ushort_t* __restrict__ plo)
{
    int t = blockIdx.x * blockDim.x + threadIdx.x;
    if (t >= Cdim * (HWPIX / 4)) return;
    int c = t / (HWPIX / 4);
    int r = t % (HWPIX / 4);
    int y = r / 28, x4 = (r % 28) * 4;
    const float* baseH = attH + c * HWPIX;
    const float* baseV = attV + c * HWPIX;

    float wvh[9], wvv[9];
    #pragma unroll
    for (int i = 0; i < 9; i++) { wvh[i] = wH[c * 9 + i]; wvv[i] = wV[c * 9 + i]; }
    float ah0 = bH[c], ah1 = ah0, ah2 = ah0, ah3 = ah0;
    float av0 = bV[c], av1 = av0, av2 = av0, av3 = av0;

    #pragma unroll
    for (int ky = 0; ky < 3; ky++) {
        int yy = y + ky - 1;
        if (yy < 0 || yy >= 112) continue;
        const float* rpH = baseH + yy * 112 + x4;
        const float* rpV = baseV + yy * 112 + x4;
        float4 mH = *(const float4*)rpH;
        float4 mV = *(const float4*)rpV;
        float lfH = (x4 > 0)   ? rpH[-1] : 0.f;
        float rtH = (x4 < 108) ? rpH[4]  : 0.f;
        float lfV = (x4 > 0)   ? rpV[-1] : 0.f;
        float rtV = (x4 < 108) ? rpV[4]  : 0.f;
        float h0 = wvh[ky*3], h1 = wvh[ky*3+1], h2 = wvh[ky*3+2];
        float v0 = wvv[ky*3], v1 = wvv[ky*3+1], v2 = wvv[ky*3+2];
        ah0 += h0 * lfH  + h1 * mH.x + h2 * mH.y;
        ah1 += h0 * mH.x + h1 * mH.y + h2 * mH.z;
        ah2 += h0 * mH.y + h1 * mH.z + h2 * mH.w;
        ah3 += h0 * mH.z + h1 * mH.w + h2 * rtH;
        av0 += v0 * lfV  + v1 * mV.x + v2 * mV.y;
        av1 += v0 * mV.x + v1 * mV.y + v2 * mV.z;
        av2 += v0 * mV.y + v1 * mV.z + v2 * mV.w;
        av3 += v0 * mV.z + v1 * mV.w + v2 * rtV;
    }

    float4 inH = *(const float4*)(baseH + y * 112 + x4);
    float4 inV = *(const float4*)(baseV + y * 112 + x4);
    const float RS2 = 0.70710678118654752f;
    float oh0 = inH.x + 0.5f * ah0 * (1.f + erff(ah0 * RS2));
    float oh1 = inH.y + 0.5f * ah1 * (1.f + erff(ah1 * RS2));
    float oh2 = inH.z + 0.5f * ah2 * (1.f + erff(ah2 * RS2));
    float oh3 = inH.w + 0.5f * ah3 * (1.f + erff(ah3 * RS2));
    float ov0 = inV.x + 0.5f * av0 * (1.f + erff(av0 * RS2));
    float ov1 = inV.y + 0.5f * av1 * (1.f + erff(av1 * RS2));
    float ov2 = inV.z + 0.5f * av2 * (1.f + erff(av2 * RS2));
    float ov3 = inV.w + 0.5f * av3 * (1.f + erff(av3 * RS2));

    float p0 = 0.5f * (oh0 + ov0);
    float p1 = 0.5f * (oh1 + ov1);
    float p2 = 0.5f * (oh2 + ov2);
    float p3 = 0.5f * (oh3 + ov3);

    uint32_t h0w = bfp(p0, p1), h1w = bfp(p2, p3);
    uint32_t l0w = bfp(p0 - bflo(h0w), p1 - bfhi(h0w));
    uint32_t l1w = bfp(p2 - bflo(h1w), p3 - bfhi(h1w));
    int idx = c * HWPIX + y * 112 + x4;
    *(uint2*)&phi[idx] = make_uint2(h0w, h1w);
    *(uint2*)&plo[idx] = make_uint2(l0w, l1w);
}

// ---------------- launch ----------------
extern "C" void kernel_launch(void* const* d_in, const int* in_sizes, int n_in,
                              void* d_out, int out_size)
{
    const float* x        = (const float*)d_in[0];
    const float* qkv_h_w  = (const float*)d_in[1];
    const float* qkv_h_b  = (const float*)d_in[2];
    const float* qkv_v_w  = (const float*)d_in[3];
    const float* qkv_v_b  = (const float*)d_in[4];
    const float* proj_w   = (const float*)d_in[5];
    const float* proj_b   = (const float*)d_in[6];
    const float* lepe_h_w = (const float*)d_in[7];
    const float* lepe_h_b = (const float*)d_in[8];
    const float* lepe_v_w = (const float*)d_in[9];
    const float* lepe_v_b = (const float*)d_in[10];
    const float* tab_h    = (const float*)d_in[11];
    const float* tab_v    = (const float*)d_in[12];
    float* out = (float*)d_out;

    float *qh, *qv, *ah, *av;
    ushort_t *xhi, *phi, *plo, *whh, *whl, *wvh, *wvl, *pwh, *pwl;
    cudaGetSymbolAddress((void**)&qh, g_qkv_h);
    cudaGetSymbolAddress((void**)&qv, g_qkv_v);
    cudaGetSymbolAddress((void**)&ah, g_att_h);
    cudaGetSymbolAddress((void**)&av, g_att_v);
    cudaGetSymbolAddress((void**)&xhi, g_xhi);
    cudaGetSymbolAddress((void**)&phi, g_phi);
    cudaGetSymbolAddress((void**)&plo, g_plo);
    cudaGetSymbolAddress((void**)&whh, g_whh);
    cudaGetSymbolAddress((void**)&whl, g_whl);
    cudaGetSymbolAddress((void**)&wvh, g_wvh);
    cudaGetSymbolAddress((void**)&wvl, g_wvl);
    cudaGetSymbolAddress((void**)&pwh, g_pwh);
    cudaGetSymbolAddress((void**)&pwl, g_pwl);

    int nx4 = GK * NPIX / 4;
    int nw4 = M_QKV * GK / 4;
    int np4 = M_PROJ * GK / 4;
    int ntot = nx4 + nw4 * 2 + np4;
    split_all<<<(ntot + 255) / 256, 256>>>(
        (const float4*)x,       (uint2*)xhi, nx4,
        (const float4*)qkv_h_w, (uint2*)whh, (uint2*)whl, nw4,
        (const float4*)qkv_v_w, (uint2*)wvh, (uint2*)wvl, nw4,
        (const float4*)proj_w,  (uint2*)pwh, (uint2*)pwl, np4);

    // QKV GEMMs (fp16 2-term, B hi-only)
    cudaFuncSetAttribute(gemm_qkv,
                         cudaFuncAttributeMaxDynamicSharedMemorySize, Q_TOTAL_BYTES);
    dim3 gq(NPIX / 128, M_QKV / 64, 2);
    gemm_qkv<<<gq, 256, Q_TOTAL_BYTES>>>(whh, whl, wvh, wvl, xhi,
                                         qkv_h_b, qkv_v_b, qh, qv);

    // attention (pipelined)
    cudaFuncSetAttribute(attn_mma,
                         cudaFuncAttributeMaxDynamicSharedMemorySize, A_TOTAL);
    dim3 ga(16, NHEAD, 2);
    attn_mma<<<ga, NTHR, A_TOTAL>>>(tab_h, tab_v);

    int nthr = Cdim * (HWPIX / 4);
    lepe_fused<<<(nthr + 255) / 256, 256>>>(ah, av, lepe_h_w, lepe_h_b,
                                            lepe_v_w, lepe_v_b, phi, plo);

    // projection GEMM (bf16 3-term)
    cudaFuncSetAttribute(gemm_mma,
                         cudaFuncAttributeMaxDynamicSharedMemorySize, G_TOTAL_BYTES);
    dim3 gp(NPIX / 128, M_PROJ / 64);
    gemm_mma<<<gp, 256, G_TOTAL_BYTES>>>(pwh, pwl, phi, plo, proj_b, out);
}

// round 15
// speedup vs baseline: 1.8438x; 1.0341x over previous
#include <cuda_runtime.h>
#include <cuda_bf16.h>
#include <cuda_fp16.h>
#include <cstdint>
#include <math.h>

#define Cdim   192
#define NHEAD  8
#define HDIM   24
#define HWPIX  12544          // 112*112
#define LTOK   784            // 7*112
#define GK     192            // gemm K
#define NPIX   12544
#define M_QKV  576
#define M_PROJ 192
#define SCALE_F 0.20412414523193154f  // 24^-0.5
#define LOG2E   1.44269504088896340736f

typedef unsigned short ushort_t;

// ---------------- scratch (device globals; no allocation) ----------------
__device__ float g_qkv_h[M_QKV * HWPIX];
__device__ float g_qkv_v[M_QKV * HWPIX];
__device__ float g_att_h[Cdim * HWPIX];
__device__ float g_att_v[Cdim * HWPIX];
__device__ ushort_t g_xhi[GK * NPIX];           // fp16
__device__ ushort_t g_phi[GK * NPIX];           // bf16 (lepe out)
__device__ ushort_t g_plo[GK * NPIX];
__device__ ushort_t g_whh[M_QKV * GK];          // fp16 hi
__device__ ushort_t g_wvh[M_QKV * GK];
__device__ ushort_t g_pwh[M_PROJ * GK];         // bf16 hi
__device__ ushort_t g_pwl[M_PROJ * GK];

// ---------------- helpers ----------------
__device__ __forceinline__ uint32_t bfp(float lo_el, float hi_el) {
    uint32_t r;
    asm("cvt.rn.bf16x2.f32 %0, %1, %2;" : "=r"(r) : "f"(hi_el), "f"(lo_el));
    return r;
}
__device__ __forceinline__ float bflo(uint32_t p) { return __uint_as_float(p << 16); }
__device__ __forceinline__ float bfhi(uint32_t p) { return __uint_as_float(p & 0xFFFF0000u); }

__device__ __forceinline__ uint32_t s2u(const void* p) {
    uint32_t a;
    asm("{ .reg .u64 t; cvta.to.shared.u64 t, %1; cvt.u32.u64 %0, t; }" : "=r"(a) : "l"(p));
    return a;
}
__device__ __forceinline__ float ex2f(float x) {
    float r;
    asm("ex2.approx.f32 %0, %1;" : "=f"(r) : "f"(x));
    return r;
}
__device__ __forceinline__ uint32_t hfp(float lo_el, float hi_el) {
    uint32_t r;
    asm("cvt.rn.f16x2.f32 %0, %1, %2;" : "=r"(r) : "f"(hi_el), "f"(lo_el));
    return r;
}

__device__ __forceinline__ void mma_bf16(float* c,
    uint32_t a0, uint32_t a1, uint32_t a2, uint32_t a3,
    uint32_t b0, uint32_t b1)
{
    asm volatile("mma.sync.aligned.m16n8k16.row.col.f32.bf16.bf16.f32 "
        "{%0,%1,%2,%3}, {%4,%5,%6,%7}, {%8,%9}, {%0,%1,%2,%3};"
        : "+f"(c[0]), "+f"(c[1]), "+f"(c[2]), "+f"(c[3])
        : "r"(a0), "r"(a1), "r"(a2), "r"(a3), "r"(b0), "r"(b1));
}
__device__ __forceinline__ void mma_f16(float* c,
    uint32_t a0, uint32_t a1, uint32_t a2, uint32_t a3,
    uint32_t b0, uint32_t b1)
{
    asm volatile("mma.sync.aligned.m16n8k16.row.col.f32.f16.f16.f32 "
        "{%0,%1,%2,%3}, {%4,%5,%6,%7}, {%8,%9}, {%0,%1,%2,%3};"
        : "+f"(c[0]), "+f"(c[1]), "+f"(c[2]), "+f"(c[3])
        : "r"(a0), "r"(a1), "r"(a2), "r"(a3), "r"(b0), "r"(b1));
}
__device__ __forceinline__ void mma_f16_k8(float* c,
    uint32_t a0, uint32_t a1, uint32_t b0)
{
    asm volatile("mma.sync.aligned.m16n8k8.row.col.f32.f16.f16.f32 "
        "{%0,%1,%2,%3}, {%4,%5}, {%6}, {%0,%1,%2,%3};"
        : "+f"(c[0]), "+f"(c[1]), "+f"(c[2]), "+f"(c[3])
        : "r"(a0), "r"(a1), "r"(b0));
}

__device__ __forceinline__ void ldsm4t(uint32_t& r0, uint32_t& r1,
                                       uint32_t& r2, uint32_t& r3, uint32_t a)
{
    asm volatile("ldmatrix.sync.aligned.m8n8.x4.trans.shared.b16 {%0,%1,%2,%3}, [%4];"
        : "=r"(r0), "=r"(r1), "=r"(r2), "=r"(r3) : "r"(a));
}
__device__ __forceinline__ void ldsm4(uint32_t& r0, uint32_t& r1,
                                      uint32_t& r2, uint32_t& r3, uint32_t a)
{
    asm volatile("ldmatrix.sync.aligned.m8n8.x4.shared.b16 {%0,%1,%2,%3}, [%4];"
        : "=r"(r0), "=r"(r1), "=r"(r2), "=r"(r3) : "r"(a));
}
__device__ __forceinline__ void ldsm2(uint32_t& r0, uint32_t& r1, uint32_t a)
{
    asm volatile("ldmatrix.sync.aligned.m8n8.x2.shared.b16 {%0,%1}, [%2];"
        : "=r"(r0), "=r"(r1) : "r"(a));
}

#define CPA16(dst, src) asm volatile("cp.async.ca.shared.global [%0], [%1], 16;" :: "r"(dst), "l"(src) : "memory")
#define CPC()  asm volatile("cp.async.commit_group;" ::: "memory")
#define CPW1() asm volatile("cp.async.wait_group 1;" ::: "memory")
#define CPW0() asm volatile("cp.async.wait_group 0;" ::: "memory")

// ---------------- combined split (one launch) ----------------
// seg0: x -> fp16 hi; seg1/2: qkv weights -> fp16 hi only; seg3: proj w -> bf16 hi/lo
__global__ __launch_bounds__(256) void split_all(
    const float4* __restrict__ sx, uint2* __restrict__ xh, int n0,
    const float4* __restrict__ w1, uint2* __restrict__ h1p, int n1,
    const float4* __restrict__ w2, uint2* __restrict__ h2p, int n2,
    const float4* __restrict__ w3, uint2* __restrict__ h3p, uint2* __restrict__ l3p, int n3)
{
    int i = blockIdx.x * blockDim.x + threadIdx.x;
    int j = i;
    if (j < n0) {
        float4 v = sx[j];
        xh[j] = make_uint2(hfp(v.x, v.y), hfp(v.z, v.w));
        return;
    }
    j -= n0;
    if (j < n1 + n2) {
        const float4* src; uint2* hd;
        if (j < n1) { src = w1; hd = h1p; }
        else { j -= n1; src = w2; hd = h2p; }
        float4 v = src[j];
        hd[j] = make_uint2(hfp(v.x, v.y), hfp(v.z, v.w));
        return;
    }
    j -= n1 + n2;
    if (j < n3) {
        float4 v = w3[j];
        uint32_t h0 = bfp(v.x, v.y);
        uint32_t h1 = bfp(v.z, v.w);
        uint32_t l0 = bfp(v.x - bflo(h0), v.y - bfhi(h0));
        uint32_t l1 = bfp(v.z - bflo(h1), v.w - bfhi(h1));
        h3p[j] = make_uint2(h0, h1);
        l3p[j] = make_uint2(l0, l1);
    }
}

// ---------------- QKV GEMM: single-term fp16 Whi·Xhi ----------------
#define Q_SBH 0
#define Q_SAH 8704
#define Q_BSTR 136
#define Q_BBUF 4352
#define Q_ASTR 40
#define Q_ABUF 2560
#define Q_TOTAL_BYTES 27648

__global__ __launch_bounds__(256) void gemm_qkv(
    const ushort_t* __restrict__ Ah0, const ushort_t* __restrict__ Ah1,
    const ushort_t* __restrict__ Bhi,
    const float* __restrict__ bias0, const float* __restrict__ bias1,
    float* __restrict__ C0, float* __restrict__ C1)
{
    extern __shared__ ushort_t gsm[];
    const ushort_t* __restrict__ Ahi = blockIdx.z ? Ah1 : Ah0;
    const float* __restrict__ bias = blockIdx.z ? bias1 : bias0;
    float* __restrict__ C = blockIdx.z ? C1 : C0;

    const int tid = threadIdx.x;
    const int bn = blockIdx.x * 128, bm = blockIdx.y * 64;
    const int wid = tid >> 5, lane = tid & 31;
    const int wm = wid & 3, wn = wid >> 2;
    const int g = lane >> 2, q = lane & 3;
    const int wc = wn * 64;
    const int row0 = bm + wm * 16 + g;
    const int row1 = row0 + 8;

    float acc[8][4];
    #pragma unroll
    for (int i = 0; i < 8; i++)
        #pragma unroll
        for (int j = 0; j < 4; j++) acc[i][j] = 0.f;

    const int rB = tid >> 3;
    const int cB = (tid & 7) * 8;
    const int rA = tid >> 2;
    const int cA = (tid & 3) * 8;

    uint32_t smb = s2u(gsm);
    uint32_t dstBh[2], dstAh[2];
    #pragma unroll
    for (int b = 0; b < 2; b++) {
        dstBh[b] = smb + (uint32_t)((Q_SBH + b * Q_BBUF + rB * Q_BSTR + cB) * 2);
        dstAh[b] = smb + (uint32_t)((Q_SAH + b * Q_ABUF + rA * Q_ASTR + cA) * 2);
    }

    const int lm = lane >> 3, lr = lane & 7;
    const int lkrow = (lm & 1) * 8 + lr;
    const int lncol = wc + (lm >> 1) * 8;
    const int arow = wm * 16 + (lm & 1) * 8 + lr;
    const int acol = (lane >> 4) * 8;
    uint32_t sbh_base[2], sah_base[2];
    #pragma unroll
    for (int b = 0; b < 2; b++) {
        sbh_base[b] = smb + (uint32_t)((Q_SBH + b * Q_BBUF + lkrow * Q_BSTR + lncol) * 2);
        sah_base[b] = smb + (uint32_t)((Q_SAH + b * Q_ABUF + arow * Q_ASTR + acol) * 2);
    }

    {
        const ushort_t* bh = &Bhi[rB * NPIX + bn + cB];
        CPA16(dstBh[0], bh); CPA16(dstBh[0] + 128, bh + 64);
        CPA16(dstAh[0], &Ahi[(bm + rA) * GK + cA]);
        CPC();
    }

    #pragma unroll
    for (int ki = 0; ki < 6; ki++) {
        if (ki < 5) {
            const int kn = (ki + 1) * 32;
            const int bf = (ki + 1) & 1;
            const ushort_t* bh = &Bhi[(kn + rB) * NPIX + bn + cB];
            CPA16(dstBh[bf], bh); CPA16(dstBh[bf] + 128, bh + 64);
            CPA16(dstAh[bf], &Ahi[(bm + rA) * GK + kn + cA]);
            CPC();
            CPW1();
        } else {
            CPW0();
        }
        __syncthreads();

        const int buf = ki & 1;
        #pragma unroll
        for (int hh = 0; hh < 2; hh++) {
            uint32_t ah[4];
            ldsm4(ah[0], ah[1], ah[2], ah[3], sah_base[buf] + hh * 32);

            const uint32_t hoff = (uint32_t)(hh * 16 * Q_BSTR) * 2;
            #pragma unroll
            for (int j = 0; j < 4; j++) {
                uint32_t off = hoff + (uint32_t)(j * 16) * 2;
                uint32_t bh0, bh1, bh2, bh3;
                ldsm4t(bh0, bh1, bh2, bh3, sbh_base[buf] + off);
                mma_f16(acc[2 * j],     ah[0], ah[1], ah[2], ah[3], bh0, bh1);
                mma_f16(acc[2 * j + 1], ah[0], ah[1], ah[2], ah[3], bh2, bh3);
            }
        }
        __syncthreads();
    }

    const float b0 = bias[row0], b1 = bias[row1];
    #pragma unroll
    for (int nf = 0; nf < 8; nf++) {
        int col = bn + wc + nf * 8 + 2 * q;
        *(float2*)&C[row0 * NPIX + col] = make_float2(acc[nf][0] + b0, acc[nf][1] + b0);
        *(float2*)&C[row1 * NPIX + col] = make_float2(acc[nf][2] + b1, acc[nf][3] + b1);
    }
}

// ---------------- proj GEMM: bf16 3-term (exact path, unchanged) ----------------
#define G_SBH 0
#define G_SBL 8704
#define G_SAH 17408
#define G_SAL 22528
#define G_BSTR 136
#define G_BBUF 4352
#define G_ASTR 40
#define G_ABUF 2560
#define G_TOTAL_BYTES 55296

__global__ __launch_bounds__(256) void gemm_mma(
    const ushort_t* __restrict__ Ahi, const ushort_t* __restrict__ Alo,
    const ushort_t* __restrict__ Bhi, const ushort_t* __restrict__ Blo,
    const float* __restrict__ bias, float* __restrict__ C)
{
    extern __shared__ ushort_t gsm[];
    const int tid = threadIdx.x;
    const int bn = blockIdx.x * 128, bm = blockIdx.y * 64;
    const int wid = tid >> 5, lane = tid & 31;
    const int wm = wid & 3, wn = wid >> 2;
    const int g = lane >> 2, q = lane & 3;
    const int wc = wn * 64;
    const int row0 = bm + wm * 16 + g;
    const int row1 = row0 + 8;

    float acc[8][4];
    #pragma unroll
    for (int i = 0; i < 8; i++)
        #pragma unroll
        for (int j = 0; j < 4; j++) acc[i][j] = 0.f;

    const int rB = tid >> 3;
    const int cB = (tid & 7) * 8;
    const int rA = tid >> 2;
    const int cA = (tid & 3) * 8;

    uint32_t smb = s2u(gsm);
    uint32_t dstBh[2], dstBl[2], dstAh[2], dstAl[2];
    #pragma unroll
    for (int b = 0; b < 2; b++) {
        dstBh[b] = smb + (uint32_t)((G_SBH + b * G_BBUF + rB * G_BSTR + cB) * 2);
        dstBl[b] = smb + (uint32_t)((G_SBL + b * G_BBUF + rB * G_BSTR + cB) * 2);
        dstAh[b] = smb + (uint32_t)((G_SAH + b * G_ABUF + rA * G_ASTR + cA) * 2);
        dstAl[b] = smb + (uint32_t)((G_SAL + b * G_ABUF + rA * G_ASTR + cA) * 2);
    }

    const int lm = lane >> 3, lr = lane & 7;
    const int lkrow = (lm & 1) * 8 + lr;
    const int lncol = wc + (lm >> 1) * 8;
    const int arow = wm * 16 + (lm & 1) * 8 + lr;
    const int acol = (lane >> 4) * 8;
    uint32_t sbh_base[2], sbl_base[2], sah_base[2], sal_base[2];
    #pragma unroll
    for (int b = 0; b < 2; b++) {
        sbh_base[b] = smb + (uint32_t)((G_SBH + b * G_BBUF + lkrow * G_BSTR + lncol) * 2);
        sbl_base[b] = smb + (uint32_t)((G_SBL + b * G_BBUF + lkrow * G_BSTR + lncol) * 2);
        sah_base[b] = smb + (uint32_t)((G_SAH + b * G_ABUF + arow * G_ASTR + acol) * 2);
        sal_base[b] = smb + (uint32_t)((G_SAL + b * G_ABUF + arow * G_ASTR + acol) * 2);
    }

    {
        const ushort_t* bh = &Bhi[rB * NPIX + bn + cB];
        const ushort_t* bl = &Blo[rB * NPIX + bn + cB];
        CPA16(dstBh[0], bh); CPA16(dstBh[0] + 128, bh + 64);
        CPA16(dstBl[0], bl); CPA16(dstBl[0] + 128, bl + 64);
        CPA16(dstAh[0], &Ahi[(bm + rA) * GK + cA]);
        CPA16(dstAl[0], &Alo[(bm + rA) * GK + cA]);
        CPC();
    }

    #pragma unroll
    for (int ki = 0; ki < 6; ki++) {
        if (ki < 5) {
            const int kn = (ki + 1) * 32;
            const int bf = (ki + 1) & 1;
            const ushort_t* bh = &Bhi[(kn + rB) * NPIX + bn + cB];
            const ushort_t* bl = &Blo[(kn + rB) * NPIX + bn + cB];
            CPA16(dstBh[bf], bh); CPA16(dstBh[bf] + 128, bh + 64);
            CPA16(dstBl[bf], bl); CPA16(dstBl[bf] + 128, bl + 64);
            CPA16(dstAh[bf], &Ahi[(bm + rA) * GK + kn + cA]);
            CPA16(dstAl[bf], &Alo[(bm + rA) * GK + kn + cA]);
            CPC();
            CPW1();
        } else {
            CPW0();
        }
        __syncthreads();

        const int buf = ki & 1;
        #pragma unroll
        for (int hh = 0; hh < 2; hh++) {
            uint32_t ah[4], al[4];
            ldsm4(ah[0], ah[1], ah[2], ah[3], sah_base[buf] + hh * 32);
            ldsm4(al[0], al[1], al[2], al[3], sal_base[buf] + hh * 32);

            const uint32_t hoff = (uint32_t)(hh * 16 * G_BSTR) * 2;
            #pragma unroll
            for (int j = 0; j < 4; j++) {
                uint32_t off = hoff + (uint32_t)(j * 16) * 2;
                uint32_t bh0, bh1, bh2, bh3, bl0, bl1, bl2, bl3;
                ldsm4t(bh0, bh1, bh2, bh3, sbh_base[buf] + off);
                ldsm4t(bl0, bl1, bl2, bl3, sbl_base[buf] + off);
                float* c0 = acc[2 * j];
                float* c1 = acc[2 * j + 1];
                mma_bf16(c0, ah[0], ah[1], ah[2], ah[3], bh0, bh1);
                mma_bf16(c0, al[0], al[1], al[2], al[3], bh0, bh1);
                mma_bf16(c0, ah[0], ah[1], ah[2], ah[3], bl0, bl1);
                mma_bf16(c1, ah[0], ah[1], ah[2], ah[3], bh2, bh3);
                mma_bf16(c1, al[0], al[1], al[2], al[3], bh2, bh3);
                mma_bf16(c1, ah[0], ah[1], ah[2], ah[3], bl2, bl3);
            }
        }
        __syncthreads();
    }

    const float b0 = bias[row0], b1 = bias[row1];
    #pragma unroll
    for (int nf = 0; nf < 8; nf++) {
        int col = bn + wc + nf * 8 + 2 * q;
        *(float2*)&C[row0 * NPIX + col] = make_float2(acc[nf][0] + b0, acc[nf][1] + b0);
        *(float2*)&C[row1 * NPIX + col] = make_float2(acc[nf][2] + b1, acc[nf][3] + b1);
    }
}

// ============================================================================
// fp16 flash attention — software-pipelined (R14, unchanged)
// ============================================================================
#define KSTR 40
#define VSTRF 792
#define NW    12
#define NTHR  384

#define A_SKH 0
#define A_SVH (A_SKH + LTOK * KSTR * 2)          // 62720
#define A_SB  (A_SVH + HDIM * VSTRF * 2)         // 100736
#define A_TOTAL (A_SB + 256)

__global__ __launch_bounds__(NTHR, 2) void attn_mma(
    const float* __restrict__ tab_h, const float* __restrict__ tab_v)
{
    extern __shared__ char asm_[];
    ushort_t* sKhi = (ushort_t*)(asm_ + A_SKH);
    ushort_t* sVhi = (ushort_t*)(asm_ + A_SVH);
    float* sb = (float*)(asm_ + A_SB);

    const int tid = threadIdx.x;
    const int w = blockIdx.x, h = blockIdx.y, br = blockIdx.z;
    const float* __restrict__ qkv = br ? g_qkv_v : g_qkv_h;
    float* __restrict__ outp = br ? g_att_v : g_att_h;
    const float* __restrict__ tab = br ? tab_v : tab_h;

    if (tid < 49) {
        int r1 = tid / 7, r2 = tid % 7, off = r1 - r2 + 6;
        float bv = br ? tab[(6 * 13 + off) * NHEAD + h]
                      : tab[(off * 13 + 6) * NHEAD + h];
        sb[tid] = bv * LOG2E;
    }
    for (int i = tid; i < LTOK * 8; i += NTHR) {
        int k = i >> 3, d = 24 + (i & 7);
        sKhi[k * KSTR + d] = 0;
    }
    if (tid < HDIM * 8) {
        int d = tid >> 3, k = LTOK + (tid & 7);
        sVhi[d * VSTRF + k] = 0;
    }
    for (int idx = tid; idx < LTOK * HDIM; idx += NTHR) {
        int d = idx / LTOK, k = idx - d * LTOK;
        int pix = br ? ((k / 7) * 112 + w * 7 + (k % 7)) : (w * LTOK + k);
        float kv = qkv[(192 + h * HDIM + d) * HWPIX + pix];
        float vv = qkv[(384 + h * HDIM + d) * HWPIX + pix];
        sKhi[k * KSTR + d] = __half_as_ushort(__float2half_rn(kv));
        sVhi[d * VSTRF + k] = __half_as_ushort(__float2half_rn(vv));
    }
    __syncthreads();

    const int warp = tid >> 5, lane = tid & 31;
    const int g = lane >> 2, q = lane & 3;
    const int d0 = 2 * q;
    const int lr = lane & 7;

    const uint32_t kln = (uint32_t)((lr * KSTR + (lane >> 3) * 8) * 2);
    const uint32_t skh_b = s2u(sKhi) + kln;
    const int vko = ((lane >> 3) & 1) * 8;
    const int vdh = ((lane >> 4) & 1) * 8 + lr;
    const uint32_t sv4 = s2u(sVhi) + (uint32_t)((vdh * VSTRF + vko) * 2);
    const uint32_t sv2a = s2u(sVhi) + (uint32_t)(((16 + lr) * VSTRF + vko) * 2);

    const float qscale = SCALE_F * LOG2E;

    for (int mt = warp; mt < 49; mt += NW) {
        const int r0 = mt * 16 + g, r1 = r0 + 8;
        const int pix0 = br ? ((r0 / 7) * 112 + w * 7 + (r0 % 7)) : (w * LTOK + r0);
        const int pix1 = br ? ((r1 / 7) * 112 + w * 7 + (r1 % 7)) : (w * LTOK + r1);
        const int bro0 = (br ? (r0 % 7) : (r0 / 112)) * 7;
        const int bro1 = (br ? (r1 % 7) : (r1 / 112)) * 7;

        uint32_t qh[6];
        #pragma unroll
        for (int p = 0; p < 3; p++) {
            int d = d0 + 8 * p;
            float a0v = qkv[(h * HDIM + d)     * HWPIX + pix0] * qscale;
            float a1v = qkv[(h * HDIM + d + 1) * HWPIX + pix0] * qscale;
            float b0v = qkv[(h * HDIM + d)     * HWPIX + pix1] * qscale;
            float b1v = qkv[(h * HDIM + d + 1) * HWPIX + pix1] * qscale;
            qh[2 * p]     = hfp(a0v, a1v);
            qh[2 * p + 1] = hfp(b0v, b1v);
        }

        float o[3][4];
        #pragma unroll
        for (int nd = 0; nd < 3; nd++)
            #pragma unroll
            for (int i = 0; i < 4; i++) o[nd][i] = 0.f;
        float rs0 = 0.f, rs1 = 0.f;

        float sA[4] = {0.f, 0.f, 0.f, 0.f};
        float sB[4] = {0.f, 0.f, 0.f, 0.f};
        {
            uint32_t h0, h1, h2, h3;
            ldsm4(h0, h1, h2, h3, skh_b);
            mma_f16(sA, qh[0], qh[1], qh[2], qh[3], h0, h1);
            mma_f16_k8(sA, qh[4], qh[5], h2);
            ldsm4(h0, h1, h2, h3, skh_b + (uint32_t)(8 * KSTR * 2));
            mma_f16(sB, qh[0], qh[1], qh[2], qh[3], h0, h1);
            mma_f16_k8(sB, qh[4], qh[5], h2);
        }

        #pragma unroll 4
        for (int s = 0; s < 56; s++) {
            const int kt = s >> 2, ks = s & 3;
            const int kbase = kt * 56;
            const int nt0 = 2 * ks;
            const bool has1 = (ks != 3);

            float nA[4] = {0.f, 0.f, 0.f, 0.f};
            float nB[4] = {0.f, 0.f, 0.f, 0.f};
            if (s < 55) {
                const int s1 = s + 1;
                const int kb1 = (s1 >> 2) * 56;
                const int ns0 = 2 * (s1 & 3);
                uint32_t ko = (uint32_t)((kb1 + ns0 * 8) * KSTR * 2);
                uint32_t h0, h1, h2, h3;
                ldsm4(h0, h1, h2, h3, skh_b + ko);
                mma_f16(nA, qh[0], qh[1], qh[2], qh[3], h0, h1);
                mma_f16_k8(nA, qh[4], qh[5], h2);
                if ((s1 & 3) != 3) {
                    ko = (uint32_t)((kb1 + (ns0 + 1) * 8) * KSTR * 2);
                    ldsm4(h0, h1, h2, h3, skh_b + ko);
                    mma_f16(nB, qh[0], qh[1], qh[2], qh[3], h0, h1);
                    mma_f16_k8(nB, qh[4], qh[5], h2);
                }
            }

            float eA0, eA1, eA2, eA3, eB0 = 0.f, eB1 = 0.f, eB2 = 0.f, eB3 = 0.f;
            if (!br) {
                float bh0 = sb[bro0 + (kt >> 1)];
                float bh1 = sb[bro1 + (kt >> 1)];
                eA0 = ex2f(sA[0] + bh0); eA1 = ex2f(sA[1] + bh0);
                eA2 = ex2f(sA[2] + bh1); eA3 = ex2f(sA[3] + bh1);
                if (has1) {
                    eB0 = ex2f(sB[0] + bh0); eB1 = ex2f(sB[1] + bh0);
                    eB2 = ex2f(sB[2] + bh1); eB3 = ex2f(sB[3] + bh1);
                }
            } else {
                int i0 = (nt0 + d0) % 7;
                int i1 = i0 + 1; if (i1 == 7) i1 = 0;
                int j1 = i1 + 1; if (j1 == 7) j1 = 0;
                eA0 = ex2f(sA[0] + sb[bro0 + i0]); eA1 = ex2f(sA[1] + sb[bro0 + i1]);
                eA2 = ex2f(sA[2] + sb[bro1 + i0]); eA3 = ex2f(sA[3] + sb[bro1 + i1]);
                if (has1) {
                    eB0 = ex2f(sB[0] + sb[bro0 + i1]); eB1 = ex2f(sB[1] + sb[bro0 + j1]);
                    eB2 = ex2f(sB[2] + sb[bro1 + i1]); eB3 = ex2f(sB[3] + sb[bro1 + j1]);
                }
            }
            rs0 += eA0 + eA1 + eB0 + eB1;
            rs1 += eA2 + eA3 + eB2 + eB3;

            uint32_t pa0 = hfp(eA0, eA1), pa1 = hfp(eA2, eA3);
            uint32_t pa2 = has1 ? hfp(eB0, eB1) : 0u;
            uint32_t pa3 = has1 ? hfp(eB2, eB3) : 0u;

            {
                uint32_t vo = (uint32_t)((kbase + ks * 16) * 2);
                uint32_t va0, va1, va2, va3, vx0, vx1;
                ldsm4(va0, va1, va2, va3, sv4 + vo);
                ldsm2(vx0, vx1, sv2a + vo);
                mma_f16(o[0], pa0, pa1, pa2, pa3, va0, va1);
                mma_f16(o[1], pa0, pa1, pa2, pa3, va2, va3);
                mma_f16(o[2], pa0, pa1, pa2, pa3, vx0, vx1);
            }

            #pragma unroll
            for (int i = 0; i < 4; i++) { sA[i] = nA[i]; sB[i] = nB[i]; }
        }

        float a0 = rs0, a1 = rs1;
        a0 += __shfl_xor_sync(0xFFFFFFFFu, a0, 1);
        a0 += __shfl_xor_sync(0xFFFFFFFFu, a0, 2);
        a1 += __shfl_xor_sync(0xFFFFFFFFu, a1, 1);
        a1 += __shfl_xor_sync(0xFFFFFFFFu, a1, 2);
        float inv0 = 1.f / a0, inv1 = 1.f / a1;
        #pragma unroll
        for (int nd = 0; nd < 3; nd++) {
            int d = nd * 8 + d0;
            outp[(h * HDIM + d)     * HWPIX + pix0] = o[nd][0] * inv0;
            outp[(h * HDIM + d + 1) * HWPIX + pix0] = o[nd][1] * inv0;
            outp[(h * HDIM + d)     * HWPIX + pix1] = o[nd][2] * inv1;
            outp[(h * HDIM + d + 1) * HWPIX + pix1] = o[nd][3] * inv1;
        }
    }
}

// ---------------- fused dual LePE -> 0.5*(h+v) -> bf16 hi/lo planes ----------------
__global__ __launch_bounds__(256) void lepe_fused(
    const float* __restrict__ attH, const float* __restrict__ attV,
    const float* __restrict__ wH, const float* __restrict__ bH,
    const float* __restrict__ wV, const float* __restrict__ bV,
    ushort_t* __restrict__ phi, ushort_t* __restrict__ plo)
{
    int t = blockIdx.x * blockDim.x + threadIdx.x;
    if (t >= Cdim * (HWPIX / 4)) return;
    int c = t / (HWPIX / 4);
    int r = t % (HWPIX / 4);
    int y = r / 28, x4 = (r % 28) * 4;
    const float* baseH = attH + c * HWPIX;
    const float* baseV = attV + c * HWPIX;

    float wvh[9], wvv[9];
    #pragma unroll
    for (int i = 0; i < 9; i++) { wvh[i] = wH[c * 9 + i]; wvv[i] = wV[c * 9 + i]; }
    float ah0 = bH[c], ah1 = ah0, ah2 = ah0, ah3 = ah0;
    float av0 = bV[c], av1 = av0, av2 = av0, av3 = av0;

    #pragma unroll
    for (int ky = 0; ky < 3; ky++) {
        int yy = y + ky - 1;
        if (yy < 0 || yy >= 112) continue;
        const float* rpH = baseH + yy * 112 + x4;
        const float* rpV = baseV + yy * 112 + x4;
        float4 mH = *(const float4*)rpH;
        float4 mV = *(const float4*)rpV;
        float lfH = (x4 > 0)   ? rpH[-1] : 0.f;
        float rtH = (x4 < 108) ? rpH[4]  : 0.f;
        float lfV = (x4 > 0)   ? rpV[-1] : 0.f;
        float rtV = (x4 < 108) ? rpV[4]  : 0.f;
        float h0 = wvh[ky*3], h1 = wvh[ky*3+1], h2 = wvh[ky*3+2];
        float v0 = wvv[ky*3], v1 = wvv[ky*3+1], v2 = wvv[ky*3+2];
        ah0 += h0 * lfH  + h1 * mH.x + h2 * mH.y;
        ah1 += h0 * mH.x + h1 * mH.y + h2 * mH.z;
        ah2 += h0 * mH.y + h1 * mH.z + h2 * mH.w;
        ah3 += h0 * mH.z + h1 * mH.w + h2 * rtH;
        av0 += v0 * lfV  + v1 * mV.x + v2 * mV.y;
        av1 += v0 * mV.x + v1 * mV.y + v2 * mV.z;
        av2 += v0 * mV.y + v1 * mV.z + v2 * mV.w;
        av3 += v0 * mV.z + v1 * mV.w + v2 * rtV;
    }

    float4 inH = *(const float4*)(baseH + y * 112 + x4);
    float4 inV = *(const float4*)(baseV + y * 112 + x4);
    const float RS2 = 0.70710678118654752f;
    float oh0 = inH.x + 0.5f * ah0 * (1.f + erff(ah0 * RS2));
    float oh1 = inH.y + 0.5f * ah1 * (1.f + erff(ah1 * RS2));
    float oh2 = inH.z + 0.5f * ah2 * (1.f + erff(ah2 * RS2));
    float oh3 = inH.w + 0.5f * ah3 * (1.f + erff(ah3 * RS2));
    float ov0 = inV.x + 0.5f * av0 * (1.f + erff(av0 * RS2));
    float ov1 = inV.y + 0.5f * av1 * (1.f + erff(av1 * RS2));
    float ov2 = inV.z + 0.5f * av2 * (1.f + erff(av2 * RS2));
    float ov3 = inV.w + 0.5f * av3 * (1.f + erff(av3 * RS2));

    float p0 = 0.5f * (oh0 + ov0);
    float p1 = 0.5f * (oh1 + ov1);
    float p2 = 0.5f * (oh2 + ov2);
    float p3 = 0.5f * (oh3 + ov3);

    uint32_t h0w = bfp(p0, p1), h1w = bfp(p2, p3);
    uint32_t l0w = bfp(p0 - bflo(h0w), p1 - bfhi(h0w));
    uint32_t l1w = bfp(p2 - bflo(h1w), p3 - bfhi(h1w));
    int idx = c * HWPIX + y * 112 + x4;
    *(uint2*)&phi[idx] = make_uint2(h0w, h1w);
    *(uint2*)&plo[idx] = make_uint2(l0w, l1w);
}

// ---------------- launch ----------------
extern "C" void kernel_launch(void* const* d_in, const int* in_sizes, int n_in,
                              void* d_out, int out_size)
{
    const float* x        = (const float*)d_in[0];
    const float* qkv_h_w  = (const float*)d_in[1];
    const float* qkv_h_b  = (const float*)d_in[2];
    const float* qkv_v_w  = (const float*)d_in[3];
    const float* qkv_v_b  = (const float*)d_in[4];
    const float* proj_w   = (const float*)d_in[5];
    const float* proj_b   = (const float*)d_in[6];
    const float* lepe_h_w = (const float*)d_in[7];
    const float* lepe_h_b = (const float*)d_in[8];
    const float* lepe_v_w = (const float*)d_in[9];
    const float* lepe_v_b = (const float*)d_in[10];
    const float* tab_h    = (const float*)d_in[11];
    const float* tab_v    = (const float*)d_in[12];
    float* out = (float*)d_out;

    float *qh, *qv, *ah, *av;
    ushort_t *xhi, *phi, *plo, *whh, *wvh, *pwh, *pwl;
    cudaGetSymbolAddress((void**)&qh, g_qkv_h);
    cudaGetSymbolAddress((void**)&qv, g_qkv_v);
    cudaGetSymbolAddress((void**)&ah, g_att_h);
    cudaGetSymbolAddress((void**)&av, g_att_v);
    cudaGetSymbolAddress((void**)&xhi, g_xhi);
    cudaGetSymbolAddress((void**)&phi, g_phi);
    cudaGetSymbolAddress((void**)&plo, g_plo);
    cudaGetSymbolAddress((void**)&whh, g_whh);
    cudaGetSymbolAddress((void**)&wvh, g_wvh);
    cudaGetSymbolAddress((void**)&pwh, g_pwh);
    cudaGetSymbolAddress((void**)&pwl, g_pwl);

    int nx4 = GK * NPIX / 4;
    int nw4 = M_QKV * GK / 4;
    int np4 = M_PROJ * GK / 4;
    int ntot = nx4 + nw4 * 2 + np4;
    split_all<<<(ntot + 255) / 256, 256>>>(
        (const float4*)x,       (uint2*)xhi, nx4,
        (const float4*)qkv_h_w, (uint2*)whh, nw4,
        (const float4*)qkv_v_w, (uint2*)wvh, nw4,
        (const float4*)proj_w,  (uint2*)pwh, (uint2*)pwl, np4);

    // QKV GEMMs (fp16 single-term)
    cudaFuncSetAttribute(gemm_qkv,
                         cudaFuncAttributeMaxDynamicSharedMemorySize, Q_TOTAL_BYTES);
    dim3 gq(NPIX / 128, M_QKV / 64, 2);
    gemm_qkv<<<gq, 256, Q_TOTAL_BYTES>>>(whh, wvh, xhi,
                                         qkv_h_b, qkv_v_b, qh, qv);

    // attention (pipelined)
    cudaFuncSetAttribute(attn_mma,
                         cudaFuncAttributeMaxDynamicSharedMemorySize, A_TOTAL);
    dim3 ga(16, NHEAD, 2);
    attn_mma<<<ga, NTHR, A_TOTAL>>>(tab_h, tab_v);

    int nthr = Cdim * (HWPIX / 4);
    lepe_fused<<<(nthr + 255) / 256, 256>>>(ah, av, lepe_h_w, lepe_h_b,
                                            lepe_v_w, lepe_v_b, phi, plo);

    // projection GEMM (bf16 3-term, exact path)
    cudaFuncSetAttribute(gemm_mma,
                         cudaFuncAttributeMaxDynamicSharedMemorySize, G_TOTAL_BYTES);
    dim3 gp(NPIX / 128, M_PROJ / 64);
    gemm_mma<<<gp, 256, G_TOTAL_BYTES>>>(pwh, pwl, phi, plo, proj_b, out);
}

// round 16
// speedup vs baseline: 1.9092x; 1.0355x over previous
#include <cuda_runtime.h>
#include <cuda_bf16.h>
#include <cuda_fp16.h>
#include <cstdint>
#include <math.h>

#define Cdim   192
#define NHEAD  8
#define HDIM   24
#define HWPIX  12544          // 112*112
#define LTOK   784            // 7*112
#define GK     192            // gemm K
#define NPIX   12544
#define M_QKV  576
#define M_PROJ 192
#define SCALE_F 0.20412414523193154f  // 24^-0.5
#define LOG2E   1.44269504088896340736f

typedef unsigned short ushort_t;

// ---------------- scratch (device globals; no allocation) ----------------
__device__ float g_qkv_h[M_QKV * HWPIX];
__device__ float g_qkv_v[M_QKV * HWPIX];
__device__ float g_att_h[Cdim * HWPIX];
__device__ float g_att_v[Cdim * HWPIX];
__device__ ushort_t g_xhi[GK * NPIX];           // fp16
__device__ ushort_t g_phi[GK * NPIX];           // bf16 (lepe out)
__device__ ushort_t g_plo[GK * NPIX];
__device__ ushort_t g_whh[M_QKV * GK];          // fp16 hi
__device__ ushort_t g_wvh[M_QKV * GK];
__device__ ushort_t g_pwh[M_PROJ * GK];         // bf16 hi
__device__ ushort_t g_pwl[M_PROJ * GK];

// ---------------- helpers ----------------
__device__ __forceinline__ uint32_t bfp(float lo_el, float hi_el) {
    uint32_t r;
    asm("cvt.rn.bf16x2.f32 %0, %1, %2;" : "=r"(r) : "f"(hi_el), "f"(lo_el));
    return r;
}
__device__ __forceinline__ float bflo(uint32_t p) { return __uint_as_float(p << 16); }
__device__ __forceinline__ float bfhi(uint32_t p) { return __uint_as_float(p & 0xFFFF0000u); }

__device__ __forceinline__ uint32_t s2u(const void* p) {
    uint32_t a;
    asm("{ .reg .u64 t; cvta.to.shared.u64 t, %1; cvt.u32.u64 %0, t; }" : "=r"(a) : "l"(p));
    return a;
}
__device__ __forceinline__ uint32_t hfp(float lo_el, float hi_el) {
    uint32_t r;
    asm("cvt.rn.f16x2.f32 %0, %1, %2;" : "=r"(r) : "f"(hi_el), "f"(lo_el));
    return r;
}
__device__ __forceinline__ uint32_t hex2(uint32_t x) {
    uint32_t r;
    asm("ex2.approx.f16x2 %0, %1;" : "=r"(r) : "r"(x));
    return r;
}
__device__ __forceinline__ uint32_t hadd2u(uint32_t a, uint32_t b) {
    uint32_t r;
    asm("add.rn.f16x2 %0, %1, %2;" : "=r"(r) : "r"(a), "r"(b));
    return r;
}
__device__ __forceinline__ float h2lo(uint32_t p) {
    return __half2float(__ushort_as_half((ushort_t)(p & 0xFFFFu)));
}
__device__ __forceinline__ float h2hi(uint32_t p) {
    return __half2float(__ushort_as_half((ushort_t)(p >> 16)));
}

__device__ __forceinline__ void mma_bf16(float* c,
    uint32_t a0, uint32_t a1, uint32_t a2, uint32_t a3,
    uint32_t b0, uint32_t b1)
{
    asm volatile("mma.sync.aligned.m16n8k16.row.col.f32.bf16.bf16.f32 "
        "{%0,%1,%2,%3}, {%4,%5,%6,%7}, {%8,%9}, {%0,%1,%2,%3};"
        : "+f"(c[0]), "+f"(c[1]), "+f"(c[2]), "+f"(c[3])
        : "r"(a0), "r"(a1), "r"(a2), "r"(a3), "r"(b0), "r"(b1));
}
__device__ __forceinline__ void mma_f16(float* c,
    uint32_t a0, uint32_t a1, uint32_t a2, uint32_t a3,
    uint32_t b0, uint32_t b1)
{
    asm volatile("mma.sync.aligned.m16n8k16.row.col.f32.f16.f16.f32 "
        "{%0,%1,%2,%3}, {%4,%5,%6,%7}, {%8,%9}, {%0,%1,%2,%3};"
        : "+f"(c[0]), "+f"(c[1]), "+f"(c[2]), "+f"(c[3])
        : "r"(a0), "r"(a1), "r"(a2), "r"(a3), "r"(b0), "r"(b1));
}
__device__ __forceinline__ void mma_f16_k8(float* c,
    uint32_t a0, uint32_t a1, uint32_t b0)
{
    asm volatile("mma.sync.aligned.m16n8k8.row.col.f32.f16.f16.f32 "
        "{%0,%1,%2,%3}, {%4,%5}, {%6}, {%0,%1,%2,%3};"
        : "+f"(c[0]), "+f"(c[1]), "+f"(c[2]), "+f"(c[3])
        : "r"(a0), "r"(a1), "r"(b0));
}

__device__ __forceinline__ void ldsm4t(uint32_t& r0, uint32_t& r1,
                                       uint32_t& r2, uint32_t& r3, uint32_t a)
{
    asm volatile("ldmatrix.sync.aligned.m8n8.x4.trans.shared.b16 {%0,%1,%2,%3}, [%4];"
        : "=r"(r0), "=r"(r1), "=r"(r2), "=r"(r3) : "r"(a));
}
__device__ __forceinline__ void ldsm4(uint32_t& r0, uint32_t& r1,
                                      uint32_t& r2, uint32_t& r3, uint32_t a)
{
    asm volatile("ldmatrix.sync.aligned.m8n8.x4.shared.b16 {%0,%1,%2,%3}, [%4];"
        : "=r"(r0), "=r"(r1), "=r"(r2), "=r"(r3) : "r"(a));
}
__device__ __forceinline__ void ldsm2(uint32_t& r0, uint32_t& r1, uint32_t a)
{
    asm volatile("ldmatrix.sync.aligned.m8n8.x2.shared.b16 {%0,%1}, [%2];"
        : "=r"(r0), "=r"(r1) : "r"(a));
}

#define CPA16(dst, src) asm volatile("cp.async.ca.shared.global [%0], [%1], 16;" :: "r"(dst), "l"(src) : "memory")
#define CPC()  asm volatile("cp.async.commit_group;" ::: "memory")
#define CPW1() asm volatile("cp.async.wait_group 1;" ::: "memory")
#define CPW0() asm volatile("cp.async.wait_group 0;" ::: "memory")

// ---------------- combined split (one launch) ----------------
__global__ __launch_bounds__(256) void split_all(
    const float4* __restrict__ sx, uint2* __restrict__ xh, int n0,
    const float4* __restrict__ w1, uint2* __restrict__ h1p, int n1,
    const float4* __restrict__ w2, uint2* __restrict__ h2p, int n2,
    const float4* __restrict__ w3, uint2* __restrict__ h3p, uint2* __restrict__ l3p, int n3)
{
    int i = blockIdx.x * blockDim.x + threadIdx.x;
    int j = i;
    if (j < n0) {
        float4 v = sx[j];
        xh[j] = make_uint2(hfp(v.x, v.y), hfp(v.z, v.w));
        return;
    }
    j -= n0;
    if (j < n1 + n2) {
        const float4* src; uint2* hd;
        if (j < n1) { src = w1; hd = h1p; }
        else { j -= n1; src = w2; hd = h2p; }
        float4 v = src[j];
        hd[j] = make_uint2(hfp(v.x, v.y), hfp(v.z, v.w));
        return;
    }
    j -= n1 + n2;
    if (j < n3) {
        float4 v = w3[j];
        uint32_t h0 = bfp(v.x, v.y);
        uint32_t h1 = bfp(v.z, v.w);
        uint32_t l0 = bfp(v.x - bflo(h0), v.y - bfhi(h0));
        uint32_t l1 = bfp(v.z - bflo(h1), v.w - bfhi(h1));
        h3p[j] = make_uint2(h0, h1);
        l3p[j] = make_uint2(l0, l1);
    }
}

// ---------------- QKV GEMM: single-term fp16 Whi·Xhi ----------------
#define Q_SBH 0
#define Q_SAH 8704
#define Q_BSTR 136
#define Q_BBUF 4352
#define Q_ASTR 40
#define Q_ABUF 2560
#define Q_TOTAL_BYTES 27648

__global__ __launch_bounds__(256) void gemm_qkv(
    const ushort_t* __restrict__ Ah0, const ushort_t* __restrict__ Ah1,
    const ushort_t* __restrict__ Bhi,
    const float* __restrict__ bias0, const float* __restrict__ bias1,
    float* __restrict__ C0, float* __restrict__ C1)
{
    extern __shared__ ushort_t gsm[];
    const ushort_t* __restrict__ Ahi = blockIdx.z ? Ah1 : Ah0;
    const float* __restrict__ bias = blockIdx.z ? bias1 : bias0;
    float* __restrict__ C = blockIdx.z ? C1 : C0;

    const int tid = threadIdx.x;
    const int bn = blockIdx.x * 128, bm = blockIdx.y * 64;
    const int wid = tid >> 5, lane = tid & 31;
    const int wm = wid & 3, wn = wid >> 2;
    const int g = lane >> 2, q = lane & 3;
    const int wc = wn * 64;
    const int row0 = bm + wm * 16 + g;
    const int row1 = row0 + 8;

    float acc[8][4];
    #pragma unroll
    for (int i = 0; i < 8; i++)
        #pragma unroll
        for (int j = 0; j < 4; j++) acc[i][j] = 0.f;

    const int rB = tid >> 3;
    const int cB = (tid & 7) * 8;
    const int rA = tid >> 2;
    const int cA = (tid & 3) * 8;

    uint32_t smb = s2u(gsm);
    uint32_t dstBh[2], dstAh[2];
    #pragma unroll
    for (int b = 0; b < 2; b++) {
        dstBh[b] = smb + (uint32_t)((Q_SBH + b * Q_BBUF + rB * Q_BSTR + cB) * 2);
        dstAh[b] = smb + (uint32_t)((Q_SAH + b * Q_ABUF + rA * Q_ASTR + cA) * 2);
    }

    const int lm = lane >> 3, lr = lane & 7;
    const int lkrow = (lm & 1) * 8 + lr;
    const int lncol = wc + (lm >> 1) * 8;
    const int arow = wm * 16 + (lm & 1) * 8 + lr;
    const int acol = (lane >> 4) * 8;
    uint32_t sbh_base[2], sah_base[2];
    #pragma unroll
    for (int b = 0; b < 2; b++) {
        sbh_base[b] = smb + (uint32_t)((Q_SBH + b * Q_BBUF + lkrow * Q_BSTR + lncol) * 2);
        sah_base[b] = smb + (uint32_t)((Q_SAH + b * Q_ABUF + arow * Q_ASTR + acol) * 2);
    }

    {
        const ushort_t* bh = &Bhi[rB * NPIX + bn + cB];
        CPA16(dstBh[0], bh); CPA16(dstBh[0] + 128, bh + 64);
        CPA16(dstAh[0], &Ahi[(bm + rA) * GK + cA]);
        CPC();
    }

    #pragma unroll
    for (int ki = 0; ki < 6; ki++) {
        if (ki < 5) {
            const int kn = (ki + 1) * 32;
            const int bf = (ki + 1) & 1;
            const ushort_t* bh = &Bhi[(kn + rB) * NPIX + bn + cB];
            CPA16(dstBh[bf], bh); CPA16(dstBh[bf] + 128, bh + 64);
            CPA16(dstAh[bf], &Ahi[(bm + rA) * GK + kn + cA]);
            CPC();
            CPW1();
        } else {
            CPW0();
        }
        __syncthreads();

        const int buf = ki & 1;
        #pragma unroll
        for (int hh = 0; hh < 2; hh++) {
            uint32_t ah[4];
            ldsm4(ah[0], ah[1], ah[2], ah[3], sah_base[buf] + hh * 32);

            const uint32_t hoff = (uint32_t)(hh * 16 * Q_BSTR) * 2;
            #pragma unroll
            for (int j = 0; j < 4; j++) {
                uint32_t off = hoff + (uint32_t)(j * 16) * 2;
                uint32_t bh0, bh1, bh2, bh3;
                ldsm4t(bh0, bh1, bh2, bh3, sbh_base[buf] + off);
                mma_f16(acc[2 * j],     ah[0], ah[1], ah[2], ah[3], bh0, bh1);
                mma_f16(acc[2 * j + 1], ah[0], ah[1], ah[2], ah[3], bh2, bh3);
            }
        }
        __syncthreads();
    }

    const float b0 = bias[row0], b1 = bias[row1];
    #pragma unroll
    for (int nf = 0; nf < 8; nf++) {
        int col = bn + wc + nf * 8 + 2 * q;
        *(float2*)&C[row0 * NPIX + col] = make_float2(acc[nf][0] + b0, acc[nf][1] + b0);
        *(float2*)&C[row1 * NPIX + col] = make_float2(acc[nf][2] + b1, acc[nf][3] + b1);
    }
}

// ---------------- proj GEMM: bf16 3-term (exact path) ----------------
#define G_SBH 0
#define G_SBL 8704
#define G_SAH 17408
#define G_SAL 22528
#define G_BSTR 136
#define G_BBUF 4352
#define G_ASTR 40
#define G_ABUF 2560
#define G_TOTAL_BYTES 55296

__global__ __launch_bounds__(256) void gemm_mma(
    const ushort_t* __restrict__ Ahi, const ushort_t* __restrict__ Alo,
    const ushort_t* __restrict__ Bhi, const ushort_t* __restrict__ Blo,
    const float* __restrict__ bias, float* __restrict__ C)
{
    extern __shared__ ushort_t gsm[];
    const int tid = threadIdx.x;
    const int bn = blockIdx.x * 128, bm = blockIdx.y * 64;
    const int wid = tid >> 5, lane = tid & 31;
    const int wm = wid & 3, wn = wid >> 2;
    const int g = lane >> 2, q = lane & 3;
    const int wc = wn * 64;
    const int row0 = bm + wm * 16 + g;
    const int row1 = row0 + 8;

    float acc[8][4];
    #pragma unroll
    for (int i = 0; i < 8; i++)
        #pragma unroll
        for (int j = 0; j < 4; j++) acc[i][j] = 0.f;

    const int rB = tid >> 3;
    const int cB = (tid & 7) * 8;
    const int rA = tid >> 2;
    const int cA = (tid & 3) * 8;

    uint32_t smb = s2u(gsm);
    uint32_t dstBh[2], dstBl[2], dstAh[2], dstAl[2];
    #pragma unroll
    for (int b = 0; b < 2; b++) {
        dstBh[b] = smb + (uint32_t)((G_SBH + b * G_BBUF + rB * G_BSTR + cB) * 2);
        dstBl[b] = smb + (uint32_t)((G_SBL + b * G_BBUF + rB * G_BSTR + cB) * 2);
        dstAh[b] = smb + (uint32_t)((G_SAH + b * G_ABUF + rA * G_ASTR + cA) * 2);
        dstAl[b] = smb + (uint32_t)((G_SAL + b * G_ABUF + rA * G_ASTR + cA) * 2);
    }

    const int lm = lane >> 3, lr = lane & 7;
    const int lkrow = (lm & 1) * 8 + lr;
    const int lncol = wc + (lm >> 1) * 8;
    const int arow = wm * 16 + (lm & 1) * 8 + lr;
    const int acol = (lane >> 4) * 8;
    uint32_t sbh_base[2], sbl_base[2], sah_base[2], sal_base[2];
    #pragma unroll
    for (int b = 0; b < 2; b++) {
        sbh_base[b] = smb + (uint32_t)((G_SBH + b * G_BBUF + lkrow * G_BSTR + lncol) * 2);
        sbl_base[b] = smb + (uint32_t)((G_SBL + b * G_BBUF + lkrow * G_BSTR + lncol) * 2);
        sah_base[b] = smb + (uint32_t)((G_SAH + b * G_ABUF + arow * G_ASTR + acol) * 2);
        sal_base[b] = smb + (uint32_t)((G_SAL + b * G_ABUF + arow * G_ASTR + acol) * 2);
    }

    {
        const ushort_t* bh = &Bhi[rB * NPIX + bn + cB];
        const ushort_t* bl = &Blo[rB * NPIX + bn + cB];
        CPA16(dstBh[0], bh); CPA16(dstBh[0] + 128, bh + 64);
        CPA16(dstBl[0], bl); CPA16(dstBl[0] + 128, bl + 64);
        CPA16(dstAh[0], &Ahi[(bm + rA) * GK + cA]);
        CPA16(dstAl[0], &Alo[(bm + rA) * GK + cA]);
        CPC();
    }

    #pragma unroll
    for (int ki = 0; ki < 6; ki++) {
        if (ki < 5) {
            const int kn = (ki + 1) * 32;
            const int bf = (ki + 1) & 1;
            const ushort_t* bh = &Bhi[(kn + rB) * NPIX + bn + cB];
            const ushort_t* bl = &Blo[(kn + rB) * NPIX + bn + cB];
            CPA16(dstBh[bf], bh); CPA16(dstBh[bf] + 128, bh + 64);
            CPA16(dstBl[bf], bl); CPA16(dstBl[bf] + 128, bl + 64);
            CPA16(dstAh[bf], &Ahi[(bm + rA) * GK + kn + cA]);
            CPA16(dstAl[bf], &Alo[(bm + rA) * GK + kn + cA]);
            CPC();
            CPW1();
        } else {
            CPW0();
        }
        __syncthreads();

        const int buf = ki & 1;
        #pragma unroll
        for (int hh = 0; hh < 2; hh++) {
            uint32_t ah[4], al[4];
            ldsm4(ah[0], ah[1], ah[2], ah[3], sah_base[buf] + hh * 32);
            ldsm4(al[0], al[1], al[2], al[3], sal_base[buf] + hh * 32);

            const uint32_t hoff = (uint32_t)(hh * 16 * G_BSTR) * 2;
            #pragma unroll
            for (int j = 0; j < 4; j++) {
                uint32_t off = hoff + (uint32_t)(j * 16) * 2;
                uint32_t bh0, bh1, bh2, bh3, bl0, bl1, bl2, bl3;
                ldsm4t(bh0, bh1, bh2, bh3, sbh_base[buf] + off);
                ldsm4t(bl0, bl1, bl2, bl3, sbl_base[buf] + off);
                float* c0 = acc[2 * j];
                float* c1 = acc[2 * j + 1];
                mma_bf16(c0, ah[0], ah[1], ah[2], ah[3], bh0, bh1);
                mma_bf16(c0, al[0], al[1], al[2], al[3], bh0, bh1);
                mma_bf16(c0, ah[0], ah[1], ah[2], ah[3], bl0, bl1);
                mma_bf16(c1, ah[0], ah[1], ah[2], ah[3], bh2, bh3);
                mma_bf16(c1, al[0], al[1], al[2], al[3], bh2, bh3);
                mma_bf16(c1, ah[0], ah[1], ah[2], ah[3], bl2, bl3);
            }
        }
        __syncthreads();
    }

    const float b0 = bias[row0], b1 = bias[row1];
    #pragma unroll
    for (int nf = 0; nf < 8; nf++) {
        int col = bn + wc + nf * 8 + 2 * q;
        *(float2*)&C[row0 * NPIX + col] = make_float2(acc[nf][0] + b0, acc[nf][1] + b0);
        *(float2*)&C[row1 * NPIX + col] = make_float2(acc[nf][2] + b1, acc[nf][3] + b1);
    }
}

// ============================================================================
// fp16 flash attention — pipelined, softmax via ex2.approx.f16x2
// ============================================================================
#define KSTR 40
#define VSTRF 792
#define NW    12
#define NTHR  384

#define A_SKH 0
#define A_SVH (A_SKH + LTOK * KSTR * 2)          // 62720
#define A_SB  (A_SVH + HDIM * VSTRF * 2)         // 100736
#define A_TOTAL (A_SB + 256)

__global__ __launch_bounds__(NTHR, 2) void attn_mma(
    const float* __restrict__ tab_h, const float* __restrict__ tab_v)
{
    extern __shared__ char asm_[];
    ushort_t* sKhi = (ushort_t*)(asm_ + A_SKH);
    ushort_t* sVhi = (ushort_t*)(asm_ + A_SVH);
    float* sb = (float*)(asm_ + A_SB);

    const int tid = threadIdx.x;
    const int w = blockIdx.x, h = blockIdx.y, br = blockIdx.z;
    const float* __restrict__ qkv = br ? g_qkv_v : g_qkv_h;
    float* __restrict__ outp = br ? g_att_v : g_att_h;
    const float* __restrict__ tab = br ? tab_v : tab_h;

    if (tid < 49) {
        int r1 = tid / 7, r2 = tid % 7, off = r1 - r2 + 6;
        float bv = br ? tab[(6 * 13 + off) * NHEAD + h]
                      : tab[(off * 13 + 6) * NHEAD + h];
        sb[tid] = bv * LOG2E;
    }
    for (int i = tid; i < LTOK * 8; i += NTHR) {
        int k = i >> 3, d = 24 + (i & 7);
        sKhi[k * KSTR + d] = 0;
    }
    if (tid < HDIM * 8) {
        int d = tid >> 3, k = LTOK + (tid & 7);
        sVhi[d * VSTRF + k] = 0;
    }
    for (int idx = tid; idx < LTOK * HDIM; idx += NTHR) {
        int d = idx / LTOK, k = idx - d * LTOK;
        int pix = br ? ((k / 7) * 112 + w * 7 + (k % 7)) : (w * LTOK + k);
        float kv = qkv[(192 + h * HDIM + d) * HWPIX + pix];
        float vv = qkv[(384 + h * HDIM + d) * HWPIX + pix];
        sKhi[k * KSTR + d] = __half_as_ushort(__float2half_rn(kv));
        sVhi[d * VSTRF + k] = __half_as_ushort(__float2half_rn(vv));
    }
    __syncthreads();

    const int warp = tid >> 5, lane = tid & 31;
    const int g = lane >> 2, q = lane & 3;
    const int d0 = 2 * q;
    const int lr = lane & 7;

    const uint32_t kln = (uint32_t)((lr * KSTR + (lane >> 3) * 8) * 2);
    const uint32_t skh_b = s2u(sKhi) + kln;
    const int vko = ((lane >> 3) & 1) * 8;
    const int vdh = ((lane >> 4) & 1) * 8 + lr;
    const uint32_t sv4 = s2u(sVhi) + (uint32_t)((vdh * VSTRF + vko) * 2);
    const uint32_t sv2a = s2u(sVhi) + (uint32_t)(((16 + lr) * VSTRF + vko) * 2);

    const float qscale = SCALE_F * LOG2E;

    for (int mt = warp; mt < 49; mt += NW) {
        const int r0 = mt * 16 + g, r1 = r0 + 8;
        const int pix0 = br ? ((r0 / 7) * 112 + w * 7 + (r0 % 7)) : (w * LTOK + r0);
        const int pix1 = br ? ((r1 / 7) * 112 + w * 7 + (r1 % 7)) : (w * LTOK + r1);
        const int bro0 = (br ? (r0 % 7) : (r0 / 112)) * 7;
        const int bro1 = (br ? (r1 % 7) : (r1 / 112)) * 7;

        uint32_t qh[6];
        #pragma unroll
        for (int p = 0; p < 3; p++) {
            int d = d0 + 8 * p;
            float a0v = qkv[(h * HDIM + d)     * HWPIX + pix0] * qscale;
            float a1v = qkv[(h * HDIM + d + 1) * HWPIX + pix0] * qscale;
            float b0v = qkv[(h * HDIM + d)     * HWPIX + pix1] * qscale;
            float b1v = qkv[(h * HDIM + d + 1) * HWPIX + pix1] * qscale;
            qh[2 * p]     = hfp(a0v, a1v);
            qh[2 * p + 1] = hfp(b0v, b1v);
        }

        float o[3][4];
        #pragma unroll
        for (int nd = 0; nd < 3; nd++)
            #pragma unroll
            for (int i = 0; i < 4; i++) o[nd][i] = 0.f;
        float rs0 = 0.f, rs1 = 0.f;

        float sA[4] = {0.f, 0.f, 0.f, 0.f};
        float sB[4] = {0.f, 0.f, 0.f, 0.f};
        {
            uint32_t h0, h1, h2, h3;
            ldsm4(h0, h1, h2, h3, skh_b);
            mma_f16(sA, qh[0], qh[1], qh[2], qh[3], h0, h1);
            mma_f16_k8(sA, qh[4], qh[5], h2);
            ldsm4(h0, h1, h2, h3, skh_b + (uint32_t)(8 * KSTR * 2));
            mma_f16(sB, qh[0], qh[1], qh[2], qh[3], h0, h1);
            mma_f16_k8(sB, qh[4], qh[5], h2);
        }

        #pragma unroll 4
        for (int s = 0; s < 56; s++) {
            const int kt = s >> 2, ks = s & 3;
            const int kbase = kt * 56;
            const int nt0 = 2 * ks;
            const bool has1 = (ks != 3);

            float nA[4] = {0.f, 0.f, 0.f, 0.f};
            float nB[4] = {0.f, 0.f, 0.f, 0.f};
            if (s < 55) {
                const int s1 = s + 1;
                const int kb1 = (s1 >> 2) * 56;
                const int ns0 = 2 * (s1 & 3);
                uint32_t ko = (uint32_t)((kb1 + ns0 * 8) * KSTR * 2);
                uint32_t h0, h1, h2, h3;
                ldsm4(h0, h1, h2, h3, skh_b + ko);
                mma_f16(nA, qh[0], qh[1], qh[2], qh[3], h0, h1);
                mma_f16_k8(nA, qh[4], qh[5], h2);
                if ((s1 & 3) != 3) {
                    ko = (uint32_t)((kb1 + (ns0 + 1) * 8) * KSTR * 2);
                    ldsm4(h0, h1, h2, h3, skh_b + ko);
                    mma_f16(nB, qh[0], qh[1], qh[2], qh[3], h0, h1);
                    mma_f16_k8(nB, qh[4], qh[5], h2);
                }
            }

            // softmax: fp32 bias add -> pack f16x2 -> ex2.f16x2 (result = P frag)
            uint32_t pa0, pa1, pa2 = 0u, pa3 = 0u;
            if (!br) {
                float bh0 = sb[bro0 + (kt >> 1)];
                float bh1 = sb[bro1 + (kt >> 1)];
                pa0 = hex2(hfp(sA[0] + bh0, sA[1] + bh0));
                pa1 = hex2(hfp(sA[2] + bh1, sA[3] + bh1));
                if (has1) {
                    pa2 = hex2(hfp(sB[0] + bh0, sB[1] + bh0));
                    pa3 = hex2(hfp(sB[2] + bh1, sB[3] + bh1));
                }
            } else {
                int i0 = (nt0 + d0) % 7;
                int i1 = i0 + 1; if (i1 == 7) i1 = 0;
                int j1 = i1 + 1; if (j1 == 7) j1 = 0;
                pa0 = hex2(hfp(sA[0] + sb[bro0 + i0], sA[1] + sb[bro0 + i1]));
                pa1 = hex2(hfp(sA[2] + sb[bro1 + i0], sA[3] + sb[bro1 + i1]));
                if (has1) {
                    pa2 = hex2(hfp(sB[0] + sb[bro0 + i1], sB[1] + sb[bro0 + j1]));
                    pa3 = hex2(hfp(sB[2] + sb[bro1 + i1], sB[3] + sb[bro1 + j1]));
                }
            }
            // row sums: HADD2 pair-tree, fp32 flush
            uint32_t t0 = hadd2u(pa0, pa2);
            uint32_t t1 = hadd2u(pa1, pa3);
            rs0 += h2lo(t0) + h2hi(t0);
            rs1 += h2lo(t1) + h2hi(t1);

            {
                uint32_t vo = (uint32_t)((kbase + ks * 16) * 2);
                uint32_t va0, va1, va2, va3, vx0, vx1;
                ldsm4(va0, va1, va2, va3, sv4 + vo);
                ldsm2(vx0, vx1, sv2a + vo);
                mma_f16(o[0], pa0, pa1, pa2, pa3, va0, va1);
                mma_f16(o[1], pa0, pa1, pa2, pa3, va2, va3);
                mma_f16(o[2], pa0, pa1, pa2, pa3, vx0, vx1);
            }

            #pragma unroll
            for (int i = 0; i < 4; i++) { sA[i] = nA[i]; sB[i] = nB[i]; }
        }

        float a0 = rs0, a1 = rs1;
        a0 += __shfl_xor_sync(0xFFFFFFFFu, a0, 1);
        a0 += __shfl_xor_sync(0xFFFFFFFFu, a0, 2);
        a1 += __shfl_xor_sync(0xFFFFFFFFu, a1, 1);
        a1 += __shfl_xor_sync(0xFFFFFFFFu, a1, 2);
        float inv0 = 1.f / a0, inv1 = 1.f / a1;
        #pragma unroll
        for (int nd = 0; nd < 3; nd++) {
            int d = nd * 8 + d0;
            outp[(h * HDIM + d)     * HWPIX + pix0] = o[nd][0] * inv0;
            outp[(h * HDIM + d + 1) * HWPIX + pix0] = o[nd][1] * inv0;
            outp[(h * HDIM + d)     * HWPIX + pix1] = o[nd][2] * inv1;
            outp[(h * HDIM + d + 1) * HWPIX + pix1] = o[nd][3] * inv1;
        }
    }
}

// ---------------- fused dual LePE -> 0.5*(h+v) -> bf16 hi/lo planes ----------------
__global__ __launch_bounds__(256) void lepe_fused(
    const float* __restrict__ attH, const float* __restrict__ attV,
    const float* __restrict__ wH, const float* __restrict__ bH,
    const float* __restrict__ wV, const float* __restrict__ bV,
    ushort_t* __restrict__ phi, ushort_t* __restrict__ plo)
{
    int t = blockIdx.x * blockDim.x + threadIdx.x;
    if (t >= Cdim * (HWPIX / 4)) return;
    int c = t / (HWPIX / 4);
    int r = t % (HWPIX / 4);
    int y = r / 28, x4 = (r % 28) * 4;
    const float* baseH = attH + c * HWPIX;
    const float* baseV = attV + c * HWPIX;

    float wvh[9], wvv[9];
    #pragma unroll
    for (int i = 0; i < 9; i++) { wvh[i] = wH[c * 9 + i]; wvv[i] = wV[c * 9 + i]; }
    float ah0 = bH[c], ah1 = ah0, ah2 = ah0, ah3 = ah0;
    float av0 = bV[c], av1 = av0, av2 = av0, av3 = av0;

    #pragma unroll
    for (int ky = 0; ky < 3; ky++) {
        int yy = y + ky - 1;
        if (yy < 0 || yy >= 112) continue;
        const float* rpH = baseH + yy * 112 + x4;
        const float* rpV = baseV + yy * 112 + x4;
        float4 mH = *(const float4*)rpH;
        float4 mV = *(const float4*)rpV;
        float lfH = (x4 > 0)   ? rpH[-1] : 0.f;
        float rtH = (x4 < 108) ? rpH[4]  : 0.f;
        float lfV = (x4 > 0)   ? rpV[-1] : 0.f;
        float rtV = (x4 < 108) ? rpV[4]  : 0.f;
        float h0 = wvh[ky*3], h1 = wvh[ky*3+1], h2 = wvh[ky*3+2];
        float v0 = wvv[ky*3], v1 = wvv[ky*3+1], v2 = wvv[ky*3+2];
        ah0 += h0 * lfH  + h1 * mH.x + h2 * mH.y;
        ah1 += h0 * mH.x + h1 * mH.y + h2 * mH.z;
        ah2 += h0 * mH.y + h1 * mH.z + h2 * mH.w;
        ah3 += h0 * mH.z + h1 * mH.w + h2 * rtH;
        av0 += v0 * lfV  + v1 * mV.x + v2 * mV.y;
        av1 += v0 * mV.x + v1 * mV.y + v2 * mV.z;
        av2 += v0 * mV.y + v1 * mV.z + v2 * mV.w;
        av3 += v0 * mV.z + v1 * mV.w + v2 * rtV;
    }

    float4 inH = *(const float4*)(baseH + y * 112 + x4);
    float4 inV = *(const float4*)(baseV + y * 112 + x4);
    const float RS2 = 0.70710678118654752f;
    float oh0 = inH.x + 0.5f * ah0 * (1.f + erff(ah0 * RS2));
    float oh1 = inH.y + 0.5f * ah1 * (1.f + erff(ah1 * RS2));
    float oh2 = inH.z + 0.5f * ah2 * (1.f + erff(ah2 * RS2));
    float oh3 = inH.w + 0.5f * ah3 * (1.f + erff(ah3 * RS2));
    float ov0 = inV.x + 0.5f * av0 * (1.f + erff(av0 * RS2));
    float ov1 = inV.y + 0.5f * av1 * (1.f + erff(av1 * RS2));
    float ov2 = inV.z + 0.5f * av2 * (1.f + erff(av2 * RS2));
    float ov3 = inV.w + 0.5f * av3 * (1.f + erff(av3 * RS2));

    float p0 = 0.5f * (oh0 + ov0);
    float p1 = 0.5f * (oh1 + ov1);
    float p2 = 0.5f * (oh2 + ov2);
    float p3 = 0.5f * (oh3 + ov3);

    uint32_t h0w = bfp(p0, p1), h1w = bfp(p2, p3);
    uint32_t l0w = bfp(p0 - bflo(h0w), p1 - bfhi(h0w));
    uint32_t l1w = bfp(p2 - bflo(h1w), p3 - bfhi(h1w));
    int idx = c * HWPIX + y * 112 + x4;
    *(uint2*)&phi[idx] = make_uint2(h0w, h1w);
    *(uint2*)&plo[idx] = make_uint2(l0w, l1w);
}

// ---------------- launch ----------------
extern "C" void kernel_launch(void* const* d_in, const int* in_sizes, int n_in,
                              void* d_out, int out_size)
{
    const float* x        = (const float*)d_in[0];
    const float* qkv_h_w  = (const float*)d_in[1];
    const float* qkv_h_b  = (const float*)d_in[2];
    const float* qkv_v_w  = (const float*)d_in[3];
    const float* qkv_v_b  = (const float*)d_in[4];
    const float* proj_w   = (const float*)d_in[5];
    const float* proj_b   = (const float*)d_in[6];
    const float* lepe_h_w = (const float*)d_in[7];
    const float* lepe_h_b = (const float*)d_in[8];
    const float* lepe_v_w = (const float*)d_in[9];
    const float* lepe_v_b = (const float*)d_in[10];
    const float* tab_h    = (const float*)d_in[11];
    const float* tab_v    = (const float*)d_in[12];
    float* out = (float*)d_out;

    float *qh, *qv, *ah, *av;
    ushort_t *xhi, *phi, *plo, *whh, *wvh, *pwh, *pwl;
    cudaGetSymbolAddress((void**)&qh, g_qkv_h);
    cudaGetSymbolAddress((void**)&qv, g_qkv_v);
    cudaGetSymbolAddress((void**)&ah, g_att_h);
    cudaGetSymbolAddress((void**)&av, g_att_v);
    cudaGetSymbolAddress((void**)&xhi, g_xhi);
    cudaGetSymbolAddress((void**)&phi, g_phi);
    cudaGetSymbolAddress((void**)&plo, g_plo);
    cudaGetSymbolAddress((void**)&whh, g_whh);
    cudaGetSymbolAddress((void**)&wvh, g_wvh);
    cudaGetSymbolAddress((void**)&pwh, g_pwh);
    cudaGetSymbolAddress((void**)&pwl, g_pwl);

    int nx4 = GK * NPIX / 4;
    int nw4 = M_QKV * GK / 4;
    int np4 = M_PROJ * GK / 4;
    int ntot = nx4 + nw4 * 2 + np4;
    split_all<<<(ntot + 255) / 256, 256>>>(
        (const float4*)x,       (uint2*)xhi, nx4,
        (const float4*)qkv_h_w, (uint2*)whh, nw4,
        (const float4*)qkv_v_w, (uint2*)wvh, nw4,
        (const float4*)proj_w,  (uint2*)pwh, (uint2*)pwl, np4);

    cudaFuncSetAttribute(gemm_qkv,
                         cudaFuncAttributeMaxDynamicSharedMemorySize, Q_TOTAL_BYTES);
    dim3 gq(NPIX / 128, M_QKV / 64, 2);
    gemm_qkv<<<gq, 256, Q_TOTAL_BYTES>>>(whh, wvh, xhi,
                                         qkv_h_b, qkv_v_b, qh, qv);

    cudaFuncSetAttribute(attn_mma,
                         cudaFuncAttributeMaxDynamicSharedMemorySize, A_TOTAL);
    dim3 ga(16, NHEAD, 2);
    attn_mma<<<ga, NTHR, A_TOTAL>>>(tab_h, tab_v);

    int nthr = Cdim * (HWPIX / 4);
    lepe_fused<<<(nthr + 255) / 256, 256>>>(ah, av, lepe_h_w, lepe_h_b,
                                            lepe_v_w, lepe_v_b, phi, plo);

    cudaFuncSetAttribute(gemm_mma,
                         cudaFuncAttributeMaxDynamicSharedMemorySize, G_TOTAL_BYTES);
    dim3 gp(NPIX / 128, M_PROJ / 64);
    gemm_mma<<<gp, 256, G_TOTAL_BYTES>>>(pwh, pwl, phi, plo, proj_b, out);
}

// round 17
// speedup vs baseline: 1.9319x; 1.0119x over previous
#include <cuda_runtime.h>
#include <cuda_bf16.h>
#include <cuda_fp16.h>
#include <cstdint>
#include <math.h>

#define Cdim   192
#define NHEAD  8
#define HDIM   24
#define HWPIX  12544          // 112*112
#define LTOK   784            // 7*112
#define GK     192            // gemm K
#define NPIX   12544
#define M_QKV  576
#define M_PROJ 192
#define SCALE_F 0.20412414523193154f  // 24^-0.5
#define LOG2E   1.44269504088896340736f

typedef unsigned short ushort_t;

// ---------------- scratch (device globals; no allocation) ----------------
__device__ ushort_t g_qkv_h[M_QKV * HWPIX];     // fp16
__device__ ushort_t g_qkv_v[M_QKV * HWPIX];     // fp16
__device__ ushort_t g_att_h[Cdim * HWPIX];      // fp16
__device__ ushort_t g_att_v[Cdim * HWPIX];      // fp16
__device__ ushort_t g_xhi[GK * NPIX];           // fp16
__device__ ushort_t g_phi[GK * NPIX];           // bf16 (lepe out)
__device__ ushort_t g_plo[GK * NPIX];
__device__ ushort_t g_whh[M_QKV * GK];          // fp16 hi
__device__ ushort_t g_wvh[M_QKV * GK];
__device__ ushort_t g_pwh[M_PROJ * GK];         // bf16 hi
__device__ ushort_t g_pwl[M_PROJ * GK];

// ---------------- helpers ----------------
__device__ __forceinline__ uint32_t bfp(float lo_el, float hi_el) {
    uint32_t r;
    asm("cvt.rn.bf16x2.f32 %0, %1, %2;" : "=r"(r) : "f"(hi_el), "f"(lo_el));
    return r;
}
__device__ __forceinline__ float bflo(uint32_t p) { return __uint_as_float(p << 16); }
__device__ __forceinline__ float bfhi(uint32_t p) { return __uint_as_float(p & 0xFFFF0000u); }

__device__ __forceinline__ uint32_t s2u(const void* p) {
    uint32_t a;
    asm("{ .reg .u64 t; cvta.to.shared.u64 t, %1; cvt.u32.u64 %0, t; }" : "=r"(a) : "l"(p));
    return a;
}
__device__ __forceinline__ uint32_t hfp(float lo_el, float hi_el) {
    uint32_t r;
    asm("cvt.rn.f16x2.f32 %0, %1, %2;" : "=r"(r) : "f"(hi_el), "f"(lo_el));
    return r;
}
__device__ __forceinline__ uint32_t hex2(uint32_t x) {
    uint32_t r;
    asm("ex2.approx.f16x2 %0, %1;" : "=r"(r) : "r"(x));
    return r;
}
__device__ __forceinline__ uint32_t hadd2u(uint32_t a, uint32_t b) {
    uint32_t r;
    asm("add.rn.f16x2 %0, %1, %2;" : "=r"(r) : "r"(a), "r"(b));
    return r;
}
__device__ __forceinline__ float h2lo(uint32_t p) {
    return __half2float(__ushort_as_half((ushort_t)(p & 0xFFFFu)));
}
__device__ __forceinline__ float h2hi(uint32_t p) {
    return __half2float(__ushort_as_half((ushort_t)(p >> 16)));
}
__device__ __forceinline__ float h2f(ushort_t u) {
    return __half2float(__ushort_as_half(u));
}

__device__ __forceinline__ void mma_bf16(float* c,
    uint32_t a0, uint32_t a1, uint32_t a2, uint32_t a3,
    uint32_t b0, uint32_t b1)
{
    asm volatile("mma.sync.aligned.m16n8k16.row.col.f32.bf16.bf16.f32 "
        "{%0,%1,%2,%3}, {%4,%5,%6,%7}, {%8,%9}, {%0,%1,%2,%3};"
        : "+f"(c[0]), "+f"(c[1]), "+f"(c[2]), "+f"(c[3])
        : "r"(a0), "r"(a1), "r"(a2), "r"(a3), "r"(b0), "r"(b1));
}
__device__ __forceinline__ void mma_f16(float* c,
    uint32_t a0, uint32_t a1, uint32_t a2, uint32_t a3,
    uint32_t b0, uint32_t b1)
{
    asm volatile("mma.sync.aligned.m16n8k16.row.col.f32.f16.f16.f32 "
        "{%0,%1,%2,%3}, {%4,%5,%6,%7}, {%8,%9}, {%0,%1,%2,%3};"
        : "+f"(c[0]), "+f"(c[1]), "+f"(c[2]), "+f"(c[3])
        : "r"(a0), "r"(a1), "r"(a2), "r"(a3), "r"(b0), "r"(b1));
}
__device__ __forceinline__ void mma_f16_k8(float* c,
    uint32_t a0, uint32_t a1, uint32_t b0)
{
    asm volatile("mma.sync.aligned.m16n8k8.row.col.f32.f16.f16.f32 "
        "{%0,%1,%2,%3}, {%4,%5}, {%6}, {%0,%1,%2,%3};"
        : "+f"(c[0]), "+f"(c[1]), "+f"(c[2]), "+f"(c[3])
        : "r"(a0), "r"(a1), "r"(b0));
}

__device__ __forceinline__ void ldsm4t(uint32_t& r0, uint32_t& r1,
                                       uint32_t& r2, uint32_t& r3, uint32_t a)
{
    asm volatile("ldmatrix.sync.aligned.m8n8.x4.trans.shared.b16 {%0,%1,%2,%3}, [%4];"
        : "=r"(r0), "=r"(r1), "=r"(r2), "=r"(r3) : "r"(a));
}
__device__ __forceinline__ void ldsm4(uint32_t& r0, uint32_t& r1,
                                      uint32_t& r2, uint32_t& r3, uint32_t a)
{
    asm volatile("ldmatrix.sync.aligned.m8n8.x4.shared.b16 {%0,%1,%2,%3}, [%4];"
        : "=r"(r0), "=r"(r1), "=r"(r2), "=r"(r3) : "r"(a));
}
__device__ __forceinline__ void ldsm2(uint32_t& r0, uint32_t& r1, uint32_t a)
{
    asm volatile("ldmatrix.sync.aligned.m8n8.x2.shared.b16 {%0,%1}, [%2];"
        : "=r"(r0), "=r"(r1) : "r"(a));
}

#define CPA16(dst, src) asm volatile("cp.async.ca.shared.global [%0], [%1], 16;" :: "r"(dst), "l"(src) : "memory")
#define CPC()  asm volatile("cp.async.commit_group;" ::: "memory")
#define CPW1() asm volatile("cp.async.wait_group 1;" ::: "memory")
#define CPW0() asm volatile("cp.async.wait_group 0;" ::: "memory")

// ---------------- combined split (one launch) ----------------
__global__ __launch_bounds__(256) void split_all(
    const float4* __restrict__ sx, uint2* __restrict__ xh, int n0,
    const float4* __restrict__ w1, uint2* __restrict__ h1p, int n1,
    const float4* __restrict__ w2, uint2* __restrict__ h2p, int n2,
    const float4* __restrict__ w3, uint2* __restrict__ h3p, uint2* __restrict__ l3p, int n3)
{
    int i = blockIdx.x * blockDim.x + threadIdx.x;
    int j = i;
    if (j < n0) {
        float4 v = sx[j];
        xh[j] = make_uint2(hfp(v.x, v.y), hfp(v.z, v.w));
        return;
    }
    j -= n0;
    if (j < n1 + n2) {
        const float4* src; uint2* hd;
        if (j < n1) { src = w1; hd = h1p; }
        else { j -= n1; src = w2; hd = h2p; }
        float4 v = src[j];
        hd[j] = make_uint2(hfp(v.x, v.y), hfp(v.z, v.w));
        return;
    }
    j -= n1 + n2;
    if (j < n3) {
        float4 v = w3[j];
        uint32_t h0 = bfp(v.x, v.y);
        uint32_t h1 = bfp(v.z, v.w);
        uint32_t l0 = bfp(v.x - bflo(h0), v.y - bfhi(h0));
        uint32_t l1 = bfp(v.z - bflo(h1), v.w - bfhi(h1));
        h3p[j] = make_uint2(h0, h1);
        l3p[j] = make_uint2(l0, l1);
    }
}

// ---------------- QKV GEMM: single-term fp16 Whi·Xhi -> fp16 out ----------------
#define Q_SBH 0
#define Q_SAH 8704
#define Q_BSTR 136
#define Q_BBUF 4352
#define Q_ASTR 40
#define Q_ABUF 2560
#define Q_TOTAL_BYTES 27648

__global__ __launch_bounds__(256) void gemm_qkv(
    const ushort_t* __restrict__ Ah0, const ushort_t* __restrict__ Ah1,
    const ushort_t* __restrict__ Bhi,
    const float* __restrict__ bias0, const float* __restrict__ bias1,
    ushort_t* __restrict__ C0, ushort_t* __restrict__ C1)
{
    extern __shared__ ushort_t gsm[];
    const ushort_t* __restrict__ Ahi = blockIdx.z ? Ah1 : Ah0;
    const float* __restrict__ bias = blockIdx.z ? bias1 : bias0;
    ushort_t* __restrict__ C = blockIdx.z ? C1 : C0;

    const int tid = threadIdx.x;
    const int bn = blockIdx.x * 128, bm = blockIdx.y * 64;
    const int wid = tid >> 5, lane = tid & 31;
    const int wm = wid & 3, wn = wid >> 2;
    const int g = lane >> 2, q = lane & 3;
    const int wc = wn * 64;
    const int row0 = bm + wm * 16 + g;
    const int row1 = row0 + 8;

    float acc[8][4];
    #pragma unroll
    for (int i = 0; i < 8; i++)
        #pragma unroll
        for (int j = 0; j < 4; j++) acc[i][j] = 0.f;

    const int rB = tid >> 3;
    const int cB = (tid & 7) * 8;
    const int rA = tid >> 2;
    const int cA = (tid & 3) * 8;

    uint32_t smb = s2u(gsm);
    uint32_t dstBh[2], dstAh[2];
    #pragma unroll
    for (int b = 0; b < 2; b++) {
        dstBh[b] = smb + (uint32_t)((Q_SBH + b * Q_BBUF + rB * Q_BSTR + cB) * 2);
        dstAh[b] = smb + (uint32_t)((Q_SAH + b * Q_ABUF + rA * Q_ASTR + cA) * 2);
    }

    const int lm = lane >> 3, lr = lane & 7;
    const int lkrow = (lm & 1) * 8 + lr;
    const int lncol = wc + (lm >> 1) * 8;
    const int arow = wm * 16 + (lm & 1) * 8 + lr;
    const int acol = (lane >> 4) * 8;
    uint32_t sbh_base[2], sah_base[2];
    #pragma unroll
    for (int b = 0; b < 2; b++) {
        sbh_base[b] = smb + (uint32_t)((Q_SBH + b * Q_BBUF + lkrow * Q_BSTR + lncol) * 2);
        sah_base[b] = smb + (uint32_t)((Q_SAH + b * Q_ABUF + arow * Q_ASTR + acol) * 2);
    }

    {
        const ushort_t* bh = &Bhi[rB * NPIX + bn + cB];
        CPA16(dstBh[0], bh); CPA16(dstBh[0] + 128, bh + 64);
        CPA16(dstAh[0], &Ahi[(bm + rA) * GK + cA]);
        CPC();
    }

    #pragma unroll
    for (int ki = 0; ki < 6; ki++) {
        if (ki < 5) {
            const int kn = (ki + 1) * 32;
            const int bf = (ki + 1) & 1;
            const ushort_t* bh = &Bhi[(kn + rB) * NPIX + bn + cB];
            CPA16(dstBh[bf], bh); CPA16(dstBh[bf] + 128, bh + 64);
            CPA16(dstAh[bf], &Ahi[(bm + rA) * GK + kn + cA]);
            CPC();
            CPW1();
        } else {
            CPW0();
        }
        __syncthreads();

        const int buf = ki & 1;
        #pragma unroll
        for (int hh = 0; hh < 2; hh++) {
            uint32_t ah[4];
            ldsm4(ah[0], ah[1], ah[2], ah[3], sah_base[buf] + hh * 32);

            const uint32_t hoff = (uint32_t)(hh * 16 * Q_BSTR) * 2;
            #pragma unroll
            for (int j = 0; j < 4; j++) {
                uint32_t off = hoff + (uint32_t)(j * 16) * 2;
                uint32_t bh0, bh1, bh2, bh3;
                ldsm4t(bh0, bh1, bh2, bh3, sbh_base[buf] + off);
                mma_f16(acc[2 * j],     ah[0], ah[1], ah[2], ah[3], bh0, bh1);
                mma_f16(acc[2 * j + 1], ah[0], ah[1], ah[2], ah[3], bh2, bh3);
            }
        }
        __syncthreads();
    }

    const float b0 = bias[row0], b1 = bias[row1];
    #pragma unroll
    for (int nf = 0; nf < 8; nf++) {
        int col = bn + wc + nf * 8 + 2 * q;
        *(uint32_t*)&C[row0 * NPIX + col] = hfp(acc[nf][0] + b0, acc[nf][1] + b0);
        *(uint32_t*)&C[row1 * NPIX + col] = hfp(acc[nf][2] + b1, acc[nf][3] + b1);
    }
}

// ---------------- proj GEMM: bf16 3-term (exact path) ----------------
#define G_SBH 0
#define G_SBL 8704
#define G_SAH 17408
#define G_SAL 22528
#define G_BSTR 136
#define G_BBUF 4352
#define G_ASTR 40
#define G_ABUF 2560
#define G_TOTAL_BYTES 55296

__global__ __launch_bounds__(256) void gemm_mma(
    const ushort_t* __restrict__ Ahi, const ushort_t* __restrict__ Alo,
    const ushort_t* __restrict__ Bhi, const ushort_t* __restrict__ Blo,
    const float* __restrict__ bias, float* __restrict__ C)
{
    extern __shared__ ushort_t gsm[];
    const int tid = threadIdx.x;
    const int bn = blockIdx.x * 128, bm = blockIdx.y * 64;
    const int wid = tid >> 5, lane = tid & 31;
    const int wm = wid & 3, wn = wid >> 2;
    const int g = lane >> 2, q = lane & 3;
    const int wc = wn * 64;
    const int row0 = bm + wm * 16 + g;
    const int row1 = row0 + 8;

    float acc[8][4];
    #pragma unroll
    for (int i = 0; i < 8; i++)
        #pragma unroll
        for (int j = 0; j < 4; j++) acc[i][j] = 0.f;

    const int rB = tid >> 3;
    const int cB = (tid & 7) * 8;
    const int rA = tid >> 2;
    const int cA = (tid & 3) * 8;

    uint32_t smb = s2u(gsm);
    uint32_t dstBh[2], dstBl[2], dstAh[2], dstAl[2];
    #pragma unroll
    for (int b = 0; b < 2; b++) {
        dstBh[b] = smb + (uint32_t)((G_SBH + b * G_BBUF + rB * G_BSTR + cB) * 2);
        dstBl[b] = smb + (uint32_t)((G_SBL + b * G_BBUF + rB * G_BSTR + cB) * 2);
        dstAh[b] = smb + (uint32_t)((G_SAH + b * G_ABUF + rA * G_ASTR + cA) * 2);
        dstAl[b] = smb + (uint32_t)((G_SAL + b * G_ABUF + rA * G_ASTR + cA) * 2);
    }

    const int lm = lane >> 3, lr = lane & 7;
    const int lkrow = (lm & 1) * 8 + lr;
    const int lncol = wc + (lm >> 1) * 8;
    const int arow = wm * 16 + (lm & 1) * 8 + lr;
    const int acol = (lane >> 4) * 8;
    uint32_t sbh_base[2], sbl_base[2], sah_base[2], sal_base[2];
    #pragma unroll
    for (int b = 0; b < 2; b++) {
        sbh_base[b] = smb + (uint32_t)((G_SBH + b * G_BBUF + lkrow * G_BSTR + lncol) * 2);
        sbl_base[b] = smb + (uint32_t)((G_SBL + b * G_BBUF + lkrow * G_BSTR + lncol) * 2);
        sah_base[b] = smb + (uint32_t)((G_SAH + b * G_ABUF + arow * G_ASTR + acol) * 2);
        sal_base[b] = smb + (uint32_t)((G_SAL + b * G_ABUF + arow * G_ASTR + acol) * 2);
    }

    {
        const ushort_t* bh = &Bhi[rB * NPIX + bn + cB];
        const ushort_t* bl = &Blo[rB * NPIX + bn + cB];
        CPA16(dstBh[0], bh); CPA16(dstBh[0] + 128, bh + 64);
        CPA16(dstBl[0], bl); CPA16(dstBl[0] + 128, bl + 64);
        CPA16(dstAh[0], &Ahi[(bm + rA) * GK + cA]);
        CPA16(dstAl[0], &Alo[(bm + rA) * GK + cA]);
        CPC();
    }

    #pragma unroll
    for (int ki = 0; ki < 6; ki++) {
        if (ki < 5) {
            const int kn = (ki + 1) * 32;
            const int bf = (ki + 1) & 1;
            const ushort_t* bh = &Bhi[(kn + rB) * NPIX + bn + cB];
            const ushort_t* bl = &Blo[(kn + rB) * NPIX + bn + cB];
            CPA16(dstBh[bf], bh); CPA16(dstBh[bf] + 128, bh + 64);
            CPA16(dstBl[bf], bl); CPA16(dstBl[bf] + 128, bl + 64);
            CPA16(dstAh[bf], &Ahi[(bm + rA) * GK + kn + cA]);
            CPA16(dstAl[bf], &Alo[(bm + rA) * GK + kn + cA]);
            CPC();
            CPW1();
        } else {
            CPW0();
        }
        __syncthreads();

        const int buf = ki & 1;
        #pragma unroll
        for (int hh = 0; hh < 2; hh++) {
            uint32_t ah[4], al[4];
            ldsm4(ah[0], ah[1], ah[2], ah[3], sah_base[buf] + hh * 32);
            ldsm4(al[0], al[1], al[2], al[3], sal_base[buf] + hh * 32);

            const uint32_t hoff = (uint32_t)(hh * 16 * G_BSTR) * 2;
            #pragma unroll
            for (int j = 0; j < 4; j++) {
                uint32_t off = hoff + (uint32_t)(j * 16) * 2;
                uint32_t bh0, bh1, bh2, bh3, bl0, bl1, bl2, bl3;
                ldsm4t(bh0, bh1, bh2, bh3, sbh_base[buf] + off);
                ldsm4t(bl0, bl1, bl2, bl3, sbl_base[buf] + off);
                float* c0 = acc[2 * j];
                float* c1 = acc[2 * j + 1];
                mma_bf16(c0, ah[0], ah[1], ah[2], ah[3], bh0, bh1);
                mma_bf16(c0, al[0], al[1], al[2], al[3], bh0, bh1);
                mma_bf16(c0, ah[0], ah[1], ah[2], ah[3], bl0, bl1);
                mma_bf16(c1, ah[0], ah[1], ah[2], ah[3], bh2, bh3);
                mma_bf16(c1, al[0], al[1], al[2], al[3], bh2, bh3);
                mma_bf16(c1, ah[0], ah[1], ah[2], ah[3], bl2, bl3);
            }
        }
        __syncthreads();
    }

    const float b0 = bias[row0], b1 = bias[row1];
    #pragma unroll
    for (int nf = 0; nf < 8; nf++) {
        int col = bn + wc + nf * 8 + 2 * q;
        *(float2*)&C[row0 * NPIX + col] = make_float2(acc[nf][0] + b0, acc[nf][1] + b0);
        *(float2*)&C[row1 * NPIX + col] = make_float2(acc[nf][2] + b1, acc[nf][3] + b1);
    }
}

// ============================================================================
// fp16 flash attention — pipelined, f16x2 softmax, fp16 I/O
// ============================================================================
#define KSTR 40
#define VSTRF 792
#define NW    12
#define NTHR  384

#define A_SKH 0
#define A_SVH (A_SKH + LTOK * KSTR * 2)          // 62720
#define A_SB  (A_SVH + HDIM * VSTRF * 2)         // 100736
#define A_TOTAL (A_SB + 256)

__global__ __launch_bounds__(NTHR, 2) void attn_mma(
    const float* __restrict__ tab_h, const float* __restrict__ tab_v)
{
    extern __shared__ char asm_[];
    ushort_t* sKhi = (ushort_t*)(asm_ + A_SKH);
    ushort_t* sVhi = (ushort_t*)(asm_ + A_SVH);
    float* sb = (float*)(asm_ + A_SB);

    const int tid = threadIdx.x;
    const int w = blockIdx.x, h = blockIdx.y, br = blockIdx.z;
    const ushort_t* __restrict__ qkv = br ? g_qkv_v : g_qkv_h;
    ushort_t* __restrict__ outp = br ? g_att_v : g_att_h;
    const float* __restrict__ tab = br ? tab_v : tab_h;

    if (tid < 49) {
        int r1 = tid / 7, r2 = tid % 7, off = r1 - r2 + 6;
        float bv = br ? tab[(6 * 13 + off) * NHEAD + h]
                      : tab[(off * 13 + 6) * NHEAD + h];
        sb[tid] = bv * LOG2E;
    }
    for (int i = tid; i < LTOK * 8; i += NTHR) {
        int k = i >> 3, d = 24 + (i & 7);
        sKhi[k * KSTR + d] = 0;
    }
    if (tid < HDIM * 8) {
        int d = tid >> 3, k = LTOK + (tid & 7);
        sVhi[d * VSTRF + k] = 0;
    }
    for (int idx = tid; idx < LTOK * HDIM; idx += NTHR) {
        int d = idx / LTOK, k = idx - d * LTOK;
        int pix = br ? ((k / 7) * 112 + w * 7 + (k % 7)) : (w * LTOK + k);
        sKhi[k * KSTR + d] = qkv[(192 + h * HDIM + d) * HWPIX + pix];
        sVhi[d * VSTRF + k] = qkv[(384 + h * HDIM + d) * HWPIX + pix];
    }
    __syncthreads();

    const int warp = tid >> 5, lane = tid & 31;
    const int g = lane >> 2, q = lane & 3;
    const int d0 = 2 * q;
    const int lr = lane & 7;

    const uint32_t kln = (uint32_t)((lr * KSTR + (lane >> 3) * 8) * 2);
    const uint32_t skh_b = s2u(sKhi) + kln;
    const int vko = ((lane >> 3) & 1) * 8;
    const int vdh = ((lane >> 4) & 1) * 8 + lr;
    const uint32_t sv4 = s2u(sVhi) + (uint32_t)((vdh * VSTRF + vko) * 2);
    const uint32_t sv2a = s2u(sVhi) + (uint32_t)(((16 + lr) * VSTRF + vko) * 2);

    const float qscale = SCALE_F * LOG2E;

    for (int mt = warp; mt < 49; mt += NW) {
        const int r0 = mt * 16 + g, r1 = r0 + 8;
        const int pix0 = br ? ((r0 / 7) * 112 + w * 7 + (r0 % 7)) : (w * LTOK + r0);
        const int pix1 = br ? ((r1 / 7) * 112 + w * 7 + (r1 % 7)) : (w * LTOK + r1);
        const int bro0 = (br ? (r0 % 7) : (r0 / 112)) * 7;
        const int bro1 = (br ? (r1 % 7) : (r1 / 112)) * 7;

        uint32_t qh[6];
        #pragma unroll
        for (int p = 0; p < 3; p++) {
            int d = d0 + 8 * p;
            float a0v = h2f(qkv[(h * HDIM + d)     * HWPIX + pix0]) * qscale;
            float a1v = h2f(qkv[(h * HDIM + d + 1) * HWPIX + pix0]) * qscale;
            float b0v = h2f(qkv[(h * HDIM + d)     * HWPIX + pix1]) * qscale;
            float b1v = h2f(qkv[(h * HDIM + d + 1) * HWPIX + pix1]) * qscale;
            qh[2 * p]     = hfp(a0v, a1v);
            qh[2 * p + 1] = hfp(b0v, b1v);
        }

        float o[3][4];
        #pragma unroll
        for (int nd = 0; nd < 3; nd++)
            #pragma unroll
            for (int i = 0; i < 4; i++) o[nd][i] = 0.f;
        float rs0 = 0.f, rs1 = 0.f;

        float sA[4] = {0.f, 0.f, 0.f, 0.f};
        float sB[4] = {0.f, 0.f, 0.f, 0.f};
        {
            uint32_t h0, h1, h2, h3;
            ldsm4(h0, h1, h2, h3, skh_b);
            mma_f16(sA, qh[0], qh[1], qh[2], qh[3], h0, h1);
            mma_f16_k8(sA, qh[4], qh[5], h2);
            ldsm4(h0, h1, h2, h3, skh_b + (uint32_t)(8 * KSTR * 2));
            mma_f16(sB, qh[0], qh[1], qh[2], qh[3], h0, h1);
            mma_f16_k8(sB, qh[4], qh[5], h2);
        }

        #pragma unroll 4
        for (int s = 0; s < 56; s++) {
            const int kt = s >> 2, ks = s & 3;
            const int kbase = kt * 56;
            const int nt0 = 2 * ks;
            const bool has1 = (ks != 3);

            float nA[4] = {0.f, 0.f, 0.f, 0.f};
            float nB[4] = {0.f, 0.f, 0.f, 0.f};
            if (s < 55) {
                const int s1 = s + 1;
                const int kb1 = (s1 >> 2) * 56;
                const int ns0 = 2 * (s1 & 3);
                uint32_t ko = (uint32_t)((kb1 + ns0 * 8) * KSTR * 2);
                uint32_t h0, h1, h2, h3;
                ldsm4(h0, h1, h2, h3, skh_b + ko);
                mma_f16(nA, qh[0], qh[1], qh[2], qh[3], h0, h1);
                mma_f16_k8(nA, qh[4], qh[5], h2);
                if ((s1 & 3) != 3) {
                    ko = (uint32_t)((kb1 + (ns0 + 1) * 8) * KSTR * 2);
                    ldsm4(h0, h1, h2, h3, skh_b + ko);
                    mma_f16(nB, qh[0], qh[1], qh[2], qh[3], h0, h1);
                    mma_f16_k8(nB, qh[4], qh[5], h2);
                }
            }

            uint32_t pa0, pa1, pa2 = 0u, pa3 = 0u;
            if (!br) {
                float bh0 = sb[bro0 + (kt >> 1)];
                float bh1 = sb[bro1 + (kt >> 1)];
                pa0 = hex2(hfp(sA[0] + bh0, sA[1] + bh0));
                pa1 = hex2(hfp(sA[2] + bh1, sA[3] + bh1));
                if (has1) {
                    pa2 = hex2(hfp(sB[0] + bh0, sB[1] + bh0));
                    pa3 = hex2(hfp(sB[2] + bh1, sB[3] + bh1));
                }
            } else {
                int i0 = (nt0 + d0) % 7;
                int i1 = i0 + 1; if (i1 == 7) i1 = 0;
                int j1 = i1 + 1; if (j1 == 7) j1 = 0;
                pa0 = hex2(hfp(sA[0] + sb[bro0 + i0], sA[1] + sb[bro0 + i1]));
                pa1 = hex2(hfp(sA[2] + sb[bro1 + i0], sA[3] + sb[bro1 + i1]));
                if (has1) {
                    pa2 = hex2(hfp(sB[0] + sb[bro0 + i1], sB[1] + sb[bro0 + j1]));
                    pa3 = hex2(hfp(sB[2] + sb[bro1 + i1], sB[3] + sb[bro1 + j1]));
                }
            }
            uint32_t t0 = hadd2u(pa0, pa2);
            uint32_t t1 = hadd2u(pa1, pa3);
            rs0 += h2lo(t0) + h2hi(t0);
            rs1 += h2lo(t1) + h2hi(t1);

            {
                uint32_t vo = (uint32_t)((kbase + ks * 16) * 2);
                uint32_t va0, va1, va2, va3, vx0, vx1;
                ldsm4(va0, va1, va2, va3, sv4 + vo);
                ldsm2(vx0, vx1, sv2a + vo);
                mma_f16(o[0], pa0, pa1, pa2, pa3, va0, va1);
                mma_f16(o[1], pa0, pa1, pa2, pa3, va2, va3);
                mma_f16(o[2], pa0, pa1, pa2, pa3, vx0, vx1);
            }

            #pragma unroll
            for (int i = 0; i < 4; i++) { sA[i] = nA[i]; sB[i] = nB[i]; }
        }

        float a0 = rs0, a1 = rs1;
        a0 += __shfl_xor_sync(0xFFFFFFFFu, a0, 1);
        a0 += __shfl_xor_sync(0xFFFFFFFFu, a0, 2);
        a1 += __shfl_xor_sync(0xFFFFFFFFu, a1, 1);
        a1 += __shfl_xor_sync(0xFFFFFFFFu, a1, 2);
        float inv0 = 1.f / a0, inv1 = 1.f / a1;
        #pragma unroll
        for (int nd = 0; nd < 3; nd++) {
            int d = nd * 8 + d0;
            outp[(h * HDIM + d)     * HWPIX + pix0] = __half_as_ushort(__float2half_rn(o[nd][0] * inv0));
            outp[(h * HDIM + d + 1) * HWPIX + pix0] = __half_as_ushort(__float2half_rn(o[nd][1] * inv0));
            outp[(h * HDIM + d)     * HWPIX + pix1] = __half_as_ushort(__float2half_rn(o[nd][2] * inv1));
            outp[(h * HDIM + d + 1) * HWPIX + pix1] = __half_as_ushort(__float2half_rn(o[nd][3] * inv1));
        }
    }
}

// ---------------- fused dual LePE (fp16 in) -> 0.5*(h+v) -> bf16 hi/lo planes ------
__global__ __launch_bounds__(256) void lepe_fused(
    const ushort_t* __restrict__ attH, const ushort_t* __restrict__ attV,
    const float* __restrict__ wH, const float* __restrict__ bH,
    const float* __restrict__ wV, const float* __restrict__ bV,
    ushort_t* __restrict__ phi, ushort_t* __restrict__ plo)
{
    int t = blockIdx.x * blockDim.x + threadIdx.x;
    if (t >= Cdim * (HWPIX / 4)) return;
    int c = t / (HWPIX / 4);
    int r = t % (HWPIX / 4);
    int y = r / 28, x4 = (r % 28) * 4;
    const ushort_t* baseH = attH + c * HWPIX;
    const ushort_t* baseV = attV + c * HWPIX;

    float wvh[9], wvv[9];
    #pragma unroll
    for (int i = 0; i < 9; i++) { wvh[i] = wH[c * 9 + i]; wvv[i] = wV[c * 9 + i]; }
    float ah0 = bH[c], ah1 = ah0, ah2 = ah0, ah3 = ah0;
    float av0 = bV[c], av1 = av0, av2 = av0, av3 = av0;

    #pragma unroll
    for (int ky = 0; ky < 3; ky++) {
        int yy = y + ky - 1;
        if (yy < 0 || yy >= 112) continue;
        const ushort_t* rpH = baseH + yy * 112 + x4;
        const ushort_t* rpV = baseV + yy * 112 + x4;
        uint2 mHu = *(const uint2*)rpH;
        uint2 mVu = *(const uint2*)rpV;
        float mh0 = h2lo(mHu.x), mh1 = h2hi(mHu.x), mh2 = h2lo(mHu.y), mh3 = h2hi(mHu.y);
        float mv0 = h2lo(mVu.x), mv1 = h2hi(mVu.x), mv2 = h2lo(mVu.y), mv3 = h2hi(mVu.y);
        float lfH = (x4 > 0)   ? h2f(rpH[-1]) : 0.f;
        float rtH = (x4 < 108) ? h2f(rpH[4])  : 0.f;
        float lfV = (x4 > 0)   ? h2f(rpV[-1]) : 0.f;
        float rtV = (x4 < 108) ? h2f(rpV[4])  : 0.f;
        float h0 = wvh[ky*3], h1 = wvh[ky*3+1], h2 = wvh[ky*3+2];
        float v0 = wvv[ky*3], v1 = wvv[ky*3+1], v2 = wvv[ky*3+2];
        ah0 += h0 * lfH + h1 * mh0 + h2 * mh1;
        ah1 += h0 * mh0 + h1 * mh1 + h2 * mh2;
        ah2 += h0 * mh1 + h1 * mh2 + h2 * mh3;
        ah3 += h0 * mh2 + h1 * mh3 + h2 * rtH;
        av0 += v0 * lfV + v1 * mv0 + v2 * mv1;
        av1 += v0 * mv0 + v1 * mv1 + v2 * mv2;
        av2 += v0 * mv1 + v1 * mv2 + v2 * mv3;
        av3 += v0 * mv2 + v1 * mv3 + v2 * rtV;
    }

    uint2 inHu = *(const uint2*)(baseH + y * 112 + x4);
    uint2 inVu = *(const uint2*)(baseV + y * 112 + x4);
    const float RS2 = 0.70710678118654752f;
    float oh0 = h2lo(inHu.x) + 0.5f * ah0 * (1.f + erff(ah0 * RS2));
    float oh1 = h2hi(inHu.x) + 0.5f * ah1 * (1.f + erff(ah1 * RS2));
    float oh2 = h2lo(inHu.y) + 0.5f * ah2 * (1.f + erff(ah2 * RS2));
    float oh3 = h2hi(inHu.y) + 0.5f * ah3 * (1.f + erff(ah3 * RS2));
    float ov0 = h2lo(inVu.x) + 0.5f * av0 * (1.f + erff(av0 * RS2));
    float ov1 = h2hi(inVu.x) + 0.5f * av1 * (1.f + erff(av1 * RS2));
    float ov2 = h2lo(inVu.y) + 0.5f * av2 * (1.f + erff(av2 * RS2));
    float ov3 = h2hi(inVu.y) + 0.5f * av3 * (1.f + erff(av3 * RS2));

    float p0 = 0.5f * (oh0 + ov0);
    float p1 = 0.5f * (oh1 + ov1);
    float p2 = 0.5f * (oh2 + ov2);
    float p3 = 0.5f * (oh3 + ov3);

    uint32_t h0w = bfp(p0, p1), h1w = bfp(p2, p3);
    uint32_t l0w = bfp(p0 - bflo(h0w), p1 - bfhi(h0w));
    uint32_t l1w = bfp(p2 - bflo(h1w), p3 - bfhi(h1w));
    int idx = c * HWPIX + y * 112 + x4;
    *(uint2*)&phi[idx] = make_uint2(h0w, h1w);
    *(uint2*)&plo[idx] = make_uint2(l0w, l1w);
}

// ---------------- launch ----------------
extern "C" void kernel_launch(void* const* d_in, const int* in_sizes, int n_in,
                              void* d_out, int out_size)
{
    const float* x        = (const float*)d_in[0];
    const float* qkv_h_w  = (const float*)d_in[1];
    const float* qkv_h_b  = (const float*)d_in[2];
    const float* qkv_v_w  = (const float*)d_in[3];
    const float* qkv_v_b  = (const float*)d_in[4];
    const float* proj_w   = (const float*)d_in[5];
    const float* proj_b   = (const float*)d_in[6];
    const float* lepe_h_w = (const float*)d_in[7];
    const float* lepe_h_b = (const float*)d_in[8];
    const float* lepe_v_w = (const float*)d_in[9];
    const float* lepe_v_b = (const float*)d_in[10];
    const float* tab_h    = (const float*)d_in[11];
    const float* tab_v    = (const float*)d_in[12];
    float* out = (float*)d_out;

    ushort_t *qh, *qv, *ah, *av;
    ushort_t *xhi, *phi, *plo, *whh, *wvh, *pwh, *pwl;
    cudaGetSymbolAddress((void**)&qh, g_qkv_h);
    cudaGetSymbolAddress((void**)&qv, g_qkv_v);
    cudaGetSymbolAddress((void**)&ah, g_att_h);
    cudaGetSymbolAddress((void**)&av, g_att_v);
    cudaGetSymbolAddress((void**)&xhi, g_xhi);
    cudaGetSymbolAddress((void**)&phi, g_phi);
    cudaGetSymbolAddress((void**)&plo, g_plo);
    cudaGetSymbolAddress((void**)&whh, g_whh);
    cudaGetSymbolAddress((void**)&wvh, g_wvh);
    cudaGetSymbolAddress((void**)&pwh, g_pwh);
    cudaGetSymbolAddress((void**)&pwl, g_pwl);

    int nx4 = GK * NPIX / 4;
    int nw4 = M_QKV * GK / 4;
    int np4 = M_PROJ * GK / 4;
    int ntot = nx4 + nw4 * 2 + np4;
    split_all<<<(ntot + 255) / 256, 256>>>(
        (const float4*)x,       (uint2*)xhi, nx4,
        (const float4*)qkv_h_w, (uint2*)whh, nw4,
        (const float4*)qkv_v_w, (uint2*)wvh, nw4,
        (const float4*)proj_w,  (uint2*)pwh, (uint2*)pwl, np4);

    cudaFuncSetAttribute(gemm_qkv,
                         cudaFuncAttributeMaxDynamicSharedMemorySize, Q_TOTAL_BYTES);
    dim3 gq(NPIX / 128, M_QKV / 64, 2);
    gemm_qkv<<<gq, 256, Q_TOTAL_BYTES>>>(whh, wvh, xhi,
                                         qkv_h_b, qkv_v_b, qh, qv);

    cudaFuncSetAttribute(attn_mma,
                         cudaFuncAttributeMaxDynamicSharedMemorySize, A_TOTAL);
    dim3 ga(16, NHEAD, 2);
    attn_mma<<<ga, NTHR, A_TOTAL>>>(tab_h, tab_v);

    int nthr = Cdim * (HWPIX / 4);
    lepe_fused<<<(nthr + 255) / 256, 256>>>(ah, av, lepe_h_w, lepe_h_b,
                                            lepe_v_w, lepe_v_b, phi, plo);

    cudaFuncSetAttribute(gemm_mma,
                         cudaFuncAttributeMaxDynamicSharedMemorySize, G_TOTAL_BYTES);
    dim3 gp(NPIX / 128, M_PROJ / 64);
    gemm_mma<<<gp, 256, G_TOTAL_BYTES>>>(pwh, pwl, phi, plo, proj_b, out);
}